// round 3
// baseline (speedup 1.0000x reference)
#include <cuda_runtime.h>
#include <math.h>

#define BB 16
#define NN 1536
#define FF 128

// ---------------- scratch (device globals; no allocation) ----------------
__device__ __align__(16) float g_h0[NN * FF];          // shared layer-0 h
__device__ float g_si0[NN];
__device__ float g_sj0[NN];
__device__ int   g_idx[BB][NN];
__device__ int   g_n[BB];
__device__ __align__(16) float g_hc[(size_t)BB * NN * FF];   // compacted h (current)
__device__ __align__(16) float g_xc[(size_t)BB * NN * FF];   // compacted layer output
__device__ __align__(16) float g_mean[(size_t)BB * NN * FF]; // compacted mean
__device__ float g_sic[BB * NN];
__device__ float g_sjc[BB * NN];
__device__ float g_kldrow[BB * NN];
__device__ __align__(16) float g_hlast[FF];
__device__ float g_sL[2];
__device__ float g_feat[BB * FF];

// attention factorization scratch
__device__ float g_sjs[BB][NN];       // sorted sj (descending)
__device__ int   g_sortidx[BB][NN];   // original index per sorted rank
__device__ float g_vs[BB][NN];        // exp(sjs)
__device__ float g_bs[BB][NN];        // exp(0.2*sjs)
__device__ float g_Dv[(size_t)BB * (NN + 1)];
__device__ float g_Db[(size_t)BB * (NN + 1)];
__device__ __align__(16) float g_Pv[(size_t)BB * (NN + 1) * FF];
__device__ __align__(16) float g_Pb[(size_t)BB * (NN + 1) * FF];

__device__ __forceinline__ float* scratchBuf(int id) {
    switch (id) {
        case 0: return g_h0;
        case 1: return g_hc;
        case 2: return g_xc;
        default: return g_mean;
    }
}

// ---------------- generic per-sample GEMM: C[n x 128] = A[n x 128] @ W(128 x C, ldW) ----------------
template <int EPI>
__global__ void gemm_kernel(const float* __restrict__ Aext, int aId, size_t strideA,
                            const float* __restrict__ W, int ldW,
                            const float* __restrict__ bias,
                            int cId, size_t strideC, int useN)
{
    int b = blockIdx.y;
    int n = useN ? g_n[b] : NN;
    int i0 = blockIdx.x * 64;
    if (i0 >= n) return;

    const float* A = (aId >= 0) ? scratchBuf(aId) : Aext;
    A += (size_t)b * strideA;
    float* C = scratchBuf(cId) + (size_t)b * strideC;

    __shared__ float shA[64][33];
    __shared__ __align__(16) float shW[32 * FF];
    __shared__ float shK[64][17];

    int t = threadIdx.x;          // 256 threads
    int rg = t >> 4, cg = t & 15; // thread tile: 4 rows x 8 cols
    float acc[4][8] = {};

    for (int k0 = 0; k0 < FF; k0 += 32) {
        __syncthreads();
        #pragma unroll
        for (int u = t; u < 64 * 32; u += 256) {
            int r = u >> 5, k = u & 31;
            shA[r][k] = (i0 + r < n) ? A[(size_t)(i0 + r) * FF + k0 + k] : 0.f;
        }
        #pragma unroll
        for (int u = t; u < 32 * 32; u += 256) {
            int r = u >> 5, c4 = u & 31;
            *(float4*)&shW[r * FF + c4 * 4] = *(const float4*)(W + (size_t)(k0 + r) * ldW + c4 * 4);
        }
        __syncthreads();
        #pragma unroll
        for (int k = 0; k < 32; k++) {
            float a0 = shA[rg * 4 + 0][k];
            float a1 = shA[rg * 4 + 1][k];
            float a2 = shA[rg * 4 + 2][k];
            float a3 = shA[rg * 4 + 3][k];
            float4 w0 = *(const float4*)&shW[k * FF + cg * 8];
            float4 w1 = *(const float4*)&shW[k * FF + cg * 8 + 4];
#define FMA8(ai, r) \
            acc[r][0] += ai * w0.x; acc[r][1] += ai * w0.y; acc[r][2] += ai * w0.z; acc[r][3] += ai * w0.w; \
            acc[r][4] += ai * w1.x; acc[r][5] += ai * w1.y; acc[r][6] += ai * w1.z; acc[r][7] += ai * w1.w;
            FMA8(a0, 0) FMA8(a1, 1) FMA8(a2, 2) FMA8(a3, 3)
#undef FMA8
        }
    }

    float bv[8];
    #pragma unroll
    for (int c = 0; c < 8; c++) bv[c] = bias ? bias[cg * 8 + c] : 0.f;

    #pragma unroll
    for (int r = 0; r < 4; r++) {
        int i = i0 + rg * 4 + r;
        float kp = 0.f;
        #pragma unroll
        for (int c = 0; c < 8; c++) {
            float v = acc[r][c] + bv[c];
            if (EPI == 1) kp += v * v;
            if (EPI == 2) kp += expm1f(v) - v;
            if (EPI != 2) { if (i < n) C[(size_t)i * FF + cg * 8 + c] = v; }
        }
        if (EPI) shK[rg * 4 + r][cg] = kp;
    }
    if (EPI) {
        __syncthreads();
        if (t < 64) {
            int i = i0 + t;
            if (i < n) {
                float s = 0.f;
                #pragma unroll
                for (int c = 0; c < 16; c++) s += shK[t][c];
                if (EPI == 1) g_kldrow[b * NN + i] = s;
                else          g_kldrow[b * NN + i] += s;
            }
        }
    }
}

// ---------------- si/sj = H @ a_src, H @ a_dst (per row) ----------------
__global__ void sisj_kernel(int mode, const float* __restrict__ a_src, const float* __restrict__ a_dst)
{
    int b = blockIdx.y;
    int n = mode ? g_n[b] : NN;
    int warp = threadIdx.x >> 5, lane = threadIdx.x & 31;
    int row = blockIdx.x * 8 + warp;
    if (row >= n) return;
    const float* H = mode ? (g_hc + (size_t)b * NN * FF) : g_h0;
    float4 h  = ((const float4*)(H + (size_t)row * FF))[lane];
    float4 as = ((const float4*)a_src)[lane];
    float4 ad = ((const float4*)a_dst)[lane];
    float vs = h.x * as.x + h.y * as.y + h.z * as.z + h.w * as.w;
    float vd = h.x * ad.x + h.y * ad.y + h.z * ad.z + h.w * ad.w;
    #pragma unroll
    for (int o = 16; o > 0; o >>= 1) {
        vs += __shfl_down_sync(0xffffffffu, vs, o);
        vd += __shfl_down_sync(0xffffffffu, vd, o);
    }
    if (lane == 0) {
        if (mode) { g_sic[b * NN + row] = vs; g_sjc[b * NN + row] = vd; }
        else      { g_si0[row] = vs;          g_sj0[row] = vd; }
    }
}

// ---------------- h_last = embed[-1] @ dec_W, plus its src/dst scores ----------------
__global__ void hlast_kernel(const float* __restrict__ embed, const float* __restrict__ dW,
                             const float* __restrict__ das, const float* __restrict__ dad)
{
    int t = threadIdx.x; // 128
    const float* e = embed + (size_t)NN * FF;
    float acc = 0.f;
    for (int k = 0; k < FF; k++) acc += e[k] * dW[k * FF + t];
    g_hlast[t] = acc;
    __shared__ float sh[128];
    sh[t] = acc * das[t];
    __syncthreads();
    for (int s = 64; s > 0; s >>= 1) { if (t < s) sh[t] += sh[t + s]; __syncthreads(); }
    if (t == 0) g_sL[0] = sh[0];
    __syncthreads();
    sh[t] = acc * dad[t];
    __syncthreads();
    for (int s = 64; s > 0; s >>= 1) { if (t < s) sh[t] += sh[t + s]; __syncthreads(); }
    if (t == 0) g_sL[1] = sh[0];
}

// ---------------- deterministic active-set compaction ----------------
__global__ void compact_kernel(const int* __restrict__ data)
{
    int b = blockIdx.x;
    int lane = threadIdx.x; // 32
    const int* d = data + b * NN;
    int cnt = 0;
    for (int base = 0; base < NN; base += 32) {
        int v = d[base + lane];
        unsigned m = __ballot_sync(0xffffffffu, v != 0);
        if (v != 0) g_idx[b][cnt + __popc(m & ((1u << lane) - 1u))] = base + lane;
        cnt += __popc(m);
    }
    if (lane == 0) g_n[b] = cnt;
}

__global__ void gather_h_kernel()
{
    int b = blockIdx.y;
    int n = g_n[b];
    int u = blockIdx.x * 256 + threadIdx.x;
    int jj = u >> 5;
    if (jj >= n) return;
    int c4 = u & 31;
    ((float4*)g_hc)[(size_t)b * NN * 32 + u] = ((const float4*)g_h0)[(size_t)g_idx[b][jj] * 32 + c4];
}

__global__ void gather_s_kernel()
{
    int b = blockIdx.y;
    int n = g_n[b];
    int jj = blockIdx.x * 256 + threadIdx.x;
    if (jj >= n) return;
    int src = g_idx[b][jj];
    g_sic[b * NN + jj] = g_si0[src];
    g_sjc[b * NN + jj] = g_sj0[src];
}

// ---------------- sort sj descending + scalar prefix sums of exp(sj), exp(0.2 sj) ----------------
__global__ void sort_kernel()
{
    int b = blockIdx.x;
    int n = g_n[b];
    __shared__ float key[2048];
    __shared__ int   val[2048];
    int t = threadIdx.x; // 1024

    #pragma unroll
    for (int u = t; u < 2048; u += 1024) {
        key[u] = (u < n) ? g_sjc[b * NN + u] : -1e30f;
        val[u] = u;
    }
    __syncthreads();

    for (int kk = 2; kk <= 2048; kk <<= 1) {
        for (int jj = kk >> 1; jj > 0; jj >>= 1) {
            #pragma unroll
            for (int u = t; u < 2048; u += 1024) {
                int p = u ^ jj;
                if (p > u) {
                    bool desc = ((u & kk) == 0);
                    float ku = key[u], kp = key[p];
                    bool sw = desc ? (ku < kp) : (ku > kp);
                    if (sw) {
                        key[u] = kp; key[p] = ku;
                        int tv = val[u]; val[u] = val[p]; val[p] = tv;
                    }
                }
            }
            __syncthreads();
        }
    }

    #pragma unroll
    for (int u = t; u < 2048; u += 1024) {
        if (u < n) { g_sjs[b][u] = key[u]; g_sortidx[b][u] = val[u]; }
    }
    __syncthreads();

    // ---- scan of v = exp(sjs) ----
    #pragma unroll
    for (int u = t; u < 2048; u += 1024) {
        float v = (u < n) ? __expf(key[u]) : 0.f;
        if (u < n) g_vs[b][u] = v;
        key[u] = v;
    }
    __syncthreads();
    for (int off = 1; off < 2048; off <<= 1) {
        float t0 = (t >= off) ? key[t - off] : 0.f;
        float t1 = key[t + 1024 - off];
        __syncthreads();
        key[t] += t0; key[t + 1024] += t1;
        __syncthreads();
    }
    if (t == 0) g_Dv[(size_t)b * (NN + 1)] = 0.f;
    #pragma unroll
    for (int u = t; u < 2048; u += 1024)
        if (u < n) g_Dv[(size_t)b * (NN + 1) + u + 1] = key[u];
    __syncthreads();

    // ---- scan of bweight = exp(0.2*sjs) ----
    #pragma unroll
    for (int u = t; u < 2048; u += 1024) {
        float v = (u < n) ? __expf(0.2f * g_sjs[b][u]) : 0.f;
        if (u < n) g_bs[b][u] = v;
        key[u] = v;
    }
    __syncthreads();
    for (int off = 1; off < 2048; off <<= 1) {
        float t0 = (t >= off) ? key[t - off] : 0.f;
        float t1 = key[t + 1024 - off];
        __syncthreads();
        key[t] += t0; key[t + 1024] += t1;
        __syncthreads();
    }
    if (t == 0) g_Db[(size_t)b * (NN + 1)] = 0.f;
    #pragma unroll
    for (int u = t; u < 2048; u += 1024)
        if (u < n) g_Db[(size_t)b * (NN + 1) + u + 1] = key[u];
}

// ---------------- vector prefix sums Pv[k][c], Pb[k][c] along sorted order ----------------
__global__ void vscan_kernel()
{
    int b = blockIdx.x;
    int n = g_n[b];
    int c = threadIdx.x; // 128
    const float* H = g_hc + (size_t)b * NN * FF;
    float* Pv = g_Pv + (size_t)b * (NN + 1) * FF;
    float* Pb = g_Pb + (size_t)b * (NN + 1) * FF;
    Pv[c] = 0.f; Pb[c] = 0.f;

    __shared__ int   sidx[128];
    __shared__ float sv[128], sb[128];
    float accV = 0.f, accB = 0.f;

    for (int base = 0; base < n; base += 128) {
        int rem = n - base; if (rem > 128) rem = 128;
        __syncthreads();
        if (c < rem) {
            sidx[c] = g_sortidx[b][base + c];
            sv[c]   = g_vs[b][base + c];
            sb[c]   = g_bs[b][base + c];
        }
        __syncthreads();
        for (int r = 0; r < rem; r++) {
            float hv = H[(size_t)sidx[r] * FF + c];
            accV = fmaf(sv[r], hv, accV);
            accB = fmaf(sb[r], hv, accB);
            Pv[(size_t)(base + r + 1) * FF + c] = accV;
            Pb[(size_t)(base + r + 1) * FF + c] = accB;
        }
    }
}

// ---------------- per-row combine: binary search + prefix lookup + elu ----------------
__global__ void combine_kernel()
{
    int b = blockIdx.y;
    int n = g_n[b];
    int i = blockIdx.x * 4 + threadIdx.y;
    if (i >= n) return;
    int c = threadIdx.x;

    float si = g_sic[b * NN + i];
    float u = __expf(si), a = __expf(0.2f * si);
    float th = -si;

    const float* sjs = g_sjs[b];
    int lo = 0, hi = n;
    while (lo < hi) {
        int mid = (lo + hi) >> 1;
        if (sjs[mid] >= th) lo = mid + 1; else hi = mid;
    }
    int k = lo;

    size_t rb = (size_t)b * (NN + 1);
    float den = u * g_Dv[rb + k] + a * (g_Db[rb + n] - g_Db[rb + k]);
    float num = u * g_Pv[(rb + k) * FF + c] + a * (g_Pb[(rb + n) * FF + c] - g_Pb[(rb + k) * FF + c]);
    float v = num / den;
    g_xc[(size_t)b * NN * FF + (size_t)i * FF + c] = (v > 0.f) ? v : expm1f(v);
}

// ---------------- decoder: single attention row (last node) per sample ----------------
__global__ void dec_attn_kernel()
{
    int b = blockIdx.x;
    int n = g_n[b];
    const float* H = g_hc + (size_t)b * NN * FF;
    const float* sj = g_sjc + b * NN;
    float sLs = g_sL[0];
    int t = threadIdx.x; // 128
    __shared__ float shw[128];
    float acc0 = 0.f, acc1 = 0.f, acc2 = 0.f, acc3 = 0.f, dsum = 0.f;
    for (int j0 = 0; j0 < n; j0 += 128) {
        int j = j0 + t;
        float w = 0.f;
        if (j < n) { float e = sLs + sj[j]; e = (e >= 0.f) ? e : 0.2f * e; w = __expf(e); }
        __syncthreads();
        shw[t] = w; dsum += w;
        __syncthreads();
        int lim = (n - j0 < 128) ? (n - j0) : 128;
        int jj = 0;
        for (; jj + 4 <= lim; jj += 4) {
            acc0 += shw[jj + 0] * H[(size_t)(j0 + jj + 0) * FF + t];
            acc1 += shw[jj + 1] * H[(size_t)(j0 + jj + 1) * FF + t];
            acc2 += shw[jj + 2] * H[(size_t)(j0 + jj + 2) * FF + t];
            acc3 += shw[jj + 3] * H[(size_t)(j0 + jj + 3) * FF + t];
        }
        for (; jj < lim; jj++) acc0 += shw[jj] * H[(size_t)(j0 + jj) * FF + t];
    }
    float acc = acc0 + acc1 + acc2 + acc3;
    __shared__ float shr[128];
    __syncthreads();
    shr[t] = dsum;
    __syncthreads();
    for (int s = 64; s > 0; s >>= 1) { if (t < s) shr[t] += shr[t + s]; __syncthreads(); }
    float eL = sLs + g_sL[1]; eL = (eL >= 0.f) ? eL : 0.2f * eL;
    float wL = __expf(eL);
    float denom = shr[0] + wL;
    acc += wL * g_hlast[t];
    g_feat[b * FF + t] = fmaxf(acc / denom, 0.f);
}

// ---------------- output MLP + KLD total ----------------
__global__ void final_kernel(const float* __restrict__ W1, const float* __restrict__ b1,
                             const float* __restrict__ W2, const float* __restrict__ b2,
                             float* __restrict__ out)
{
    int t = threadIdx.x; // 256
    __shared__ float shh[16 * 128];
    for (int u = t; u < 16 * 128; u += 256) {
        int b = u >> 7, c = u & 127;
        const float* f = g_feat + b * FF;
        float acc = b1[c];
        for (int k = 0; k < FF; k++) acc += f[k] * W1[k * FF + c];
        shh[u] = fmaxf(acc, 0.f);
    }
    __shared__ float shr[256];
    float kld = 0.f;
    for (int b = 0; b < BB; b++) {
        int n = g_n[b];
        float p = 0.f;
        for (int r = t; r < n; r += 256) p += g_kldrow[b * NN + r];
        shr[t] = p;
        __syncthreads();
        for (int s = 128; s > 0; s >>= 1) { if (t < s) shr[t] += shr[t + s]; __syncthreads(); }
        if (t == 0) kld += 0.5f * shr[0] / fmaxf((float)n, 1.f);
        __syncthreads();
    }
    __syncthreads();
    if (t < 16) {
        float acc = b2[0];
        for (int c = 0; c < FF; c++) acc += shh[t * FF + c] * W2[c];
        out[t] = acc;
    }
    if (t == 0) out[16] = kld;
}

// ---------------- launch ----------------
extern "C" void kernel_launch(void* const* d_in, const int* in_sizes, int n_in,
                              void* d_out, int out_size)
{
    (void)in_sizes; (void)n_in; (void)out_size;
    const int*   data  = (const int*)d_in[0];
    const float* embed = (const float*)d_in[1];
    const float* encW  = (const float*)d_in[2];
    const float* eas   = (const float*)d_in[3];
    const float* ead   = (const float*)d_in[4];
    const float* pW    = (const float*)d_in[5];
    const float* pb    = (const float*)d_in[6];
    const float* dW    = (const float*)d_in[7];
    const float* das   = (const float*)d_in[8];
    const float* dad   = (const float*)d_in[9];
    const float* oW1   = (const float*)d_in[10];
    const float* ob1   = (const float*)d_in[11];
    const float* oW2   = (const float*)d_in[12];
    const float* ob2   = (const float*)d_in[13];
    float* out = (float*)d_out;

    const size_t SS = (size_t)NN * FF;

    // shared layer-0 precompute
    gemm_kernel<0><<<dim3(24, 1), 256>>>(embed, -1, 0, encW, FF, nullptr, 0, 0, 0);
    sisj_kernel<<<dim3(192, 1), 256>>>(0, eas, ead);
    hlast_kernel<<<1, 128>>>(embed, dW, das, dad);

    // compaction + gather
    compact_kernel<<<16, 32>>>(data);
    gather_h_kernel<<<dim3(192, 16), 256>>>();
    gather_s_kernel<<<dim3(6, 16), 256>>>();

    // encoder layer 0 attention (factorized)
    sort_kernel<<<16, 1024>>>();
    vscan_kernel<<<16, 128>>>();
    combine_kernel<<<dim3(384, 16), dim3(128, 4)>>>();

    // encoder layer 1
    gemm_kernel<0><<<dim3(24, 16), 256>>>(nullptr, 2, SS, encW + FF * FF, FF, nullptr, 1, SS, 1);
    sisj_kernel<<<dim3(192, 16), 256>>>(1, eas + FF, ead + FF);
    sort_kernel<<<16, 1024>>>();
    vscan_kernel<<<16, 128>>>();
    combine_kernel<<<dim3(384, 16), dim3(128, 4)>>>();

    // param head: mean (store + kld part) and sigma (kld part)
    gemm_kernel<1><<<dim3(24, 16), 256>>>(nullptr, 2, SS, pW, 2 * FF, pb, 3, SS, 1);
    gemm_kernel<2><<<dim3(24, 16), 256>>>(nullptr, 2, SS, pW + FF, 2 * FF, pb + FF, 3, SS, 1);

    // decoder
    gemm_kernel<0><<<dim3(24, 16), 256>>>(nullptr, 3, SS, dW, FF, nullptr, 1, SS, 1);
    sisj_kernel<<<dim3(192, 16), 256>>>(1, das, dad);
    dec_attn_kernel<<<16, 128>>>();

    // output MLP + KLD sum
    final_kernel<<<1, 256>>>(oW1, ob1, oW2, ob2, out);
}

// round 4
// speedup vs baseline: 1.5897x; 1.5897x over previous
#include <cuda_runtime.h>
#include <math.h>

#define BB 16
#define NN 1536
#define FF 128
#define CH 32
#define NCH (NN / CH)   // 48

// ---------------- scratch (device globals; no allocation) ----------------
__device__ __align__(16) float g_h0[NN * FF];
__device__ float g_si0[NN];
__device__ float g_sj0[NN];
__device__ int   g_idx[BB][NN];
__device__ int   g_n[BB];
__device__ __align__(16) float g_hc[(size_t)BB * NN * FF];
__device__ __align__(16) float g_xc[(size_t)BB * NN * FF];
__device__ __align__(16) float g_mean[(size_t)BB * NN * FF];
__device__ float g_sic[BB * NN];
__device__ float g_sjc[BB * NN];
__device__ float g_kldrow[BB * NN];
__device__ __align__(16) float g_hlast[FF];
__device__ float g_sL[2];
__device__ float g_feat[BB * FF];

// attention factorization scratch
__device__ float g_sjs[BB][NN];       // sorted sj (descending)
__device__ int   g_sortidx[BB][NN];
__device__ float g_vs[BB][NN];        // exp(sjs)
__device__ float g_bs[BB][NN];        // exp(0.2*sjs)
__device__ float g_Dv[(size_t)BB * (NN + 1)];   // scalar full prefix
__device__ float g_Db[(size_t)BB * (NN + 1)];
__device__ __align__(16) float g_hs[(size_t)BB * NN * FF];      // h permuted to sorted order
__device__ __align__(16) float g_Sv[BB][NCH][FF];               // per-chunk sums
__device__ __align__(16) float g_Sb[BB][NCH][FF];
__device__ __align__(16) float g_Cv[BB][NCH + 1][FF];           // exclusive chunk prefix
__device__ __align__(16) float g_Cb[BB][NCH + 1][FF];

__device__ __forceinline__ float* scratchBuf(int id) {
    switch (id) {
        case 0: return g_h0;
        case 1: return g_hc;
        case 2: return g_xc;
        default: return g_mean;
    }
}

// ---------------- generic per-sample GEMM ----------------
template <int EPI>
__global__ void gemm_kernel(const float* __restrict__ Aext, int aId, size_t strideA,
                            const float* __restrict__ W, int ldW,
                            const float* __restrict__ bias,
                            int cId, size_t strideC, int useN)
{
    int b = blockIdx.y;
    int n = useN ? g_n[b] : NN;
    int i0 = blockIdx.x * 64;
    if (i0 >= n) return;

    const float* A = (aId >= 0) ? scratchBuf(aId) : Aext;
    A += (size_t)b * strideA;
    float* C = scratchBuf(cId) + (size_t)b * strideC;

    __shared__ float shA[64][33];
    __shared__ __align__(16) float shW[32 * FF];
    __shared__ float shK[64][17];

    int t = threadIdx.x;
    int rg = t >> 4, cg = t & 15;
    float acc[4][8] = {};

    for (int k0 = 0; k0 < FF; k0 += 32) {
        __syncthreads();
        #pragma unroll
        for (int u = t; u < 64 * 32; u += 256) {
            int r = u >> 5, k = u & 31;
            shA[r][k] = (i0 + r < n) ? A[(size_t)(i0 + r) * FF + k0 + k] : 0.f;
        }
        #pragma unroll
        for (int u = t; u < 32 * 32; u += 256) {
            int r = u >> 5, c4 = u & 31;
            *(float4*)&shW[r * FF + c4 * 4] = *(const float4*)(W + (size_t)(k0 + r) * ldW + c4 * 4);
        }
        __syncthreads();
        #pragma unroll
        for (int k = 0; k < 32; k++) {
            float a0 = shA[rg * 4 + 0][k];
            float a1 = shA[rg * 4 + 1][k];
            float a2 = shA[rg * 4 + 2][k];
            float a3 = shA[rg * 4 + 3][k];
            float4 w0 = *(const float4*)&shW[k * FF + cg * 8];
            float4 w1 = *(const float4*)&shW[k * FF + cg * 8 + 4];
#define FMA8(ai, r) \
            acc[r][0] += ai * w0.x; acc[r][1] += ai * w0.y; acc[r][2] += ai * w0.z; acc[r][3] += ai * w0.w; \
            acc[r][4] += ai * w1.x; acc[r][5] += ai * w1.y; acc[r][6] += ai * w1.z; acc[r][7] += ai * w1.w;
            FMA8(a0, 0) FMA8(a1, 1) FMA8(a2, 2) FMA8(a3, 3)
#undef FMA8
        }
    }

    float bv[8];
    #pragma unroll
    for (int c = 0; c < 8; c++) bv[c] = bias ? bias[cg * 8 + c] : 0.f;

    #pragma unroll
    for (int r = 0; r < 4; r++) {
        int i = i0 + rg * 4 + r;
        float kp = 0.f;
        #pragma unroll
        for (int c = 0; c < 8; c++) {
            float v = acc[r][c] + bv[c];
            if (EPI == 1) kp += v * v;
            if (EPI == 2) kp += expm1f(v) - v;
            if (EPI != 2) { if (i < n) C[(size_t)i * FF + cg * 8 + c] = v; }
        }
        if (EPI) shK[rg * 4 + r][cg] = kp;
    }
    if (EPI) {
        __syncthreads();
        if (t < 64) {
            int i = i0 + t;
            if (i < n) {
                float s = 0.f;
                #pragma unroll
                for (int c = 0; c < 16; c++) s += shK[t][c];
                if (EPI == 1) g_kldrow[b * NN + i] = s;
                else          g_kldrow[b * NN + i] += s;
            }
        }
    }
}

// ---------------- si/sj ----------------
__global__ void sisj_kernel(int mode, const float* __restrict__ a_src, const float* __restrict__ a_dst)
{
    int b = blockIdx.y;
    int n = mode ? g_n[b] : NN;
    int warp = threadIdx.x >> 5, lane = threadIdx.x & 31;
    int row = blockIdx.x * 8 + warp;
    if (row >= n) return;
    const float* H = mode ? (g_hc + (size_t)b * NN * FF) : g_h0;
    float4 h  = ((const float4*)(H + (size_t)row * FF))[lane];
    float4 as = ((const float4*)a_src)[lane];
    float4 ad = ((const float4*)a_dst)[lane];
    float vs = h.x * as.x + h.y * as.y + h.z * as.z + h.w * as.w;
    float vd = h.x * ad.x + h.y * ad.y + h.z * ad.z + h.w * ad.w;
    #pragma unroll
    for (int o = 16; o > 0; o >>= 1) {
        vs += __shfl_down_sync(0xffffffffu, vs, o);
        vd += __shfl_down_sync(0xffffffffu, vd, o);
    }
    if (lane == 0) {
        if (mode) { g_sic[b * NN + row] = vs; g_sjc[b * NN + row] = vd; }
        else      { g_si0[row] = vs;          g_sj0[row] = vd; }
    }
}

// ---------------- h_last ----------------
__global__ void hlast_kernel(const float* __restrict__ embed, const float* __restrict__ dW,
                             const float* __restrict__ das, const float* __restrict__ dad)
{
    int t = threadIdx.x; // 128
    const float* e = embed + (size_t)NN * FF;
    float acc = 0.f;
    for (int k = 0; k < FF; k++) acc += e[k] * dW[k * FF + t];
    g_hlast[t] = acc;
    __shared__ float sh[128];
    sh[t] = acc * das[t];
    __syncthreads();
    for (int s = 64; s > 0; s >>= 1) { if (t < s) sh[t] += sh[t + s]; __syncthreads(); }
    if (t == 0) g_sL[0] = sh[0];
    __syncthreads();
    sh[t] = acc * dad[t];
    __syncthreads();
    for (int s = 64; s > 0; s >>= 1) { if (t < s) sh[t] += sh[t + s]; __syncthreads(); }
    if (t == 0) g_sL[1] = sh[0];
}

// ---------------- compaction ----------------
__global__ void compact_kernel(const int* __restrict__ data)
{
    int b = blockIdx.x;
    int lane = threadIdx.x; // 32
    const int* d = data + b * NN;
    int cnt = 0;
    for (int base = 0; base < NN; base += 32) {
        int v = d[base + lane];
        unsigned m = __ballot_sync(0xffffffffu, v != 0);
        if (v != 0) g_idx[b][cnt + __popc(m & ((1u << lane) - 1u))] = base + lane;
        cnt += __popc(m);
    }
    if (lane == 0) g_n[b] = cnt;
}

__global__ void gather_h_kernel()
{
    int b = blockIdx.y;
    int n = g_n[b];
    int u = blockIdx.x * 256 + threadIdx.x;
    int jj = u >> 5;
    if (jj >= n) return;
    int c4 = u & 31;
    ((float4*)g_hc)[(size_t)b * NN * 32 + u] = ((const float4*)g_h0)[(size_t)g_idx[b][jj] * 32 + c4];
}

__global__ void gather_s_kernel()
{
    int b = blockIdx.y;
    int n = g_n[b];
    int jj = blockIdx.x * 256 + threadIdx.x;
    if (jj >= n) return;
    int src = g_idx[b][jj];
    g_sic[b * NN + jj] = g_si0[src];
    g_sjc[b * NN + jj] = g_sj0[src];
}

// ---------------- sort sj descending + scalar prefix sums ----------------
__global__ void sort_kernel()
{
    int b = blockIdx.x;
    int n = g_n[b];
    __shared__ float key[2048];
    __shared__ int   val[2048];
    int t = threadIdx.x; // 1024

    #pragma unroll
    for (int u = t; u < 2048; u += 1024) {
        key[u] = (u < n) ? g_sjc[b * NN + u] : -1e30f;
        val[u] = u;
    }
    __syncthreads();

    for (int kk = 2; kk <= 2048; kk <<= 1) {
        for (int jj = kk >> 1; jj > 0; jj >>= 1) {
            #pragma unroll
            for (int u = t; u < 2048; u += 1024) {
                int p = u ^ jj;
                if (p > u) {
                    bool desc = ((u & kk) == 0);
                    float ku = key[u], kp = key[p];
                    bool sw = desc ? (ku < kp) : (ku > kp);
                    if (sw) {
                        key[u] = kp; key[p] = ku;
                        int tv = val[u]; val[u] = val[p]; val[p] = tv;
                    }
                }
            }
            __syncthreads();
        }
    }

    #pragma unroll
    for (int u = t; u < 2048; u += 1024) {
        if (u < n) { g_sjs[b][u] = key[u]; g_sortidx[b][u] = val[u]; }
    }
    __syncthreads();

    // scan of v = exp(sjs)
    #pragma unroll
    for (int u = t; u < 2048; u += 1024) {
        float v = (u < n) ? __expf(key[u]) : 0.f;
        if (u < n) g_vs[b][u] = v;
        key[u] = v;
    }
    __syncthreads();
    for (int off = 1; off < 2048; off <<= 1) {
        float t0 = (t >= off) ? key[t - off] : 0.f;
        float t1 = key[t + 1024 - off];
        __syncthreads();
        key[t] += t0; key[t + 1024] += t1;
        __syncthreads();
    }
    if (t == 0) g_Dv[(size_t)b * (NN + 1)] = 0.f;
    #pragma unroll
    for (int u = t; u < 2048; u += 1024)
        if (u < n) g_Dv[(size_t)b * (NN + 1) + u + 1] = key[u];
    __syncthreads();

    // scan of exp(0.2*sjs)
    #pragma unroll
    for (int u = t; u < 2048; u += 1024) {
        float v = (u < n) ? __expf(0.2f * g_sjs[b][u]) : 0.f;
        if (u < n) g_bs[b][u] = v;
        key[u] = v;
    }
    __syncthreads();
    for (int off = 1; off < 2048; off <<= 1) {
        float t0 = (t >= off) ? key[t - off] : 0.f;
        float t1 = key[t + 1024 - off];
        __syncthreads();
        key[t] += t0; key[t + 1024] += t1;
        __syncthreads();
    }
    if (t == 0) g_Db[(size_t)b * (NN + 1)] = 0.f;
    #pragma unroll
    for (int u = t; u < 2048; u += 1024)
        if (u < n) g_Db[(size_t)b * (NN + 1) + u + 1] = key[u];
}

// ---------------- stage A: permute h to sorted order + per-chunk weighted sums ----------------
__global__ void gatherchunk_kernel()
{
    int b = blockIdx.y;
    int n = g_n[b];
    int chunk = blockIdx.x;   // 0..NCH-1
    int c = threadIdx.x;      // 128
    int j0 = chunk * CH;
    float av = 0.f, ab = 0.f;
    if (j0 < n) {
        int lim = n - j0; if (lim > CH) lim = CH;
        const float* H = g_hc + (size_t)b * NN * FF;
        float* Hs = g_hs + (size_t)b * NN * FF;
        __shared__ int   sidx[CH];
        __shared__ float sv[CH], sb[CH];
        if (c < lim) {
            sidx[c] = g_sortidx[b][j0 + c];
            sv[c]   = g_vs[b][j0 + c];
            sb[c]   = g_bs[b][j0 + c];
        }
        __syncthreads();
        for (int r = 0; r < lim; r++) {
            float hv = H[(size_t)sidx[r] * FF + c];
            Hs[(size_t)(j0 + r) * FF + c] = hv;
            av = fmaf(sv[r], hv, av);
            ab = fmaf(sb[r], hv, ab);
        }
    }
    g_Sv[b][chunk][c] = av;
    g_Sb[b][chunk][c] = ab;
}

// ---------------- stage B: exclusive scan over chunk sums ----------------
__global__ void chunkscan_kernel()
{
    int b = blockIdx.x;
    int c = threadIdx.x; // 128
    float av = 0.f, ab = 0.f;
    #pragma unroll 8
    for (int ch = 0; ch < NCH; ch++) {
        g_Cv[b][ch][c] = av;
        g_Cb[b][ch][c] = ab;
        av += g_Sv[b][ch][c];
        ab += g_Sb[b][ch][c];
    }
    g_Cv[b][NCH][c] = av;
    g_Cb[b][NCH][c] = ab;
}

// ---------------- stage C: per-row combine ----------------
__global__ void combine_kernel()
{
    int b = blockIdx.y;
    int n = g_n[b];
    int i = blockIdx.x * 4 + threadIdx.y;
    if (i >= n) return;
    int c = threadIdx.x;

    float si = g_sic[b * NN + i];
    float u = __expf(si), a = __expf(0.2f * si);
    float th = -si;

    const float* sjs = g_sjs[b];
    int lo = 0, hi = n;
    while (lo < hi) {
        int mid = (lo + hi) >> 1;
        if (sjs[mid] >= th) lo = mid + 1; else hi = mid;
    }
    int k = lo;
    int c0 = k >> 5, j0 = c0 << 5;

    float pv = g_Cv[b][c0][c];
    float pb = g_Cb[b][c0][c];
    const float* Hs = g_hs + (size_t)b * NN * FF;
    for (int j = j0; j < k; j++) {
        float hv = Hs[(size_t)j * FF + c];
        pv = fmaf(g_vs[b][j], hv, pv);
        pb = fmaf(g_bs[b][j], hv, pb);
    }

    float totb = g_Cb[b][NCH][c];
    size_t rb = (size_t)b * (NN + 1);
    float den = u * g_Dv[rb + k] + a * (g_Db[rb + n] - g_Db[rb + k]);
    float num = u * pv + a * (totb - pb);
    float v = num / den;
    g_xc[(size_t)b * NN * FF + (size_t)i * FF + c] = (v > 0.f) ? v : expm1f(v);
}

// ---------------- decoder: single attention row ----------------
__global__ void dec_attn_kernel()
{
    int b = blockIdx.x;
    int n = g_n[b];
    const float* H = g_hc + (size_t)b * NN * FF;
    const float* sj = g_sjc + b * NN;
    float sLs = g_sL[0];
    int t = threadIdx.x; // 128
    __shared__ float shw[128];
    float acc0 = 0.f, acc1 = 0.f, acc2 = 0.f, acc3 = 0.f, dsum = 0.f;
    for (int j0 = 0; j0 < n; j0 += 128) {
        int j = j0 + t;
        float w = 0.f;
        if (j < n) { float e = sLs + sj[j]; e = (e >= 0.f) ? e : 0.2f * e; w = __expf(e); }
        __syncthreads();
        shw[t] = w; dsum += w;
        __syncthreads();
        int lim = (n - j0 < 128) ? (n - j0) : 128;
        int jj = 0;
        for (; jj + 4 <= lim; jj += 4) {
            acc0 += shw[jj + 0] * H[(size_t)(j0 + jj + 0) * FF + t];
            acc1 += shw[jj + 1] * H[(size_t)(j0 + jj + 1) * FF + t];
            acc2 += shw[jj + 2] * H[(size_t)(j0 + jj + 2) * FF + t];
            acc3 += shw[jj + 3] * H[(size_t)(j0 + jj + 3) * FF + t];
        }
        for (; jj < lim; jj++) acc0 += shw[jj] * H[(size_t)(j0 + jj) * FF + t];
    }
    float acc = acc0 + acc1 + acc2 + acc3;
    __shared__ float shr[128];
    __syncthreads();
    shr[t] = dsum;
    __syncthreads();
    for (int s = 64; s > 0; s >>= 1) { if (t < s) shr[t] += shr[t + s]; __syncthreads(); }
    float eL = sLs + g_sL[1]; eL = (eL >= 0.f) ? eL : 0.2f * eL;
    float wL = __expf(eL);
    float denom = shr[0] + wL;
    acc += wL * g_hlast[t];
    g_feat[b * FF + t] = fmaxf(acc / denom, 0.f);
}

// ---------------- output MLP + KLD total ----------------
__global__ void final_kernel(const float* __restrict__ W1, const float* __restrict__ b1,
                             const float* __restrict__ W2, const float* __restrict__ b2,
                             float* __restrict__ out)
{
    int t = threadIdx.x; // 256
    __shared__ float shh[16 * 128];
    for (int u = t; u < 16 * 128; u += 256) {
        int b = u >> 7, c = u & 127;
        const float* f = g_feat + b * FF;
        float acc = b1[c];
        for (int k = 0; k < FF; k++) acc += f[k] * W1[k * FF + c];
        shh[u] = fmaxf(acc, 0.f);
    }
    __shared__ float shr[256];
    float kld = 0.f;
    for (int b = 0; b < BB; b++) {
        int n = g_n[b];
        float p = 0.f;
        for (int r = t; r < n; r += 256) p += g_kldrow[b * NN + r];
        shr[t] = p;
        __syncthreads();
        for (int s = 128; s > 0; s >>= 1) { if (t < s) shr[t] += shr[t + s]; __syncthreads(); }
        if (t == 0) kld += 0.5f * shr[0] / fmaxf((float)n, 1.f);
        __syncthreads();
    }
    __syncthreads();
    if (t < 16) {
        float acc = b2[0];
        for (int c = 0; c < FF; c++) acc += shh[t * FF + c] * W2[c];
        out[t] = acc;
    }
    if (t == 0) out[16] = kld;
}

// ---------------- launch ----------------
extern "C" void kernel_launch(void* const* d_in, const int* in_sizes, int n_in,
                              void* d_out, int out_size)
{
    (void)in_sizes; (void)n_in; (void)out_size;
    const int*   data  = (const int*)d_in[0];
    const float* embed = (const float*)d_in[1];
    const float* encW  = (const float*)d_in[2];
    const float* eas   = (const float*)d_in[3];
    const float* ead   = (const float*)d_in[4];
    const float* pW    = (const float*)d_in[5];
    const float* pb    = (const float*)d_in[6];
    const float* dW    = (const float*)d_in[7];
    const float* das   = (const float*)d_in[8];
    const float* dad   = (const float*)d_in[9];
    const float* oW1   = (const float*)d_in[10];
    const float* ob1   = (const float*)d_in[11];
    const float* oW2   = (const float*)d_in[12];
    const float* ob2   = (const float*)d_in[13];
    float* out = (float*)d_out;

    const size_t SS = (size_t)NN * FF;

    // shared layer-0 precompute
    gemm_kernel<0><<<dim3(24, 1), 256>>>(embed, -1, 0, encW, FF, nullptr, 0, 0, 0);
    sisj_kernel<<<dim3(192, 1), 256>>>(0, eas, ead);
    hlast_kernel<<<1, 128>>>(embed, dW, das, dad);

    // compaction + gather
    compact_kernel<<<16, 32>>>(data);
    gather_h_kernel<<<dim3(192, 16), 256>>>();
    gather_s_kernel<<<dim3(6, 16), 256>>>();

    // encoder layer 0 attention (factorized, two-level)
    sort_kernel<<<16, 1024>>>();
    gatherchunk_kernel<<<dim3(NCH, 16), 128>>>();
    chunkscan_kernel<<<16, 128>>>();
    combine_kernel<<<dim3(384, 16), dim3(128, 4)>>>();

    // encoder layer 1
    gemm_kernel<0><<<dim3(24, 16), 256>>>(nullptr, 2, SS, encW + FF * FF, FF, nullptr, 1, SS, 1);
    sisj_kernel<<<dim3(192, 16), 256>>>(1, eas + FF, ead + FF);
    sort_kernel<<<16, 1024>>>();
    gatherchunk_kernel<<<dim3(NCH, 16), 128>>>();
    chunkscan_kernel<<<16, 128>>>();
    combine_kernel<<<dim3(384, 16), dim3(128, 4)>>>();

    // param head
    gemm_kernel<1><<<dim3(24, 16), 256>>>(nullptr, 2, SS, pW, 2 * FF, pb, 3, SS, 1);
    gemm_kernel<2><<<dim3(24, 16), 256>>>(nullptr, 2, SS, pW + FF, 2 * FF, pb + FF, 3, SS, 1);

    // decoder
    gemm_kernel<0><<<dim3(24, 16), 256>>>(nullptr, 3, SS, dW, FF, nullptr, 1, SS, 1);
    sisj_kernel<<<dim3(192, 16), 256>>>(1, das, dad);
    dec_attn_kernel<<<16, 128>>>();

    // output MLP + KLD sum
    final_kernel<<<1, 256>>>(oW1, ob1, oW2, ob2, out);
}

// round 5
// speedup vs baseline: 2.0480x; 1.2883x over previous
#include <cuda_runtime.h>
#include <math.h>

#define BB 16
#define NN 1536
#define FF 128

// ---------------- scratch (device globals; no allocation) ----------------
__device__ __align__(16) float g_h0[NN * FF];
__device__ float g_si0[NN];
__device__ float g_sj0[NN];
__device__ int   g_idx[BB][NN];
__device__ int   g_n[BB];
__device__ __align__(16) float g_hc[(size_t)BB * NN * FF];
__device__ __align__(16) float g_xc[(size_t)BB * NN * FF];
__device__ __align__(16) float g_mean[(size_t)BB * NN * FF];
__device__ float g_sic[BB * NN];
__device__ float g_sjc[BB * NN];
__device__ float g_kldrow1[BB * NN];
__device__ float g_kldrow2[BB * NN];
__device__ __align__(16) float g_hlast[FF];
__device__ float g_sL[2];
__device__ float g_feat[BB * FF];

__device__ __forceinline__ float* scratchBuf(int id) {
    switch (id) {
        case 0: return g_h0;
        case 1: return g_hc;
        case 2: return g_xc;
        default: return g_mean;
    }
}

// ============ fused GEMM: C[n x 128] = A[n x 128] @ W(128 x C) + epilogues ============
// MODE 0: layer-0 (A=embed ext, write g_h0, sisj->si0/sj0; block 24 = hlast side-task)
// MODE 1: batched (A=scratch aId, write g_hc, sisj->sic/sjc)
// MODE 2: param head (z=0: mean -> g_mean + kldrow1 = sum v^2 ; z=1: sigma -> kldrow2)
template <int MODE>
__global__ void gemm_fused(const float* __restrict__ Aext,
                           const float* __restrict__ W, int ldW,
                           const float* __restrict__ bias,
                           const float* __restrict__ asrc, const float* __restrict__ adst,
                           int aId, int cId,
                           const float* __restrict__ hW, const float* __restrict__ hs2,
                           const float* __restrict__ hd2)
{
    if (MODE == 0 && blockIdx.x == 24) {
        // ---- hlast side-task: h_last = embed[-1] @ dec_W, + its src/dst scores ----
        __shared__ float sh[128];
        int t = threadIdx.x;  // 256
        float acc = 0.f;
        if (t < 128) {
            const float* e = Aext + (size_t)NN * FF;
            #pragma unroll 8
            for (int k = 0; k < FF; k++) acc += e[k] * hW[k * FF + t];
            g_hlast[t] = acc;
            sh[t] = acc * hs2[t];
        }
        __syncthreads();
        for (int s = 64; s > 0; s >>= 1) { if (t < s) sh[t] += sh[t + s]; __syncthreads(); }
        if (t == 0) g_sL[0] = sh[0];
        __syncthreads();
        if (t < 128) sh[t] = acc * hd2[t];
        __syncthreads();
        for (int s = 64; s > 0; s >>= 1) { if (t < s) sh[t] += sh[t + s]; __syncthreads(); }
        if (t == 0) g_sL[1] = sh[0];
        return;
    }

    int b = (MODE == 0) ? 0 : blockIdx.y;
    int n = (MODE == 0) ? NN : g_n[b];
    int i0 = blockIdx.x * 64;
    if (i0 >= n) return;

    const float* A = (MODE == 0) ? Aext : (scratchBuf(aId) + (size_t)b * NN * FF);
    const float* Wp = W;
    const float* bp = bias;
    if (MODE == 2 && blockIdx.z == 1) { Wp += FF; bp += FF; }
    float* C = scratchBuf(cId) + ((MODE == 0) ? 0 : (size_t)b * NN * FF);

    __shared__ float shA[64][33];
    __shared__ __align__(16) float shW[32 * FF];
    __shared__ float shK[64][17];

    int t = threadIdx.x;          // 256
    int rg = t >> 4, cg = t & 15;
    float acc[4][8] = {};

    for (int k0 = 0; k0 < FF; k0 += 32) {
        __syncthreads();
        #pragma unroll
        for (int u = t; u < 64 * 32; u += 256) {
            int r = u >> 5, k = u & 31;
            shA[r][k] = (i0 + r < n) ? A[(size_t)(i0 + r) * FF + k0 + k] : 0.f;
        }
        #pragma unroll
        for (int u = t; u < 32 * 32; u += 256) {
            int r = u >> 5, c4 = u & 31;
            *(float4*)&shW[r * FF + c4 * 4] = *(const float4*)(Wp + (size_t)(k0 + r) * ldW + c4 * 4);
        }
        __syncthreads();
        #pragma unroll
        for (int k = 0; k < 32; k++) {
            float a0 = shA[rg * 4 + 0][k];
            float a1 = shA[rg * 4 + 1][k];
            float a2 = shA[rg * 4 + 2][k];
            float a3 = shA[rg * 4 + 3][k];
            float4 w0 = *(const float4*)&shW[k * FF + cg * 8];
            float4 w1 = *(const float4*)&shW[k * FF + cg * 8 + 4];
#define FMA8(ai, r) \
            acc[r][0] += ai * w0.x; acc[r][1] += ai * w0.y; acc[r][2] += ai * w0.z; acc[r][3] += ai * w0.w; \
            acc[r][4] += ai * w1.x; acc[r][5] += ai * w1.y; acc[r][6] += ai * w1.z; acc[r][7] += ai * w1.w;
            FMA8(a0, 0) FMA8(a1, 1) FMA8(a2, 2) FMA8(a3, 3)
#undef FMA8
        }
    }

    if (MODE != 2) {
        // plain store + fused si/sj epilogue
        float as8[8], ad8[8];
        #pragma unroll
        for (int c = 0; c < 8; c++) { as8[c] = asrc[cg * 8 + c]; ad8[c] = adst[cg * 8 + c]; }
        float ss[4] = {}, sd[4] = {};
        #pragma unroll
        for (int r = 0; r < 4; r++) {
            int i = i0 + rg * 4 + r;
            #pragma unroll
            for (int c = 0; c < 8; c++) {
                float v = acc[r][c];
                ss[r] += v * as8[c];
                sd[r] += v * ad8[c];
                if (i < n) C[(size_t)i * FF + cg * 8 + c] = v;
            }
        }
        #pragma unroll
        for (int r = 0; r < 4; r++) {
            #pragma unroll
            for (int o = 8; o > 0; o >>= 1) {
                ss[r] += __shfl_xor_sync(0xffffffffu, ss[r], o);
                sd[r] += __shfl_xor_sync(0xffffffffu, sd[r], o);
            }
        }
        if (cg == 0) {
            #pragma unroll
            for (int r = 0; r < 4; r++) {
                int i = i0 + rg * 4 + r;
                if (i < n) {
                    if (MODE == 0) { g_si0[i] = ss[r]; g_sj0[i] = sd[r]; }
                    else           { g_sic[b * NN + i] = ss[r]; g_sjc[b * NN + i] = sd[r]; }
                }
            }
        }
    } else {
        int z = blockIdx.z;
        float bv[8];
        #pragma unroll
        for (int c = 0; c < 8; c++) bv[c] = bp[cg * 8 + c];
        #pragma unroll
        for (int r = 0; r < 4; r++) {
            int i = i0 + rg * 4 + r;
            float kp = 0.f;
            #pragma unroll
            for (int c = 0; c < 8; c++) {
                float v = acc[r][c] + bv[c];
                if (z == 0) { kp += v * v; if (i < n) C[(size_t)i * FF + cg * 8 + c] = v; }
                else        { kp += expm1f(v) - v; }
            }
            shK[rg * 4 + r][cg] = kp;
        }
        __syncthreads();
        if (t < 64) {
            int i = i0 + t;
            if (i < n) {
                float s = 0.f;
                #pragma unroll
                for (int c = 0; c < 16; c++) s += shK[t][c];
                if (z == 0) g_kldrow1[b * NN + i] = s;
                else        g_kldrow2[b * NN + i] = s;
            }
        }
    }
}

// ============ compaction + gather (h and scores) in one kernel ============
__global__ void compact_gather_kernel(const int* __restrict__ data)
{
    int b = blockIdx.x;
    int t = threadIdx.x;  // 512
    __shared__ int sn;
    if (t < 32) {
        const int* d = data + b * NN;
        int cnt = 0;
        for (int base = 0; base < NN; base += 32) {
            int v = d[base + t];
            unsigned m = __ballot_sync(0xffffffffu, v != 0);
            if (v != 0) g_idx[b][cnt + __popc(m & ((1u << t) - 1u))] = base + t;
            cnt += __popc(m);
        }
        if (t == 0) { g_n[b] = cnt; sn = cnt; }
    }
    __syncthreads();
    int n = sn;
    for (int u = t; u < n * 32; u += 512)
        ((float4*)g_hc)[(size_t)b * NN * 32 + u] =
            ((const float4*)g_h0)[(size_t)g_idx[b][u >> 5] * 32 + (u & 31)];
    for (int jj = t; jj < n; jj += 512) {
        int src = g_idx[b][jj];
        g_sic[b * NN + jj] = g_si0[src];
        g_sjc[b * NN + jj] = g_sj0[src];
    }
}

// ============ fully-fused factorized attention layer ============
// one block per sample, 1024 threads, dynamic smem.
// sort sj desc -> scalar prefix scans -> chunk sums (32-wide) -> chunk scan -> combine.
#define SM_KEY 0
#define SM_SJS 2048
#define SM_VS  4096
#define SM_BS  6144
#define SM_DV  8192
#define SM_DB  10244
#define SM_SV  12296
#define SM_SB  18568
#define SM_VAL 24840
#define SM_TOT_FLOATS 26888

__global__ void attn_fused_kernel()
{
    extern __shared__ float sm[];
    float* key = sm + SM_KEY;
    float* sjs = sm + SM_SJS;
    float* vs  = sm + SM_VS;
    float* bs  = sm + SM_BS;
    float* Dv  = sm + SM_DV;
    float* Db  = sm + SM_DB;
    float* Sv  = sm + SM_SV;   // 49*128
    float* Sb  = sm + SM_SB;   // 49*128
    int*   val = (int*)(sm + SM_VAL);

    int b = blockIdx.x;
    int n = g_n[b];
    int t = threadIdx.x;  // 1024
    const float* H = g_hc + (size_t)b * NN * FF;

    // ---- load keys ----
    #pragma unroll
    for (int u = t; u < 2048; u += 1024) {
        key[u] = (u < n) ? g_sjc[b * NN + u] : -1e30f;
        val[u] = u;
    }
    __syncthreads();

    // ---- bitonic sort descending ----
    for (int kk = 2; kk <= 2048; kk <<= 1) {
        for (int jj = kk >> 1; jj > 0; jj >>= 1) {
            #pragma unroll
            for (int u = t; u < 2048; u += 1024) {
                int p = u ^ jj;
                if (p > u) {
                    bool desc = ((u & kk) == 0);
                    float ku = key[u], kp = key[p];
                    if (desc ? (ku < kp) : (ku > kp)) {
                        key[u] = kp; key[p] = ku;
                        int tv = val[u]; val[u] = val[p]; val[p] = tv;
                    }
                }
            }
            __syncthreads();
        }
    }

    // ---- sjs / vs / bs ----
    #pragma unroll
    for (int u = t; u < 2048; u += 1024) {
        float kv = key[u];
        sjs[u] = kv;
        vs[u] = (u < n) ? __expf(kv) : 0.f;
        bs[u] = (u < n) ? __expf(0.2f * kv) : 0.f;
    }
    __syncthreads();

    // ---- scalar prefix scans (Hillis-Steele on 2048, key as workspace) ----
    #pragma unroll
    for (int u = t; u < 2048; u += 1024) key[u] = vs[u];
    __syncthreads();
    for (int off = 1; off < 2048; off <<= 1) {
        float t0 = (t >= off) ? key[t - off] : 0.f;
        float t1 = key[t + 1024 - off];
        __syncthreads();
        key[t] += t0; key[t + 1024] += t1;
        __syncthreads();
    }
    if (t == 0) Dv[0] = 0.f;
    #pragma unroll
    for (int u = t; u < 2048; u += 1024) if (u < n) Dv[u + 1] = key[u];
    __syncthreads();

    #pragma unroll
    for (int u = t; u < 2048; u += 1024) key[u] = bs[u];
    __syncthreads();
    for (int off = 1; off < 2048; off <<= 1) {
        float t0 = (t >= off) ? key[t - off] : 0.f;
        float t1 = key[t + 1024 - off];
        __syncthreads();
        key[t] += t0; key[t + 1024] += t1;
        __syncthreads();
    }
    if (t == 0) Db[0] = 0.f;
    #pragma unroll
    for (int u = t; u < 2048; u += 1024) if (u < n) Db[u + 1] = key[u];
    __syncthreads();

    // ---- chunk sums: 8 groups of 128 threads ----
    int grp = t >> 7, c = t & 127;
    int nch = (n + 31) >> 5;
    for (int ch = grp; ch < nch; ch += 8) {
        int j0 = ch * 32;
        int lim = n - j0; if (lim > 32) lim = 32;
        float av = 0.f, ab = 0.f;
        for (int r = 0; r < lim; r++) {
            int j = j0 + r;
            float hv = H[(size_t)val[j] * FF + c];
            av = fmaf(vs[j], hv, av);
            ab = fmaf(bs[j], hv, ab);
        }
        Sv[ch * 128 + c] = av;
        Sb[ch * 128 + c] = ab;
    }
    __syncthreads();

    // ---- exclusive scan over chunks (threads 0..127), total goes in slot nch ----
    if (t < 128) {
        float av = 0.f, ab = 0.f;
        for (int ch = 0; ch < nch; ch++) {
            float sv = Sv[ch * 128 + t], sb2 = Sb[ch * 128 + t];
            Sv[ch * 128 + t] = av; Sb[ch * 128 + t] = ab;
            av += sv; ab += sb2;
        }
        Sv[nch * 128 + t] = av;
        Sb[nch * 128 + t] = ab;
    }
    __syncthreads();

    // ---- combine: one warp per row, lane covers c = lane*4 .. lane*4+3 ----
    int warp = t >> 5, lane = t & 31;
    float* O = g_xc + (size_t)b * NN * FF;
    for (int i = warp; i < n; i += 32) {
        float si = g_sic[b * NN + i];
        float uu = __expf(si), aa = __expf(0.2f * si);
        float th = -si;
        int lo = 0, hi = n;
        while (lo < hi) {
            int mid = (lo + hi) >> 1;
            if (sjs[mid] >= th) lo = mid + 1; else hi = mid;
        }
        int k = lo;
        int c0 = k >> 5;

        float4 pv = *(float4*)&Sv[c0 * 128 + lane * 4];
        float4 pb = *(float4*)&Sb[c0 * 128 + lane * 4];
        for (int j = c0 * 32; j < k; j++) {
            float4 hv = *(const float4*)&H[(size_t)val[j] * FF + lane * 4];
            float wv = vs[j], wb = bs[j];
            pv.x = fmaf(wv, hv.x, pv.x); pv.y = fmaf(wv, hv.y, pv.y);
            pv.z = fmaf(wv, hv.z, pv.z); pv.w = fmaf(wv, hv.w, pv.w);
            pb.x = fmaf(wb, hv.x, pb.x); pb.y = fmaf(wb, hv.y, pb.y);
            pb.z = fmaf(wb, hv.z, pb.z); pb.w = fmaf(wb, hv.w, pb.w);
        }
        float4 tb = *(float4*)&Sb[nch * 128 + lane * 4];
        float inv = 1.f / (uu * Dv[k] + aa * (Db[n] - Db[k]));
        float4 o;
        o.x = (uu * pv.x + aa * (tb.x - pb.x)) * inv;
        o.y = (uu * pv.y + aa * (tb.y - pb.y)) * inv;
        o.z = (uu * pv.z + aa * (tb.z - pb.z)) * inv;
        o.w = (uu * pv.w + aa * (tb.w - pb.w)) * inv;
        o.x = (o.x > 0.f) ? o.x : expm1f(o.x);
        o.y = (o.y > 0.f) ? o.y : expm1f(o.y);
        o.z = (o.z > 0.f) ? o.z : expm1f(o.z);
        o.w = (o.w > 0.f) ? o.w : expm1f(o.w);
        *(float4*)&O[(size_t)i * FF + lane * 4] = o;
    }
}

// ============ decoder: single attention row (last node) per sample ============
__global__ void dec_attn_kernel()
{
    int b = blockIdx.x;
    int n = g_n[b];
    const float* H = g_hc + (size_t)b * NN * FF;
    const float* sj = g_sjc + b * NN;
    float sLs = g_sL[0];
    int t = threadIdx.x; // 128
    __shared__ float shw[128];
    float acc0 = 0.f, acc1 = 0.f, acc2 = 0.f, acc3 = 0.f, dsum = 0.f;
    for (int j0 = 0; j0 < n; j0 += 128) {
        int j = j0 + t;
        float w = 0.f;
        if (j < n) { float e = sLs + sj[j]; e = (e >= 0.f) ? e : 0.2f * e; w = __expf(e); }
        __syncthreads();
        shw[t] = w; dsum += w;
        __syncthreads();
        int lim = (n - j0 < 128) ? (n - j0) : 128;
        int jj = 0;
        for (; jj + 4 <= lim; jj += 4) {
            acc0 += shw[jj + 0] * H[(size_t)(j0 + jj + 0) * FF + t];
            acc1 += shw[jj + 1] * H[(size_t)(j0 + jj + 1) * FF + t];
            acc2 += shw[jj + 2] * H[(size_t)(j0 + jj + 2) * FF + t];
            acc3 += shw[jj + 3] * H[(size_t)(j0 + jj + 3) * FF + t];
        }
        for (; jj < lim; jj++) acc0 += shw[jj] * H[(size_t)(j0 + jj) * FF + t];
    }
    float acc = acc0 + acc1 + acc2 + acc3;
    __shared__ float shr[128];
    __syncthreads();
    shr[t] = dsum;
    __syncthreads();
    for (int s = 64; s > 0; s >>= 1) { if (t < s) shr[t] += shr[t + s]; __syncthreads(); }
    float eL = sLs + g_sL[1]; eL = (eL >= 0.f) ? eL : 0.2f * eL;
    float wL = __expf(eL);
    float denom = shr[0] + wL;
    acc += wL * g_hlast[t];
    g_feat[b * FF + t] = fmaxf(acc / denom, 0.f);
}

// ============ output MLP + KLD total ============
__global__ void final_kernel(const float* __restrict__ W1, const float* __restrict__ b1,
                             const float* __restrict__ W2, const float* __restrict__ b2,
                             float* __restrict__ out)
{
    int t = threadIdx.x; // 256
    __shared__ float shh[16 * 128];
    for (int u = t; u < 16 * 128; u += 256) {
        int b = u >> 7, c = u & 127;
        const float* f = g_feat + b * FF;
        float acc = b1[c];
        for (int k = 0; k < FF; k++) acc += f[k] * W1[k * FF + c];
        shh[u] = fmaxf(acc, 0.f);
    }
    __shared__ float shr[256];
    float kld = 0.f;
    for (int b = 0; b < BB; b++) {
        int n = g_n[b];
        float p = 0.f;
        for (int r = t; r < n; r += 256) p += g_kldrow1[b * NN + r] + g_kldrow2[b * NN + r];
        shr[t] = p;
        __syncthreads();
        for (int s = 128; s > 0; s >>= 1) { if (t < s) shr[t] += shr[t + s]; __syncthreads(); }
        if (t == 0) kld += 0.5f * shr[0] / fmaxf((float)n, 1.f);
        __syncthreads();
    }
    __syncthreads();
    if (t < 16) {
        float acc = b2[0];
        for (int c = 0; c < FF; c++) acc += shh[t * FF + c] * W2[c];
        out[t] = acc;
    }
    if (t == 0) out[16] = kld;
}

// ============ launch ============
extern "C" void kernel_launch(void* const* d_in, const int* in_sizes, int n_in,
                              void* d_out, int out_size)
{
    (void)in_sizes; (void)n_in; (void)out_size;
    const int*   data  = (const int*)d_in[0];
    const float* embed = (const float*)d_in[1];
    const float* encW  = (const float*)d_in[2];
    const float* eas   = (const float*)d_in[3];
    const float* ead   = (const float*)d_in[4];
    const float* pW    = (const float*)d_in[5];
    const float* pb    = (const float*)d_in[6];
    const float* dW    = (const float*)d_in[7];
    const float* das   = (const float*)d_in[8];
    const float* dad   = (const float*)d_in[9];
    const float* oW1   = (const float*)d_in[10];
    const float* ob1   = (const float*)d_in[11];
    const float* oW2   = (const float*)d_in[12];
    const float* ob2   = (const float*)d_in[13];
    float* out = (float*)d_out;

    const int SMEMB = SM_TOT_FLOATS * 4;
    cudaFuncSetAttribute(attn_fused_kernel, cudaFuncAttributeMaxDynamicSharedMemorySize, SMEMB);

    // 1) layer-0 h + si0/sj0, plus hlast side-block
    gemm_fused<0><<<dim3(25, 1), 256>>>(embed, encW, FF, nullptr, eas, ead, -1, 0, dW, das, dad);
    // 2) compaction + gather
    compact_gather_kernel<<<16, 512>>>(data);
    // 3) encoder layer 0 attention (fully fused)
    attn_fused_kernel<<<16, 1024, SMEMB>>>();
    // 4) encoder layer 1 linear + si/sj
    gemm_fused<1><<<dim3(24, 16), 256>>>(nullptr, encW + FF * FF, FF, nullptr,
                                         eas + FF, ead + FF, 2, 1, nullptr, nullptr, nullptr);
    // 5) encoder layer 1 attention
    attn_fused_kernel<<<16, 1024, SMEMB>>>();
    // 6) param head (mean z=0, sigma z=1)
    gemm_fused<2><<<dim3(24, 16, 2), 256>>>(nullptr, pW, 2 * FF, pb, nullptr, nullptr,
                                            2, 3, nullptr, nullptr, nullptr);
    // 7) decoder linear + dec si/sj
    gemm_fused<1><<<dim3(24, 16), 256>>>(nullptr, dW, FF, nullptr, das, dad,
                                         3, 1, nullptr, nullptr, nullptr);
    // 8) decoder single-row attention
    dec_attn_kernel<<<16, 128>>>();
    // 9) output MLP + KLD
    final_kernel<<<1, 256>>>(oW1, ob1, oW2, ob2, out);
}

// round 6
// speedup vs baseline: 2.7929x; 1.3637x over previous
#include <cuda_runtime.h>
#include <math.h>

#define BB 16
#define NN 1536
#define FF 128
#define NB 128

// ---------------- scratch (device globals; no allocation) ----------------
__device__ __align__(16) float g_h0[NN * FF];
__device__ float g_si0[NN];
__device__ float g_sj0[NN];
__device__ int   g_idx[BB][NN];
__device__ int   g_n[BB];
__device__ __align__(16) float g_hc[(size_t)BB * NN * FF];
__device__ __align__(16) float g_xc[(size_t)BB * NN * FF];
__device__ __align__(16) float g_mean[(size_t)BB * NN * FF];
__device__ float g_sic[BB * NN];
__device__ float g_sjc[BB * NN];
__device__ float g_kldrow1[BB * NN];
__device__ float g_kldrow2[BB * NN];
__device__ __align__(16) float g_hlast[FF];
__device__ float g_sL[2];
__device__ float g_feat[BB * FF];

// bucket-factorized attention scratch
__device__ int   g_ord[BB][NN];
__device__ float g_sjo[BB][NN];
__device__ float g_vso[BB][NN];
__device__ float g_bso[BB][NN];
__device__ int   g_bstart[BB][NB + 1];
__device__ __align__(16) float g_Cv[BB][(NB + 1) * FF];
__device__ __align__(16) float g_Cb[BB][(NB + 1) * FF];
__device__ float g_CvS[BB][NB + 1];
__device__ float g_CbS[BB][NB + 1];
__device__ float g_bmax[BB];
__device__ float g_bscale[BB];

__device__ __forceinline__ float* scratchBuf(int id) {
    switch (id) {
        case 0: return g_h0;
        case 1: return g_hc;
        case 2: return g_xc;
        default: return g_mean;
    }
}

// ============ GEMM v2: 64x128 block tile, 128 threads, 8x8 per thread ============
// MODE 0: layer-0 (A=embed, write g_h0, si0/sj0; block 24 = hlast side-task)
// MODE 1: batched (A=scratch aId, write scratch cId, sic/sjc)
// MODE 2: param head (z=0: mean -> g_mean + kldrow1; z=1: sigma -> kldrow2)
template <int MODE>
__global__ void gemm2(const float* __restrict__ Aext,
                      const float* __restrict__ W, int ldW,
                      const float* __restrict__ bias,
                      const float* __restrict__ asrc, const float* __restrict__ adst,
                      int aId, int cId,
                      const float* __restrict__ hW, const float* __restrict__ hs2,
                      const float* __restrict__ hd2)
{
    int t = threadIdx.x;  // 128
    if (MODE == 0 && blockIdx.x == 24) {
        // hlast side-task
        __shared__ float sh[128];
        const float* e = Aext + (size_t)NN * FF;
        float acc = 0.f;
        #pragma unroll 8
        for (int k = 0; k < FF; k++) acc += e[k] * hW[k * FF + t];
        g_hlast[t] = acc;
        sh[t] = acc * hs2[t];
        __syncthreads();
        for (int s = 64; s > 0; s >>= 1) { if (t < s) sh[t] += sh[t + s]; __syncthreads(); }
        if (t == 0) g_sL[0] = sh[0];
        __syncthreads();
        sh[t] = acc * hd2[t];
        __syncthreads();
        for (int s = 64; s > 0; s >>= 1) { if (t < s) sh[t] += sh[t + s]; __syncthreads(); }
        if (t == 0) g_sL[1] = sh[0];
        return;
    }

    int b = (MODE == 0) ? 0 : blockIdx.y;
    int n = (MODE == 0) ? NN : g_n[b];
    int i0 = blockIdx.x * 64;
    if (i0 >= n) return;

    const float* A = (MODE == 0) ? Aext : (scratchBuf(aId) + (size_t)b * NN * FF);
    const float* Wp = W;
    const float* bp = bias;
    if (MODE == 2 && blockIdx.z == 1) { Wp += FF; bp += FF; }
    float* C = scratchBuf(cId) + ((MODE == 0) ? 0 : (size_t)b * NN * FF);

    __shared__ float shA[16][68];                 // transposed A tile [k][row]
    __shared__ __align__(16) float shW[16][128];  // W tile [k][col]

    int ty = t >> 4, tx = t & 15;   // ty: 8 row-groups, tx: 16 col-groups
    float acc[8][8] = {};

    for (int k0 = 0; k0 < FF; k0 += 16) {
        __syncthreads();
        #pragma unroll
        for (int u = t; u < 256; u += 128) {
            int row = u >> 2, c4 = u & 3;
            float4 v = make_float4(0.f, 0.f, 0.f, 0.f);
            if (i0 + row < n) v = *(const float4*)&A[(size_t)(i0 + row) * FF + k0 + c4 * 4];
            shA[c4 * 4 + 0][row] = v.x;
            shA[c4 * 4 + 1][row] = v.y;
            shA[c4 * 4 + 2][row] = v.z;
            shA[c4 * 4 + 3][row] = v.w;
        }
        #pragma unroll
        for (int u = t; u < 512; u += 128) {
            int r = u >> 5, c4 = u & 31;
            *(float4*)&shW[r][c4 * 4] = *(const float4*)&Wp[(size_t)(k0 + r) * ldW + c4 * 4];
        }
        __syncthreads();
        #pragma unroll
        for (int k = 0; k < 16; k++) {
            float av[8], bv[8];
            *(float4*)&av[0] = *(float4*)&shA[k][ty * 8];
            *(float4*)&av[4] = *(float4*)&shA[k][ty * 8 + 4];
            *(float4*)&bv[0] = *(float4*)&shW[k][tx * 8];
            *(float4*)&bv[4] = *(float4*)&shW[k][tx * 8 + 4];
            #pragma unroll
            for (int r = 0; r < 8; r++)
                #pragma unroll
                for (int c = 0; c < 8; c++)
                    acc[r][c] = fmaf(av[r], bv[c], acc[r][c]);
        }
    }

    if (MODE != 2) {
        float as8[8], ad8[8];
        #pragma unroll
        for (int c = 0; c < 8; c++) { as8[c] = asrc[tx * 8 + c]; ad8[c] = adst[tx * 8 + c]; }
        float ss[8], sd[8];
        #pragma unroll
        for (int r = 0; r < 8; r++) {
            int i = i0 + ty * 8 + r;
            float s1 = 0.f, s2 = 0.f;
            #pragma unroll
            for (int c = 0; c < 8; c++) { s1 += acc[r][c] * as8[c]; s2 += acc[r][c] * ad8[c]; }
            ss[r] = s1; sd[r] = s2;
            if (i < n) {
                *(float4*)&C[(size_t)i * FF + tx * 8]     = make_float4(acc[r][0], acc[r][1], acc[r][2], acc[r][3]);
                *(float4*)&C[(size_t)i * FF + tx * 8 + 4] = make_float4(acc[r][4], acc[r][5], acc[r][6], acc[r][7]);
            }
        }
        #pragma unroll
        for (int r = 0; r < 8; r++) {
            #pragma unroll
            for (int o = 8; o > 0; o >>= 1) {
                ss[r] += __shfl_xor_sync(0xffffffffu, ss[r], o);
                sd[r] += __shfl_xor_sync(0xffffffffu, sd[r], o);
            }
        }
        if (tx == 0) {
            #pragma unroll
            for (int r = 0; r < 8; r++) {
                int i = i0 + ty * 8 + r;
                if (i < n) {
                    if (MODE == 0) { g_si0[i] = ss[r]; g_sj0[i] = sd[r]; }
                    else           { g_sic[b * NN + i] = ss[r]; g_sjc[b * NN + i] = sd[r]; }
                }
            }
        }
    } else {
        int z = blockIdx.z;
        float bv8[8];
        #pragma unroll
        for (int c = 0; c < 8; c++) bv8[c] = bp[tx * 8 + c];
        #pragma unroll
        for (int r = 0; r < 8; r++) {
            int i = i0 + ty * 8 + r;
            float kp = 0.f;
            float vv[8];
            #pragma unroll
            for (int c = 0; c < 8; c++) {
                float v = acc[r][c] + bv8[c];
                vv[c] = v;
                kp += (z == 0) ? v * v : (expm1f(v) - v);
            }
            if (z == 0 && i < n) {
                *(float4*)&C[(size_t)i * FF + tx * 8]     = make_float4(vv[0], vv[1], vv[2], vv[3]);
                *(float4*)&C[(size_t)i * FF + tx * 8 + 4] = make_float4(vv[4], vv[5], vv[6], vv[7]);
            }
            #pragma unroll
            for (int o = 8; o > 0; o >>= 1) kp += __shfl_xor_sync(0xffffffffu, kp, o);
            if (tx == 0 && i < n) {
                if (z == 0) g_kldrow1[b * NN + i] = kp;
                else        g_kldrow2[b * NN + i] = kp;
            }
        }
    }
}

// ============ compaction + gather ============
__global__ void compact_gather_kernel(const int* __restrict__ data)
{
    int b = blockIdx.x;
    int t = threadIdx.x;  // 512
    __shared__ int sn;
    if (t < 32) {
        const int* d = data + b * NN;
        int cnt = 0;
        for (int base = 0; base < NN; base += 32) {
            int v = d[base + t];
            unsigned m = __ballot_sync(0xffffffffu, v != 0);
            if (v != 0) g_idx[b][cnt + __popc(m & ((1u << t) - 1u))] = base + t;
            cnt += __popc(m);
        }
        if (t == 0) { g_n[b] = cnt; sn = cnt; }
    }
    __syncthreads();
    int n = sn;
    for (int u = t; u < n * 32; u += 512)
        ((float4*)g_hc)[(size_t)b * NN * 32 + u] =
            ((const float4*)g_h0)[(size_t)g_idx[b][u >> 5] * 32 + (u & 31)];
    for (int jj = t; jj < n; jj += 512) {
        int src = g_idx[b][jj];
        g_sic[b * NN + jj] = g_si0[src];
        g_sjc[b * NN + jj] = g_sj0[src];
    }
}

// ============ attention prep: bucket structure + per-bucket prefix sums ============
#define SP_SJ 0
#define SP_VO 1536
#define SP_BO 3072
#define SP_JO 4608
#define SP_SV 6144
#define SP_SB (6144 + 16384)
#define SP_SVS (SP_SB + 16384)
#define SP_SBS (SP_SVS + 132)
#define SP_HIST (SP_SBS + 132)
#define SP_ORD (SP_HIST + 132)
#define SP_QV (SP_ORD + 1536)
#define SP_RED (SP_QV + 1536)
#define SP_TOT (SP_RED + 80)

__global__ void attn_prep()
{
    extern __shared__ float sm[];
    float* sjv = sm + SP_SJ;
    float* vso = sm + SP_VO;
    float* bso = sm + SP_BO;
    float* sjo = sm + SP_JO;
    float* Sv  = sm + SP_SV;
    float* Sb  = sm + SP_SB;
    float* SvS = sm + SP_SVS;
    float* SbS = sm + SP_SBS;
    int*   hist = (int*)(sm + SP_HIST);
    int*   ord  = (int*)(sm + SP_ORD);
    int*   qv   = (int*)(sm + SP_QV);
    float* red  = sm + SP_RED;

    int b = blockIdx.x;
    int n = g_n[b];
    int t = threadIdx.x;  // 1024
    int lane = t & 31, warp = t >> 5;
    const float* H = g_hc + (size_t)b * NN * FF;

    // min/max of sj
    float mn = 1e30f, mx = -1e30f;
    for (int u = t; u < n; u += 1024) {
        float s = g_sjc[b * NN + u];
        sjv[u] = s;
        mn = fminf(mn, s); mx = fmaxf(mx, s);
    }
    #pragma unroll
    for (int o = 16; o > 0; o >>= 1) {
        mn = fminf(mn, __shfl_xor_sync(0xffffffffu, mn, o));
        mx = fmaxf(mx, __shfl_xor_sync(0xffffffffu, mx, o));
    }
    if (lane == 0) { red[warp] = mn; red[32 + warp] = mx; }
    if (t <= NB) hist[t] = 0;
    __syncthreads();
    if (t == 0) {
        float a = 1e30f, z = -1e30f;
        for (int w = 0; w < 32; w++) { a = fminf(a, red[w]); z = fmaxf(z, red[32 + w]); }
        float span = z - a;
        float sc = (span > 1e-20f) ? (float)NB / span : 0.f;
        red[64] = z; red[65] = sc;
        g_bmax[b] = z; g_bscale[b] = sc;
    }
    __syncthreads();
    float bmax = red[64], bscale = red[65];

    // bucket assignment + histogram
    for (int u = t; u < n; u += 1024) {
        int q = (int)((bmax - sjv[u]) * bscale);
        q = max(0, min(NB - 1, q));
        qv[u] = q;
        atomicAdd(&hist[q], 1);
    }
    __syncthreads();

    // exclusive scan of histogram (warp 0, 4 buckets per lane)
    if (t < 32) {
        int base = t * 4;
        int h0 = hist[base], h1 = hist[base + 1], h2 = hist[base + 2], h3 = hist[base + 3];
        int s = h0 + h1 + h2 + h3, inc = s;
        #pragma unroll
        for (int o = 1; o < 32; o <<= 1) {
            int v = __shfl_up_sync(0xffffffffu, inc, o);
            if (lane >= o) inc += v;
        }
        int ex = inc - s;
        hist[base] = ex; hist[base + 1] = ex + h0;
        hist[base + 2] = ex + h0 + h1; hist[base + 3] = ex + h0 + h1 + h2;
        if (t == 31) hist[NB] = inc;
    }
    __syncthreads();
    if (t <= NB) g_bstart[b][t] = hist[t];

    // deterministic bucket-gather (one thread per bucket, scans in index order)
    if (t < NB) {
        int cnt = hist[t];
        for (int j = 0; j < n; j++)
            if (qv[j] == t) ord[cnt++] = j;
    }
    __syncthreads();

    // per-position arrays (bucket order)
    for (int pos = t; pos < n; pos += 1024) {
        int j = ord[pos];
        float s = sjv[j];
        float v = __expf(s), w = __expf(0.2f * s);
        sjo[pos] = s; vso[pos] = v; bso[pos] = w;
        g_ord[b][pos] = j; g_sjo[b][pos] = s; g_vso[b][pos] = v; g_bso[b][pos] = w;
    }
    __syncthreads();

    // per-bucket vector + scalar sums (8 groups of 128 channels)
    {
        int grp = t >> 7, c = t & 127;
        for (int q = grp; q < NB; q += 8) {
            int p0 = hist[q], p1 = hist[q + 1];
            float av = 0.f, ab = 0.f;
            for (int p = p0; p < p1; p++) {
                int jj = ord[p];
                float hv = H[(size_t)jj * FF + c];
                av = fmaf(vso[p], hv, av);
                ab = fmaf(bso[p], hv, ab);
            }
            Sv[q * 128 + c] = av;
            Sb[q * 128 + c] = ab;
            if (c == 0) { float s = 0.f; for (int p = p0; p < p1; p++) s += vso[p]; SvS[q] = s; }
            if (c == 1) { float s = 0.f; for (int p = p0; p < p1; p++) s += bso[p]; SbS[q] = s; }
        }
    }
    __syncthreads();

    // exclusive prefix over buckets -> global
    if (t < 128) {
        float run = 0.f;
        for (int q = 0; q < NB; q++) { g_Cv[b][q * 128 + t] = run; run += Sv[q * 128 + t]; }
        g_Cv[b][NB * 128 + t] = run;
    } else if (t < 256) {
        int c = t - 128;
        float run = 0.f;
        for (int q = 0; q < NB; q++) { g_Cb[b][q * 128 + c] = run; run += Sb[q * 128 + c]; }
        g_Cb[b][NB * 128 + c] = run;
    } else if (t == 256) {
        float run = 0.f;
        for (int q = 0; q < NB; q++) { g_CvS[b][q] = run; run += SvS[q]; }
        g_CvS[b][NB] = run;
    } else if (t == 257) {
        float run = 0.f;
        for (int q = 0; q < NB; q++) { g_CbS[b][q] = run; run += SbS[q]; }
        g_CbS[b][NB] = run;
    }
}

// ============ attention combine: chip-wide, one warp per output row ============
__global__ void attn_combine()
{
    int b = blockIdx.y;
    int n = g_n[b];
    int warp = threadIdx.x >> 5, lane = threadIdx.x & 31;
    int i = blockIdx.x * 8 + warp;
    if (i >= n) return;
    const float* H = g_hc + (size_t)b * NN * FF;

    float si = g_sic[b * NN + i];
    float uu = __expf(si), aa = __expf(0.2f * si);
    float th = -si;
    float bmax = g_bmax[b], bscale = g_bscale[b];
    int qt = (int)((bmax - th) * bscale);
    qt = max(0, min(NB - 1, qt));
    int pos0 = g_bstart[b][qt], bend = g_bstart[b][qt + 1];

    float4 pv = *(const float4*)&g_Cv[b][qt * 128 + lane * 4];
    float4 pb = *(const float4*)&g_Cb[b][qt * 128 + lane * 4];
    float pvs = g_CvS[b][qt], pbs = g_CbS[b][qt];

    for (int p = pos0; p < bend; p++) {
        float s = g_sjo[b][p];
        if (s >= th) {
            int jj = g_ord[b][p];
            float w = g_vso[b][p], wb = g_bso[b][p];
            float4 hv = *(const float4*)&H[(size_t)jj * FF + lane * 4];
            pv.x = fmaf(w, hv.x, pv.x); pv.y = fmaf(w, hv.y, pv.y);
            pv.z = fmaf(w, hv.z, pv.z); pv.w = fmaf(w, hv.w, pv.w);
            pb.x = fmaf(wb, hv.x, pb.x); pb.y = fmaf(wb, hv.y, pb.y);
            pb.z = fmaf(wb, hv.z, pb.z); pb.w = fmaf(wb, hv.w, pb.w);
            pvs += w; pbs += wb;
        }
    }

    float totbs = g_CbS[b][NB];
    float4 tb = *(const float4*)&g_Cb[b][NB * 128 + lane * 4];
    float inv = 1.f / (uu * pvs + aa * (totbs - pbs));
    float4 o;
    o.x = (uu * pv.x + aa * (tb.x - pb.x)) * inv;
    o.y = (uu * pv.y + aa * (tb.y - pb.y)) * inv;
    o.z = (uu * pv.z + aa * (tb.z - pb.z)) * inv;
    o.w = (uu * pv.w + aa * (tb.w - pb.w)) * inv;
    o.x = (o.x > 0.f) ? o.x : expm1f(o.x);
    o.y = (o.y > 0.f) ? o.y : expm1f(o.y);
    o.z = (o.z > 0.f) ? o.z : expm1f(o.z);
    o.w = (o.w > 0.f) ? o.w : expm1f(o.w);
    *(float4*)&g_xc[(size_t)b * NN * FF + (size_t)i * FF + lane * 4] = o;
}

// ============ decoder: single attention row (last node) per sample ============
__global__ void dec_attn_kernel()
{
    int b = blockIdx.x;
    int n = g_n[b];
    const float* H = g_hc + (size_t)b * NN * FF;
    const float* sj = g_sjc + b * NN;
    float sLs = g_sL[0];
    int t = threadIdx.x; // 128
    __shared__ float shw[128];
    float acc0 = 0.f, acc1 = 0.f, acc2 = 0.f, acc3 = 0.f, dsum = 0.f;
    for (int j0 = 0; j0 < n; j0 += 128) {
        int j = j0 + t;
        float w = 0.f;
        if (j < n) { float e = sLs + sj[j]; e = (e >= 0.f) ? e : 0.2f * e; w = __expf(e); }
        __syncthreads();
        shw[t] = w; dsum += w;
        __syncthreads();
        int lim = (n - j0 < 128) ? (n - j0) : 128;
        int jj = 0;
        for (; jj + 4 <= lim; jj += 4) {
            acc0 += shw[jj + 0] * H[(size_t)(j0 + jj + 0) * FF + t];
            acc1 += shw[jj + 1] * H[(size_t)(j0 + jj + 1) * FF + t];
            acc2 += shw[jj + 2] * H[(size_t)(j0 + jj + 2) * FF + t];
            acc3 += shw[jj + 3] * H[(size_t)(j0 + jj + 3) * FF + t];
        }
        for (; jj < lim; jj++) acc0 += shw[jj] * H[(size_t)(j0 + jj) * FF + t];
    }
    float acc = acc0 + acc1 + acc2 + acc3;
    __shared__ float shr[128];
    __syncthreads();
    shr[t] = dsum;
    __syncthreads();
    for (int s = 64; s > 0; s >>= 1) { if (t < s) shr[t] += shr[t + s]; __syncthreads(); }
    float eL = sLs + g_sL[1]; eL = (eL >= 0.f) ? eL : 0.2f * eL;
    float wL = __expf(eL);
    float denom = shr[0] + wL;
    acc += wL * g_hlast[t];
    g_feat[b * FF + t] = fmaxf(acc / denom, 0.f);
}

// ============ output MLP + KLD total ============
__global__ void final_kernel(const float* __restrict__ W1, const float* __restrict__ b1,
                             const float* __restrict__ W2, const float* __restrict__ b2,
                             float* __restrict__ out)
{
    int t = threadIdx.x; // 256
    __shared__ float shh[16 * 128];
    for (int u = t; u < 16 * 128; u += 256) {
        int b = u >> 7, c = u & 127;
        const float* f = g_feat + b * FF;
        float acc = b1[c];
        for (int k = 0; k < FF; k++) acc += f[k] * W1[k * FF + c];
        shh[u] = fmaxf(acc, 0.f);
    }
    __shared__ float shr[256];
    float kld = 0.f;
    for (int b = 0; b < BB; b++) {
        int n = g_n[b];
        float p = 0.f;
        for (int r = t; r < n; r += 256) p += g_kldrow1[b * NN + r] + g_kldrow2[b * NN + r];
        shr[t] = p;
        __syncthreads();
        for (int s = 128; s > 0; s >>= 1) { if (t < s) shr[t] += shr[t + s]; __syncthreads(); }
        if (t == 0) kld += 0.5f * shr[0] / fmaxf((float)n, 1.f);
        __syncthreads();
    }
    __syncthreads();
    if (t < 16) {
        float acc = b2[0];
        for (int c = 0; c < FF; c++) acc += shh[t * FF + c] * W2[c];
        out[t] = acc;
    }
    if (t == 0) out[16] = kld;
}

// ============ launch ============
extern "C" void kernel_launch(void* const* d_in, const int* in_sizes, int n_in,
                              void* d_out, int out_size)
{
    (void)in_sizes; (void)n_in; (void)out_size;
    const int*   data  = (const int*)d_in[0];
    const float* embed = (const float*)d_in[1];
    const float* encW  = (const float*)d_in[2];
    const float* eas   = (const float*)d_in[3];
    const float* ead   = (const float*)d_in[4];
    const float* pW    = (const float*)d_in[5];
    const float* pb    = (const float*)d_in[6];
    const float* dW    = (const float*)d_in[7];
    const float* das   = (const float*)d_in[8];
    const float* dad   = (const float*)d_in[9];
    const float* oW1   = (const float*)d_in[10];
    const float* ob1   = (const float*)d_in[11];
    const float* oW2   = (const float*)d_in[12];
    const float* ob2   = (const float*)d_in[13];
    float* out = (float*)d_out;

    const int SMEMB = SP_TOT * 4;
    cudaFuncSetAttribute(attn_prep, cudaFuncAttributeMaxDynamicSharedMemorySize, SMEMB);

    // 1) layer-0 h + si0/sj0 (+ hlast side-block)
    gemm2<0><<<dim3(25, 1), 128>>>(embed, encW, FF, nullptr, eas, ead, -1, 0, dW, das, dad);
    // 2) compaction + gather
    compact_gather_kernel<<<16, 512>>>(data);
    // 3) encoder layer 0 attention
    attn_prep<<<16, 1024, SMEMB>>>();
    attn_combine<<<dim3(192, 16), 256>>>();
    // 4) encoder layer 1 linear + si/sj
    gemm2<1><<<dim3(24, 16), 128>>>(nullptr, encW + FF * FF, FF, nullptr,
                                    eas + FF, ead + FF, 2, 1, nullptr, nullptr, nullptr);
    // 5) encoder layer 1 attention
    attn_prep<<<16, 1024, SMEMB>>>();
    attn_combine<<<dim3(192, 16), 256>>>();
    // 6) param head (mean z=0, sigma z=1)
    gemm2<2><<<dim3(24, 16, 2), 128>>>(nullptr, pW, 2 * FF, pb, nullptr, nullptr,
                                       2, 3, nullptr, nullptr, nullptr);
    // 7) decoder linear + dec si/sj
    gemm2<1><<<dim3(24, 16), 128>>>(nullptr, dW, FF, nullptr, das, dad,
                                    3, 1, nullptr, nullptr, nullptr);
    // 8) decoder single-row attention
    dec_attn_kernel<<<16, 128>>>();
    // 9) output MLP + KLD
    final_kernel<<<1, 256>>>(oW1, ob1, oW2, ob2, out);
}

// round 9
// speedup vs baseline: 3.1551x; 1.1297x over previous
#include <cuda_runtime.h>
#include <math.h>

#define BB 16
#define NN 1536
#define FF 128
#define NB 128
#define NCHK 48

// ---------------- scratch (device globals; no allocation) ----------------
__device__ __align__(16) float g_h0[NN * FF];
__device__ float g_si0[NN];
__device__ float g_sj0[NN];
__device__ int   g_idx[BB][NN];
__device__ int   g_n[BB];
__device__ __align__(16) float g_hc[(size_t)BB * NN * FF];   // layer-0 h compacted; later dec h
__device__ __align__(16) float g_xc[(size_t)BB * NN * FF];   // layer-1 h
__device__ __align__(16) float g_mean[(size_t)BB * NN * FF]; // layer-2 x (elu output)
__device__ float g_sic[BB * NN];
__device__ float g_sjc[BB * NN];
__device__ float g_kldrow1[BB * NN];
__device__ float g_kldrow2[BB * NN];
__device__ __align__(16) float g_hlast[FF];
__device__ float g_sL[2];
__device__ float g_feat[BB * FF];
__device__ __align__(16) float g_Wcomb[FF * FF];
__device__ __align__(16) float g_bcomb[FF];

// bucket-factorized attention scratch
__device__ int   g_ord[BB][NN];
__device__ float g_sjo[BB][NN];
__device__ float g_vso[BB][NN];
__device__ float g_bso[BB][NN];
__device__ int   g_bstart[BB][NB + 4];
__device__ __align__(16) float g_Cv[BB][(NB + 1) * FF];
__device__ __align__(16) float g_Cb[BB][(NB + 1) * FF];
__device__ float g_CvS[BB][NB + 1];
__device__ float g_CbS[BB][NB + 1];
__device__ float g_bmax[BB];
__device__ float g_bscale[BB];

__device__ __forceinline__ float* scratchBuf(int id) {
    switch (id) {
        case 0: return g_h0;
        case 1: return g_hc;
        case 2: return g_xc;
        default: return g_mean;
    }
}

// ============ GEMM: 64x128 tile, 128 threads, 8x8/thread ============
// MODE 0: layer-0 (blocks 0-23: embed@encW0 -> g_h0 + si0/sj0; blk 24: hlast+bcomb; blks 25,26: Wcomb)
// MODE 1: batched x@W -> scratch cId + sic/sjc (unused this round; kept for clarity)
// MODE 2: z=0 mean-KLD, z=1 sigma-KLD, z=2 dec linear via Wcomb -> g_hc + sic/sjc
template <int MODE>
__global__ void gemm2(const float* __restrict__ Aext,
                      const float* __restrict__ W, int ldW,
                      const float* __restrict__ bias,
                      const float* __restrict__ asrc, const float* __restrict__ adst,
                      int aId, int cId,
                      const float* __restrict__ hW, const float* __restrict__ hs2,
                      const float* __restrict__ hd2,
                      const float* __restrict__ pWm, const float* __restrict__ pbm)
{
    int t = threadIdx.x;  // 128
    if (MODE == 0 && blockIdx.x == 24) {
        // hlast = embed[-1] @ dec_W (+ scores), bcomb = pb_mean @ dec_W
        __shared__ float sh[128];
        const float* e = Aext + (size_t)NN * FF;
        float acc = 0.f;
        #pragma unroll 8
        for (int k = 0; k < FF; k++) acc += e[k] * hW[k * FF + t];
        g_hlast[t] = acc;
        sh[t] = acc * hs2[t];
        __syncthreads();
        for (int s = 64; s > 0; s >>= 1) { if (t < s) sh[t] += sh[t + s]; __syncthreads(); }
        if (t == 0) g_sL[0] = sh[0];
        __syncthreads();
        sh[t] = acc * hd2[t];
        __syncthreads();
        for (int s = 64; s > 0; s >>= 1) { if (t < s) sh[t] += sh[t + s]; __syncthreads(); }
        if (t == 0) g_sL[1] = sh[0];
        float bc = 0.f;
        #pragma unroll 8
        for (int m = 0; m < FF; m++) bc += pbm[m] * hW[m * FF + t];
        g_bcomb[t] = bc;
        return;
    }

    bool wcomb = (MODE == 0 && blockIdx.x >= 25);
    int b = (MODE == 0) ? 0 : blockIdx.y;
    int n = wcomb ? FF : ((MODE == 0) ? NN : g_n[b]);
    int i0 = wcomb ? (blockIdx.x - 25) * 64 : blockIdx.x * 64;
    if (i0 >= n) return;

    const float* A; int lda;
    if (wcomb)          { A = pWm; lda = 2 * FF; }
    else if (MODE == 0) { A = Aext; lda = FF; }
    else                { A = scratchBuf(aId) + (size_t)b * NN * FF; lda = FF; }

    const float* Wp; const float* bp = nullptr; int ldw;
    if (wcomb) { Wp = hW; ldw = FF; }
    else if (MODE == 2) {
        int z = blockIdx.z;
        if (z == 0)      { Wp = W;       bp = bias;      ldw = ldW; }
        else if (z == 1) { Wp = W + FF;  bp = bias + FF; ldw = ldW; }
        else             { Wp = g_Wcomb; bp = g_bcomb;   ldw = FF; }
    } else { Wp = W; ldw = ldW; }

    float* C;
    if (wcomb) C = g_Wcomb;
    else if (MODE == 2 && blockIdx.z == 2) C = g_hc + (size_t)b * NN * FF;
    else C = scratchBuf(cId) + ((MODE == 0) ? 0 : (size_t)b * NN * FF);

    __shared__ float shA[16][68];
    __shared__ __align__(16) float shW[16][128];

    int ty = t >> 4, tx = t & 15;
    float acc[8][8] = {};

    for (int k0 = 0; k0 < FF; k0 += 16) {
        __syncthreads();
        #pragma unroll
        for (int u = t; u < 256; u += 128) {
            int row = u >> 2, c4 = u & 3;
            float4 v = make_float4(0.f, 0.f, 0.f, 0.f);
            if (i0 + row < n) v = *(const float4*)&A[(size_t)(i0 + row) * lda + k0 + c4 * 4];
            shA[c4 * 4 + 0][row] = v.x;
            shA[c4 * 4 + 1][row] = v.y;
            shA[c4 * 4 + 2][row] = v.z;
            shA[c4 * 4 + 3][row] = v.w;
        }
        #pragma unroll
        for (int u = t; u < 512; u += 128) {
            int r = u >> 5, c4 = u & 31;
            *(float4*)&shW[r][c4 * 4] = *(const float4*)&Wp[(size_t)(k0 + r) * ldw + c4 * 4];
        }
        __syncthreads();
        #pragma unroll
        for (int k = 0; k < 16; k++) {
            float av[8], bv[8];
            *(float4*)&av[0] = *(float4*)&shA[k][ty * 8];
            *(float4*)&av[4] = *(float4*)&shA[k][ty * 8 + 4];
            *(float4*)&bv[0] = *(float4*)&shW[k][tx * 8];
            *(float4*)&bv[4] = *(float4*)&shW[k][tx * 8 + 4];
            #pragma unroll
            for (int r = 0; r < 8; r++)
                #pragma unroll
                for (int c = 0; c < 8; c++)
                    acc[r][c] = fmaf(av[r], bv[c], acc[r][c]);
        }
    }

    if (wcomb) {
        #pragma unroll
        for (int r = 0; r < 8; r++) {
            int i = i0 + ty * 8 + r;
            *(float4*)&C[(size_t)i * FF + tx * 8]     = make_float4(acc[r][0], acc[r][1], acc[r][2], acc[r][3]);
            *(float4*)&C[(size_t)i * FF + tx * 8 + 4] = make_float4(acc[r][4], acc[r][5], acc[r][6], acc[r][7]);
        }
        return;
    }

    if (MODE == 2 && blockIdx.z <= 1) {
        int z = blockIdx.z;
        float bv8[8];
        #pragma unroll
        for (int c = 0; c < 8; c++) bv8[c] = bp[tx * 8 + c];
        #pragma unroll
        for (int r = 0; r < 8; r++) {
            int i = i0 + ty * 8 + r;
            float kp = 0.f;
            #pragma unroll
            for (int c = 0; c < 8; c++) {
                float v = acc[r][c] + bv8[c];
                kp += (z == 0) ? v * v : (expm1f(v) - v);
            }
            #pragma unroll
            for (int o = 8; o > 0; o >>= 1) kp += __shfl_xor_sync(0xffffffffu, kp, o);
            if (tx == 0 && i < n) {
                if (z == 0) g_kldrow1[b * NN + i] = kp;
                else        g_kldrow2[b * NN + i] = kp;
            }
        }
        return;
    }

    // store + si/sj epilogue (MODE 0 main, MODE 1, MODE 2 z==2)
    float as8[8], ad8[8], bb8[8];
    #pragma unroll
    for (int c = 0; c < 8; c++) {
        as8[c] = asrc[tx * 8 + c];
        ad8[c] = adst[tx * 8 + c];
        bb8[c] = bp ? bp[tx * 8 + c] : 0.f;
    }
    float ss[8], sd[8];
    #pragma unroll
    for (int r = 0; r < 8; r++) {
        int i = i0 + ty * 8 + r;
        float s1 = 0.f, s2 = 0.f;
        float vv[8];
        #pragma unroll
        for (int c = 0; c < 8; c++) {
            float v = acc[r][c] + bb8[c];
            vv[c] = v;
            s1 += v * as8[c]; s2 += v * ad8[c];
        }
        ss[r] = s1; sd[r] = s2;
        if (i < n) {
            *(float4*)&C[(size_t)i * FF + tx * 8]     = make_float4(vv[0], vv[1], vv[2], vv[3]);
            *(float4*)&C[(size_t)i * FF + tx * 8 + 4] = make_float4(vv[4], vv[5], vv[6], vv[7]);
        }
    }
    #pragma unroll
    for (int r = 0; r < 8; r++) {
        #pragma unroll
        for (int o = 8; o > 0; o >>= 1) {
            ss[r] += __shfl_xor_sync(0xffffffffu, ss[r], o);
            sd[r] += __shfl_xor_sync(0xffffffffu, sd[r], o);
        }
    }
    if (tx == 0) {
        #pragma unroll
        for (int r = 0; r < 8; r++) {
            int i = i0 + ty * 8 + r;
            if (i < n) {
                if (MODE == 0) { g_si0[i] = ss[r]; g_sj0[i] = sd[r]; }
                else           { g_sic[b * NN + i] = ss[r]; g_sjc[b * NN + i] = sd[r]; }
            }
        }
    }
}

// ============ compaction + gather ============
__global__ void compact_gather_kernel(const int* __restrict__ data)
{
    int b = blockIdx.x;
    int t = threadIdx.x;  // 512
    __shared__ int sn;
    if (t < 32) {
        const int* d = data + b * NN;
        int cnt = 0;
        for (int base = 0; base < NN; base += 32) {
            int v = d[base + t];
            unsigned m = __ballot_sync(0xffffffffu, v != 0);
            if (v != 0) g_idx[b][cnt + __popc(m & ((1u << t) - 1u))] = base + t;
            cnt += __popc(m);
        }
        if (t == 0) { g_n[b] = cnt; sn = cnt; }
    }
    __syncthreads();
    int n = sn;
    for (int u = t; u < n * 32; u += 512)
        ((float4*)g_hc)[(size_t)b * NN * 32 + u] =
            ((const float4*)g_h0)[(size_t)g_idx[b][u >> 5] * 32 + (u & 31)];
    for (int jj = t; jj < n; jj += 512) {
        int src = g_idx[b][jj];
        g_sic[b * NN + jj] = g_si0[src];
        g_sjc[b * NN + jj] = g_sj0[src];
    }
}

// ============ attention prep: bucket structure + per-bucket prefix sums ============
// smem layout (floats)
#define SQ_SJV  0
#define SQ_QV   (SQ_SJV + 1536)
#define SQ_RNK  (SQ_QV + 1536)
#define SQ_ORD  (SQ_RNK + 1536)
#define SQ_CNT  (SQ_ORD + 1536)                 // NCHK*NB ints = 6144
#define SQ_TOT  (SQ_CNT + NCHK * NB)            // 128
#define SQ_BST  (SQ_TOT + 128)                  // 132
#define SQ_SJO  (SQ_BST + 132)
#define SQ_VSO  (SQ_SJO + 1536)
#define SQ_BSO  (SQ_VSO + 1536)
#define SQ_SV   (SQ_BSO + 1536)                 // NB*128
#define SQ_SB   (SQ_SV + NB * 128)
#define SQ_SVS  (SQ_SB + NB * 128)              // 132
#define SQ_SBS  (SQ_SVS + 132)
#define SQ_RED  (SQ_SBS + 132)                  // 80
#define SQ_TOTF (SQ_RED + 80)

__global__ void attn_prep(int hId)
{
    extern __shared__ float sm[];
    float* sjv = sm + SQ_SJV;
    int*   qv  = (int*)(sm + SQ_QV);
    int*   rnk = (int*)(sm + SQ_RNK);
    int*   ord = (int*)(sm + SQ_ORD);
    int*   cnt = (int*)(sm + SQ_CNT);
    int*   tot = (int*)(sm + SQ_TOT);
    int*   bst = (int*)(sm + SQ_BST);
    float* sjo = sm + SQ_SJO;
    float* vso = sm + SQ_VSO;
    float* bso = sm + SQ_BSO;
    float* Sv  = sm + SQ_SV;
    float* Sb  = sm + SQ_SB;
    float* SvS = sm + SQ_SVS;
    float* SbS = sm + SQ_SBS;
    float* red = sm + SQ_RED;

    int b = blockIdx.x;
    int n = g_n[b];
    int t = threadIdx.x;  // 1024
    int lane = t & 31, warp = t >> 5;
    const float* H = (hId ? g_xc : g_hc) + (size_t)b * NN * FF;

    // min/max of sj
    float mn = 1e30f, mx = -1e30f;
    for (int u = t; u < n; u += 1024) {
        float s = g_sjc[b * NN + u];
        sjv[u] = s;
        mn = fminf(mn, s); mx = fmaxf(mx, s);
    }
    #pragma unroll
    for (int o = 16; o > 0; o >>= 1) {
        mn = fminf(mn, __shfl_xor_sync(0xffffffffu, mn, o));
        mx = fmaxf(mx, __shfl_xor_sync(0xffffffffu, mx, o));
    }
    if (lane == 0) { red[warp] = mn; red[32 + warp] = mx; }
    for (int u = t; u < NCHK * NB; u += 1024) cnt[u] = 0;
    __syncthreads();
    if (t == 0) {
        float a = 1e30f, z = -1e30f;
        for (int w = 0; w < 32; w++) { a = fminf(a, red[w]); z = fmaxf(z, red[32 + w]); }
        float span = z - a;
        float sc = (span > 1e-20f) ? (float)NB / span : 0.f;
        red[64] = z; red[65] = sc;
        g_bmax[b] = z; g_bscale[b] = sc;
    }
    __syncthreads();
    float bmax = red[64], bscale = red[65];

    // bucket + stable rank via match_any (chunk = 32 consecutive indices per warp)
    int nchk = (n + 31) >> 5;
    for (int ch = warp; ch < nchk; ch += 32) {
        int j = ch * 32 + lane;
        int q = -1;
        if (j < n) {
            q = (int)((bmax - sjv[j]) * bscale);
            q = max(0, min(NB - 1, q));
        }
        unsigned mask = __match_any_sync(0xffffffffu, q);
        int rank = __popc(mask & ((1u << lane) - 1u));
        if (j < n) {
            qv[j] = q; rnk[j] = rank;
            if (rank == 0) cnt[ch * NB + q] = __popc(mask);
        }
    }
    __syncthreads();

    // per-bucket exclusive prefix over chunks + totals
    if (t < NB) {
        int run = 0;
        for (int ch = 0; ch < nchk; ch++) {
            int c = cnt[ch * NB + t];
            cnt[ch * NB + t] = run;
            run += c;
        }
        tot[t] = run;
    }
    __syncthreads();
    // exclusive scan of tot -> bst (warp 0, 4 buckets per lane)
    if (t < 32) {
        int base = t * 4;
        int h0 = tot[base], h1 = tot[base + 1], h2 = tot[base + 2], h3 = tot[base + 3];
        int s = h0 + h1 + h2 + h3, inc = s;
        #pragma unroll
        for (int o = 1; o < 32; o <<= 1) {
            int v = __shfl_up_sync(0xffffffffu, inc, o);
            if (lane >= o) inc += v;
        }
        int ex = inc - s;
        bst[base] = ex; bst[base + 1] = ex + h0;
        bst[base + 2] = ex + h0 + h1; bst[base + 3] = ex + h0 + h1 + h2;
        if (t == 31) bst[NB] = inc;
    }
    __syncthreads();
    if (t <= NB) g_bstart[b][t] = bst[t];

    // scatter to bucket order
    for (int j = t; j < n; j += 1024) {
        int q = qv[j];
        int pos = bst[q] + cnt[(j >> 5) * NB + q] + rnk[j];
        ord[pos] = j;
    }
    __syncthreads();

    // per-position arrays (bucket order)
    for (int pos = t; pos < n; pos += 1024) {
        int j = ord[pos];
        float s = sjv[j];
        float v = __expf(s), w = __expf(0.2f * s);
        sjo[pos] = s; vso[pos] = v; bso[pos] = w;
        g_ord[b][pos] = j; g_sjo[b][pos] = s; g_vso[b][pos] = v; g_bso[b][pos] = w;
    }
    __syncthreads();

    // per-bucket vector + scalar sums (8 groups of 128 channels)
    {
        int grp = t >> 7, c = t & 127;
        for (int q = grp; q < NB; q += 8) {
            int p0 = bst[q], p1 = bst[q + 1];
            float av = 0.f, ab = 0.f;
            for (int p = p0; p < p1; p++) {
                int jj = ord[p];
                float hv = H[(size_t)jj * FF + c];
                av = fmaf(vso[p], hv, av);
                ab = fmaf(bso[p], hv, ab);
            }
            Sv[q * 128 + c] = av;
            Sb[q * 128 + c] = ab;
            if (c == 0) { float s = 0.f; for (int p = p0; p < p1; p++) s += vso[p]; SvS[q] = s; }
            if (c == 1) { float s = 0.f; for (int p = p0; p < p1; p++) s += bso[p]; SbS[q] = s; }
        }
    }
    __syncthreads();

    // exclusive prefix over buckets -> global
    if (t < 128) {
        float run = 0.f;
        for (int q = 0; q < NB; q++) { g_Cv[b][q * 128 + t] = run; run += Sv[q * 128 + t]; }
        g_Cv[b][NB * 128 + t] = run;
    } else if (t < 256) {
        int c = t - 128;
        float run = 0.f;
        for (int q = 0; q < NB; q++) { g_Cb[b][q * 128 + c] = run; run += Sb[q * 128 + c]; }
        g_Cb[b][NB * 128 + c] = run;
    } else if (t == 256) {
        float run = 0.f;
        for (int q = 0; q < NB; q++) { g_CvS[b][q] = run; run += SvS[q]; }
        g_CvS[b][NB] = run;
    } else if (t == 257) {
        float run = 0.f;
        for (int q = 0; q < NB; q++) { g_CbS[b][q] = run; run += SbS[q]; }
        g_CbS[b][NB] = run;
    }
}

// ============ per-row combine (shared by attn_combine and combine_gemm) ============
__device__ __forceinline__ float4 combine_row(int b, int i, int lane, const float* __restrict__ H)
{
    float si = g_sic[b * NN + i];
    float uu = __expf(si), aa = __expf(0.2f * si);
    float th = -si;
    int qt = (int)((g_bmax[b] - th) * g_bscale[b]);
    qt = max(0, min(NB - 1, qt));
    int p0 = g_bstart[b][qt], p1 = g_bstart[b][qt + 1];

    float4 pv = *(const float4*)&g_Cv[b][qt * 128 + lane * 4];
    float4 pb = *(const float4*)&g_Cb[b][qt * 128 + lane * 4];
    float pvs = g_CvS[b][qt], pbs = g_CbS[b][qt];

    for (int p = p0; p < p1; p++) {
        float s = g_sjo[b][p];
        if (s >= th) {
            int jj = g_ord[b][p];
            float w = g_vso[b][p], wb = g_bso[b][p];
            float4 hv = *(const float4*)&H[(size_t)jj * FF + lane * 4];
            pv.x = fmaf(w, hv.x, pv.x); pv.y = fmaf(w, hv.y, pv.y);
            pv.z = fmaf(w, hv.z, pv.z); pv.w = fmaf(w, hv.w, pv.w);
            pb.x = fmaf(wb, hv.x, pb.x); pb.y = fmaf(wb, hv.y, pb.y);
            pb.z = fmaf(wb, hv.z, pb.z); pb.w = fmaf(wb, hv.w, pb.w);
            pvs += w; pbs += wb;
        }
    }

    float totbs = g_CbS[b][NB];
    float4 tb = *(const float4*)&g_Cb[b][NB * 128 + lane * 4];
    float inv = 1.f / (uu * pvs + aa * (totbs - pbs));
    float4 o;
    o.x = (uu * pv.x + aa * (tb.x - pb.x)) * inv;
    o.y = (uu * pv.y + aa * (tb.y - pb.y)) * inv;
    o.z = (uu * pv.z + aa * (tb.z - pb.z)) * inv;
    o.w = (uu * pv.w + aa * (tb.w - pb.w)) * inv;
    o.x = (o.x > 0.f) ? o.x : expm1f(o.x);
    o.y = (o.y > 0.f) ? o.y : expm1f(o.y);
    o.z = (o.z > 0.f) ? o.z : expm1f(o.z);
    o.w = (o.w > 0.f) ? o.w : expm1f(o.w);
    return o;
}

// ============ standalone combine (layer 2): H=hId buffer -> out oId buffer ============
__global__ void attn_combine(int hId, int oId)
{
    int b = blockIdx.y;
    int n = g_n[b];
    int warp = threadIdx.x >> 5, lane = threadIdx.x & 31;
    int i = blockIdx.x * 8 + warp;
    if (i >= n) return;
    const float* H = (hId ? g_xc : g_hc) + (size_t)b * NN * FF;
    float* O = scratchBuf(oId) + (size_t)b * NN * FF;
    float4 o = combine_row(b, i, lane, H);
    *(float4*)&O[(size_t)i * FF + lane * 4] = o;
}

// ============ fused combine + GEMM (layer 1): x = combine(g_hc); h1 = x@W -> g_xc + sic/sjc ============
__global__ void combine_gemm(const float* __restrict__ W,
                             const float* __restrict__ asrc, const float* __restrict__ adst)
{
    __shared__ float shX[64][132];
    __shared__ float shA[16][68];
    __shared__ __align__(16) float shW[16][128];

    int b = blockIdx.y;
    int n = g_n[b];
    int i0 = blockIdx.x * 64;
    if (i0 >= n) return;
    int t = threadIdx.x;  // 128
    int lane = t & 31, warp = t >> 5;
    const float* H = g_hc + (size_t)b * NN * FF;

    // combine 16 rows per warp into smem
    for (int r = 0; r < 16; r++) {
        int il = warp * 16 + r;
        int i = i0 + il;
        float4 o = make_float4(0.f, 0.f, 0.f, 0.f);
        if (i < n) o = combine_row(b, i, lane, H);
        *(float4*)&shX[il][lane * 4] = o;
    }
    __syncthreads();

    // GEMM from smem A
    int ty = t >> 4, tx = t & 15;
    float acc[8][8] = {};
    for (int k0 = 0; k0 < FF; k0 += 16) {
        __syncthreads();
        #pragma unroll
        for (int u = t; u < 1024; u += 128) {
            int row = u >> 4, k = u & 15;
            shA[k][row] = shX[row][k0 + k];
        }
        #pragma unroll
        for (int u = t; u < 512; u += 128) {
            int r = u >> 5, c4 = u & 31;
            *(float4*)&shW[r][c4 * 4] = *(const float4*)&W[(size_t)(k0 + r) * FF + c4 * 4];
        }
        __syncthreads();
        #pragma unroll
        for (int k = 0; k < 16; k++) {
            float av[8], bv[8];
            *(float4*)&av[0] = *(float4*)&shA[k][ty * 8];
            *(float4*)&av[4] = *(float4*)&shA[k][ty * 8 + 4];
            *(float4*)&bv[0] = *(float4*)&shW[k][tx * 8];
            *(float4*)&bv[4] = *(float4*)&shW[k][tx * 8 + 4];
            #pragma unroll
            for (int r = 0; r < 8; r++)
                #pragma unroll
                for (int c = 0; c < 8; c++)
                    acc[r][c] = fmaf(av[r], bv[c], acc[r][c]);
        }
    }

    float* C = g_xc + (size_t)b * NN * FF;
    float as8[8], ad8[8];
    #pragma unroll
    for (int c = 0; c < 8; c++) { as8[c] = asrc[tx * 8 + c]; ad8[c] = adst[tx * 8 + c]; }
    float ss[8], sd[8];
    #pragma unroll
    for (int r = 0; r < 8; r++) {
        int i = i0 + ty * 8 + r;
        float s1 = 0.f, s2 = 0.f;
        #pragma unroll
        for (int c = 0; c < 8; c++) { s1 += acc[r][c] * as8[c]; s2 += acc[r][c] * ad8[c]; }
        ss[r] = s1; sd[r] = s2;
        if (i < n) {
            *(float4*)&C[(size_t)i * FF + tx * 8]     = make_float4(acc[r][0], acc[r][1], acc[r][2], acc[r][3]);
            *(float4*)&C[(size_t)i * FF + tx * 8 + 4] = make_float4(acc[r][4], acc[r][5], acc[r][6], acc[r][7]);
        }
    }
    #pragma unroll
    for (int r = 0; r < 8; r++) {
        #pragma unroll
        for (int o = 8; o > 0; o >>= 1) {
            ss[r] += __shfl_xor_sync(0xffffffffu, ss[r], o);
            sd[r] += __shfl_xor_sync(0xffffffffu, sd[r], o);
        }
    }
    if (tx == 0) {
        #pragma unroll
        for (int r = 0; r < 8; r++) {
            int i = i0 + ty * 8 + r;
            if (i < n) { g_sic[b * NN + i] = ss[r]; g_sjc[b * NN + i] = sd[r]; }
        }
    }
}

// ============ decoder: single attention row (last node) per sample ============
__global__ void dec_attn_kernel()
{
    int b = blockIdx.x;
    int n = g_n[b];
    const float* H = g_hc + (size_t)b * NN * FF;   // dec h
    const float* sj = g_sjc + b * NN;
    float sLs = g_sL[0];
    int t = threadIdx.x; // 128
    __shared__ float shw[128];
    float acc0 = 0.f, acc1 = 0.f, acc2 = 0.f, acc3 = 0.f, dsum = 0.f;
    for (int j0 = 0; j0 < n; j0 += 128) {
        int j = j0 + t;
        float w = 0.f;
        if (j < n) { float e = sLs + sj[j]; e = (e >= 0.f) ? e : 0.2f * e; w = __expf(e); }
        __syncthreads();
        shw[t] = w; dsum += w;
        __syncthreads();
        int lim = (n - j0 < 128) ? (n - j0) : 128;
        int jj = 0;
        for (; jj + 4 <= lim; jj += 4) {
            acc0 += shw[jj + 0] * H[(size_t)(j0 + jj + 0) * FF + t];
            acc1 += shw[jj + 1] * H[(size_t)(j0 + jj + 1) * FF + t];
            acc2 += shw[jj + 2] * H[(size_t)(j0 + jj + 2) * FF + t];
            acc3 += shw[jj + 3] * H[(size_t)(j0 + jj + 3) * FF + t];
        }
        for (; jj < lim; jj++) acc0 += shw[jj] * H[(size_t)(j0 + jj) * FF + t];
    }
    float acc = acc0 + acc1 + acc2 + acc3;
    __shared__ float shr[128];
    __syncthreads();
    shr[t] = dsum;
    __syncthreads();
    for (int s = 64; s > 0; s >>= 1) { if (t < s) shr[t] += shr[t + s]; __syncthreads(); }
    float eL = sLs + g_sL[1]; eL = (eL >= 0.f) ? eL : 0.2f * eL;
    float wL = __expf(eL);
    float denom = shr[0] + wL;
    acc += wL * g_hlast[t];
    g_feat[b * FF + t] = fmaxf(acc / denom, 0.f);
}

// ============ output MLP + KLD total ============
__global__ void final_kernel(const float* __restrict__ W1, const float* __restrict__ b1,
                             const float* __restrict__ W2, const float* __restrict__ b2,
                             float* __restrict__ out)
{
    int t = threadIdx.x; // 256
    __shared__ float shh[16 * 128];
    for (int u = t; u < 16 * 128; u += 256) {
        int b = u >> 7, c = u & 127;
        const float* f = g_feat + b * FF;
        float acc = b1[c];
        for (int k = 0; k < FF; k++) acc += f[k] * W1[k * FF + c];
        shh[u] = fmaxf(acc, 0.f);
    }
    __shared__ float shr[256];
    float kld = 0.f;
    for (int b = 0; b < BB; b++) {
        int n = g_n[b];
        float p = 0.f;
        for (int r = t; r < n; r += 256) p += g_kldrow1[b * NN + r] + g_kldrow2[b * NN + r];
        shr[t] = p;
        __syncthreads();
        for (int s = 128; s > 0; s >>= 1) { if (t < s) shr[t] += shr[t + s]; __syncthreads(); }
        if (t == 0) kld += 0.5f * shr[0] / fmaxf((float)n, 1.f);
        __syncthreads();
    }
    __syncthreads();
    if (t < 16) {
        float acc = b2[0];
        for (int c = 0; c < FF; c++) acc += shh[t * FF + c] * W2[c];
        out[t] = acc;
    }
    if (t == 0) out[16] = kld;
}

// ============ launch ============
extern "C" void kernel_launch(void* const* d_in, const int* in_sizes, int n_in,
                              void* d_out, int out_size)
{
    (void)in_sizes; (void)n_in; (void)out_size;
    const int*   data  = (const int*)d_in[0];
    const float* embed = (const float*)d_in[1];
    const float* encW  = (const float*)d_in[2];
    const float* eas   = (const float*)d_in[3];
    const float* ead   = (const float*)d_in[4];
    const float* pW    = (const float*)d_in[5];
    const float* pb    = (const float*)d_in[6];
    const float* dW    = (const float*)d_in[7];
    const float* das   = (const float*)d_in[8];
    const float* dad   = (const float*)d_in[9];
    const float* oW1   = (const float*)d_in[10];
    const float* ob1   = (const float*)d_in[11];
    const float* oW2   = (const float*)d_in[12];
    const float* ob2   = (const float*)d_in[13];
    float* out = (float*)d_out;

    const int SMEMB = SQ_TOTF * 4;
    cudaFuncSetAttribute(attn_prep, cudaFuncAttributeMaxDynamicSharedMemorySize, SMEMB);

    // 1) layer-0 h + si0/sj0 (+ hlast/bcomb blk24, Wcomb blks 25-26)
    gemm2<0><<<dim3(27, 1), 128>>>(embed, encW, FF, nullptr, eas, ead, -1, 0,
                                   dW, das, dad, pW, pb);
    // 2) compaction + gather
    compact_gather_kernel<<<16, 512>>>(data);
    // 3) L1 attention prep (buckets over g_hc)
    attn_prep<<<16, 1024, SMEMB>>>(0);
    // 4) fused L1 combine + L1 linear -> g_xc + sic/sjc
    combine_gemm<<<dim3(24, 16), 128>>>(encW + FF * FF, eas + FF, ead + FF);
    // 5) L2 attention prep (buckets over g_xc)
    attn_prep<<<16, 1024, SMEMB>>>(1);
    // 6) L2 combine -> g_mean (x2)
    attn_combine<<<dim3(192, 16), 256>>>(1, 3);
    // 7) param head (z=0 mean-KLD, z=1 sigma-KLD) + decoder linear (z=2 via Wcomb) -> g_hc + sic/sjc
    gemm2<2><<<dim3(24, 16, 3), 128>>>(nullptr, pW, 2 * FF, pb, das, dad, 3, 1,
                                       nullptr, nullptr, nullptr, nullptr, nullptr);
    // 8) decoder single-row attention
    dec_attn_kernel<<<16, 128>>>();
    // 9) output MLP + KLD
    final_kernel<<<1, 256>>>(oW1, ob1, oW2, ob2, out);
}

// round 10
// speedup vs baseline: 3.4209x; 1.0843x over previous
#include <cuda_runtime.h>
#include <math.h>

#define BB 16
#define NN 1536
#define FF 128
#define NB 128
#define NCHK 48

// ---------------- scratch (device globals; no allocation) ----------------
__device__ __align__(16) float g_h0[NN * FF];
__device__ float g_si0[NN];
__device__ float g_sj0[NN];
__device__ int   g_idx[BB][NN];
__device__ int   g_n[BB];
__device__ __align__(16) float g_hc[(size_t)BB * NN * FF];   // layer-0 h compacted; later dec h
__device__ __align__(16) float g_xc[(size_t)BB * NN * FF];   // layer-1 h
__device__ __align__(16) float g_mean[(size_t)BB * NN * FF]; // combine outputs (x1, then x2)
__device__ float g_sic[BB * NN];
__device__ float g_sjc[BB * NN];
__device__ float g_kldrow1[BB * NN];
__device__ float g_kldrow2[BB * NN];
__device__ __align__(16) float g_hlast[FF];
__device__ float g_sL[2];
__device__ float g_feat[BB * FF];
__device__ __align__(16) float g_Wcomb[FF * FF];
__device__ __align__(16) float g_bcomb[FF];

// bucket-factorized attention scratch
__device__ int   g_ord[BB][NN];
__device__ float g_sjo[BB][NN];
__device__ float g_vso[BB][NN];
__device__ float g_bso[BB][NN];
__device__ int   g_bstart[BB][NB + 4];
__device__ __align__(16) float g_Cv[BB][(NB + 1) * FF];
__device__ __align__(16) float g_Cb[BB][(NB + 1) * FF];
__device__ float g_CvS[BB][NB + 1];
__device__ float g_CbS[BB][NB + 1];
__device__ float g_bmax[BB];
__device__ float g_bscale[BB];

__device__ __forceinline__ float* scratchBuf(int id) {
    switch (id) {
        case 0: return g_h0;
        case 1: return g_hc;
        case 2: return g_xc;
        default: return g_mean;
    }
}

// ============ GEMM: 64x128 tile, 128 threads, 8x8/thread ============
// MODE 0: launch 1. blocks 0-23: embed@encW0 -> g_h0 + si0/sj0; blk 24: hlast+bcomb;
//         blks 25,26: Wcomb = pW_mean @ dec_W; blks 27-42: per-sample compaction.
// MODE 1: batched x@W -> scratch cId + sic/sjc
// MODE 2: z=0 mean-KLD, z=1 sigma-KLD, z=2 dec linear via Wcomb -> g_hc + sic/sjc
template <int MODE>
__global__ void gemm2(const float* __restrict__ Aext,
                      const float* __restrict__ W, int ldW,
                      const float* __restrict__ bias,
                      const float* __restrict__ asrc, const float* __restrict__ adst,
                      int aId, int cId,
                      const float* __restrict__ hW, const float* __restrict__ hs2,
                      const float* __restrict__ hd2,
                      const float* __restrict__ pWm, const float* __restrict__ pbm,
                      const int* __restrict__ dataPtr)
{
    int t = threadIdx.x;  // 128
    if (MODE == 0 && blockIdx.x >= 27) {
        // per-sample compaction (one block per sample, first warp)
        int b = blockIdx.x - 27;
        if (t < 32) {
            const int* d = dataPtr + b * NN;
            int cnt = 0;
            for (int base = 0; base < NN; base += 32) {
                int v = d[base + t];
                unsigned m = __ballot_sync(0xffffffffu, v != 0);
                if (v != 0) g_idx[b][cnt + __popc(m & ((1u << t) - 1u))] = base + t;
                cnt += __popc(m);
            }
            if (t == 0) g_n[b] = cnt;
        }
        return;
    }
    if (MODE == 0 && blockIdx.x == 24) {
        // hlast = embed[-1] @ dec_W (+ scores), bcomb = pb_mean @ dec_W
        __shared__ float sh[128];
        const float* e = Aext + (size_t)NN * FF;
        float acc = 0.f;
        #pragma unroll 8
        for (int k = 0; k < FF; k++) acc += e[k] * hW[k * FF + t];
        g_hlast[t] = acc;
        sh[t] = acc * hs2[t];
        __syncthreads();
        for (int s = 64; s > 0; s >>= 1) { if (t < s) sh[t] += sh[t + s]; __syncthreads(); }
        if (t == 0) g_sL[0] = sh[0];
        __syncthreads();
        sh[t] = acc * hd2[t];
        __syncthreads();
        for (int s = 64; s > 0; s >>= 1) { if (t < s) sh[t] += sh[t + s]; __syncthreads(); }
        if (t == 0) g_sL[1] = sh[0];
        float bc = 0.f;
        #pragma unroll 8
        for (int m = 0; m < FF; m++) bc += pbm[m] * hW[m * FF + t];
        g_bcomb[t] = bc;
        return;
    }

    bool wcomb = (MODE == 0 && blockIdx.x >= 25);
    int b = (MODE == 0) ? 0 : blockIdx.y;
    int n = wcomb ? FF : ((MODE == 0) ? NN : g_n[b]);
    int i0 = wcomb ? (blockIdx.x - 25) * 64 : blockIdx.x * 64;
    if (i0 >= n) return;

    const float* A; int lda;
    if (wcomb)          { A = pWm; lda = 2 * FF; }
    else if (MODE == 0) { A = Aext; lda = FF; }
    else                { A = scratchBuf(aId) + (size_t)b * NN * FF; lda = FF; }

    const float* Wp; const float* bp = nullptr; int ldw;
    if (wcomb) { Wp = hW; ldw = FF; }
    else if (MODE == 2) {
        int z = blockIdx.z;
        if (z == 0)      { Wp = W;       bp = bias;      ldw = ldW; }
        else if (z == 1) { Wp = W + FF;  bp = bias + FF; ldw = ldW; }
        else             { Wp = g_Wcomb; bp = g_bcomb;   ldw = FF; }
    } else { Wp = W; ldw = ldW; }

    float* C;
    if (wcomb) C = g_Wcomb;
    else if (MODE == 2 && blockIdx.z == 2) C = g_hc + (size_t)b * NN * FF;
    else C = scratchBuf(cId) + ((MODE == 0) ? 0 : (size_t)b * NN * FF);

    __shared__ float shA[16][68];
    __shared__ __align__(16) float shW[16][128];

    int ty = t >> 4, tx = t & 15;
    float acc[8][8] = {};

    for (int k0 = 0; k0 < FF; k0 += 16) {
        __syncthreads();
        #pragma unroll
        for (int u = t; u < 256; u += 128) {
            int row = u >> 2, c4 = u & 3;
            float4 v = make_float4(0.f, 0.f, 0.f, 0.f);
            if (i0 + row < n) v = *(const float4*)&A[(size_t)(i0 + row) * lda + k0 + c4 * 4];
            shA[c4 * 4 + 0][row] = v.x;
            shA[c4 * 4 + 1][row] = v.y;
            shA[c4 * 4 + 2][row] = v.z;
            shA[c4 * 4 + 3][row] = v.w;
        }
        #pragma unroll
        for (int u = t; u < 512; u += 128) {
            int r = u >> 5, c4 = u & 31;
            *(float4*)&shW[r][c4 * 4] = *(const float4*)&Wp[(size_t)(k0 + r) * ldw + c4 * 4];
        }
        __syncthreads();
        #pragma unroll
        for (int k = 0; k < 16; k++) {
            float av[8], bv[8];
            *(float4*)&av[0] = *(float4*)&shA[k][ty * 8];
            *(float4*)&av[4] = *(float4*)&shA[k][ty * 8 + 4];
            *(float4*)&bv[0] = *(float4*)&shW[k][tx * 8];
            *(float4*)&bv[4] = *(float4*)&shW[k][tx * 8 + 4];
            #pragma unroll
            for (int r = 0; r < 8; r++)
                #pragma unroll
                for (int c = 0; c < 8; c++)
                    acc[r][c] = fmaf(av[r], bv[c], acc[r][c]);
        }
    }

    if (wcomb) {
        #pragma unroll
        for (int r = 0; r < 8; r++) {
            int i = i0 + ty * 8 + r;
            *(float4*)&C[(size_t)i * FF + tx * 8]     = make_float4(acc[r][0], acc[r][1], acc[r][2], acc[r][3]);
            *(float4*)&C[(size_t)i * FF + tx * 8 + 4] = make_float4(acc[r][4], acc[r][5], acc[r][6], acc[r][7]);
        }
        return;
    }

    if (MODE == 2 && blockIdx.z <= 1) {
        int z = blockIdx.z;
        float bv8[8];
        #pragma unroll
        for (int c = 0; c < 8; c++) bv8[c] = bp[tx * 8 + c];
        #pragma unroll
        for (int r = 0; r < 8; r++) {
            int i = i0 + ty * 8 + r;
            float kp = 0.f;
            #pragma unroll
            for (int c = 0; c < 8; c++) {
                float v = acc[r][c] + bv8[c];
                kp += (z == 0) ? v * v : (expm1f(v) - v);
            }
            #pragma unroll
            for (int o = 8; o > 0; o >>= 1) kp += __shfl_xor_sync(0xffffffffu, kp, o);
            if (tx == 0 && i < n) {
                if (z == 0) g_kldrow1[b * NN + i] = kp;
                else        g_kldrow2[b * NN + i] = kp;
            }
        }
        return;
    }

    // store + si/sj epilogue (MODE 0 main, MODE 1, MODE 2 z==2)
    float as8[8], ad8[8], bb8[8];
    #pragma unroll
    for (int c = 0; c < 8; c++) {
        as8[c] = asrc[tx * 8 + c];
        ad8[c] = adst[tx * 8 + c];
        bb8[c] = bp ? bp[tx * 8 + c] : 0.f;
    }
    float ss[8], sd[8];
    #pragma unroll
    for (int r = 0; r < 8; r++) {
        int i = i0 + ty * 8 + r;
        float s1 = 0.f, s2 = 0.f;
        float vv[8];
        #pragma unroll
        for (int c = 0; c < 8; c++) {
            float v = acc[r][c] + bb8[c];
            vv[c] = v;
            s1 += v * as8[c]; s2 += v * ad8[c];
        }
        ss[r] = s1; sd[r] = s2;
        if (i < n) {
            *(float4*)&C[(size_t)i * FF + tx * 8]     = make_float4(vv[0], vv[1], vv[2], vv[3]);
            *(float4*)&C[(size_t)i * FF + tx * 8 + 4] = make_float4(vv[4], vv[5], vv[6], vv[7]);
        }
    }
    #pragma unroll
    for (int r = 0; r < 8; r++) {
        #pragma unroll
        for (int o = 8; o > 0; o >>= 1) {
            ss[r] += __shfl_xor_sync(0xffffffffu, ss[r], o);
            sd[r] += __shfl_xor_sync(0xffffffffu, sd[r], o);
        }
    }
    if (tx == 0) {
        #pragma unroll
        for (int r = 0; r < 8; r++) {
            int i = i0 + ty * 8 + r;
            if (i < n) {
                if (MODE == 0) { g_si0[i] = ss[r]; g_sj0[i] = sd[r]; }
                else           { g_sic[b * NN + i] = ss[r]; g_sjc[b * NN + i] = sd[r]; }
            }
        }
    }
}

// ============ attention prep: (optional gather) + bucket structure + prefix sums ============
// smem layout (floats)
#define SQ_SJV  0
#define SQ_QV   (SQ_SJV + 1536)
#define SQ_RNK  (SQ_QV + 1536)
#define SQ_ORD  (SQ_RNK + 1536)
#define SQ_CNT  (SQ_ORD + 1536)                 // NCHK*NB ints = 6144
#define SQ_TOT  (SQ_CNT + NCHK * NB)            // 128
#define SQ_BST  (SQ_TOT + 128)                  // 132
#define SQ_SJO  (SQ_BST + 132)
#define SQ_VSO  (SQ_SJO + 1536)
#define SQ_BSO  (SQ_VSO + 1536)
#define SQ_SV   (SQ_BSO + 1536)                 // NB*128
#define SQ_SB   (SQ_SV + NB * 128)
#define SQ_SVS  (SQ_SB + NB * 128)              // 132
#define SQ_SBS  (SQ_SVS + 132)
#define SQ_RED  (SQ_SBS + 132)                  // 80
#define SQ_TOTF (SQ_RED + 80)

__global__ void attn_prep(int hId)
{
    extern __shared__ float sm[];
    float* sjv = sm + SQ_SJV;
    int*   qv  = (int*)(sm + SQ_QV);
    int*   rnk = (int*)(sm + SQ_RNK);
    int*   ord = (int*)(sm + SQ_ORD);
    int*   cnt = (int*)(sm + SQ_CNT);
    int*   tot = (int*)(sm + SQ_TOT);
    int*   bst = (int*)(sm + SQ_BST);
    float* sjo = sm + SQ_SJO;
    float* vso = sm + SQ_VSO;
    float* bso = sm + SQ_BSO;
    float* Sv  = sm + SQ_SV;
    float* Sb  = sm + SQ_SB;
    float* SvS = sm + SQ_SVS;
    float* SbS = sm + SQ_SBS;
    float* red = sm + SQ_RED;

    int b = blockIdx.x;
    int n = g_n[b];
    int t = threadIdx.x;  // 1024
    int lane = t & 31, warp = t >> 5;
    const float* H = (hId ? g_xc : g_hc) + (size_t)b * NN * FF;

    // gather phase (layer 1 only): compacted h + scores from shared layer-0 arrays
    if (hId == 0) {
        for (int u = t; u < n * 32; u += 1024)
            ((float4*)g_hc)[(size_t)b * NN * 32 + u] =
                ((const float4*)g_h0)[(size_t)g_idx[b][u >> 5] * 32 + (u & 31)];
        for (int jj = t; jj < n; jj += 1024) {
            int src = g_idx[b][jj];
            float sv = g_si0[src], dv = g_sj0[src];
            g_sic[b * NN + jj] = sv;
            g_sjc[b * NN + jj] = dv;
            sjv[jj] = dv;
        }
    } else {
        for (int u = t; u < n; u += 1024) sjv[u] = g_sjc[b * NN + u];
    }
    for (int u = t; u < NCHK * NB; u += 1024) cnt[u] = 0;
    __syncthreads();

    // min/max of sj
    float mn = 1e30f, mx = -1e30f;
    for (int u = t; u < n; u += 1024) {
        float s = sjv[u];
        mn = fminf(mn, s); mx = fmaxf(mx, s);
    }
    #pragma unroll
    for (int o = 16; o > 0; o >>= 1) {
        mn = fminf(mn, __shfl_xor_sync(0xffffffffu, mn, o));
        mx = fmaxf(mx, __shfl_xor_sync(0xffffffffu, mx, o));
    }
    if (lane == 0) { red[warp] = mn; red[32 + warp] = mx; }
    __syncthreads();
    if (t == 0) {
        float a = 1e30f, z = -1e30f;
        for (int w = 0; w < 32; w++) { a = fminf(a, red[w]); z = fmaxf(z, red[32 + w]); }
        float span = z - a;
        float sc = (span > 1e-20f) ? (float)NB / span : 0.f;
        red[64] = z; red[65] = sc;
        g_bmax[b] = z; g_bscale[b] = sc;
    }
    __syncthreads();
    float bmax = red[64], bscale = red[65];

    // bucket + stable rank via match_any (chunk = 32 consecutive indices per warp)
    int nchk = (n + 31) >> 5;
    for (int ch = warp; ch < nchk; ch += 32) {
        int j = ch * 32 + lane;
        int q = -1;
        if (j < n) {
            q = (int)((bmax - sjv[j]) * bscale);
            q = max(0, min(NB - 1, q));
        }
        unsigned mask = __match_any_sync(0xffffffffu, q);
        int rank = __popc(mask & ((1u << lane) - 1u));
        if (j < n) {
            qv[j] = q; rnk[j] = rank;
            if (rank == 0) cnt[ch * NB + q] = __popc(mask);
        }
    }
    __syncthreads();

    // per-bucket exclusive prefix over chunks + totals
    if (t < NB) {
        int run = 0;
        for (int ch = 0; ch < nchk; ch++) {
            int c = cnt[ch * NB + t];
            cnt[ch * NB + t] = run;
            run += c;
        }
        tot[t] = run;
    }
    __syncthreads();
    // exclusive scan of tot -> bst (warp 0, 4 buckets per lane)
    if (t < 32) {
        int base = t * 4;
        int h0 = tot[base], h1 = tot[base + 1], h2 = tot[base + 2], h3 = tot[base + 3];
        int s = h0 + h1 + h2 + h3, inc = s;
        #pragma unroll
        for (int o = 1; o < 32; o <<= 1) {
            int v = __shfl_up_sync(0xffffffffu, inc, o);
            if (lane >= o) inc += v;
        }
        int ex = inc - s;
        bst[base] = ex; bst[base + 1] = ex + h0;
        bst[base + 2] = ex + h0 + h1; bst[base + 3] = ex + h0 + h1 + h2;
        if (t == 31) bst[NB] = inc;
    }
    __syncthreads();
    if (t <= NB) g_bstart[b][t] = bst[t];

    // scatter to bucket order
    for (int j = t; j < n; j += 1024) {
        int q = qv[j];
        int pos = bst[q] + cnt[(j >> 5) * NB + q] + rnk[j];
        ord[pos] = j;
    }
    __syncthreads();

    // per-position arrays (bucket order)
    for (int pos = t; pos < n; pos += 1024) {
        int j = ord[pos];
        float s = sjv[j];
        float v = __expf(s), w = __expf(0.2f * s);
        sjo[pos] = s; vso[pos] = v; bso[pos] = w;
        g_ord[b][pos] = j; g_sjo[b][pos] = s; g_vso[b][pos] = v; g_bso[b][pos] = w;
    }
    __syncthreads();

    // per-bucket vector + scalar sums (8 groups of 128 channels)
    {
        int grp = t >> 7, c = t & 127;
        for (int q = grp; q < NB; q += 8) {
            int p0 = bst[q], p1 = bst[q + 1];
            float av = 0.f, ab = 0.f;
            for (int p = p0; p < p1; p++) {
                int jj = ord[p];
                float hv = H[(size_t)jj * FF + c];
                av = fmaf(vso[p], hv, av);
                ab = fmaf(bso[p], hv, ab);
            }
            Sv[q * 128 + c] = av;
            Sb[q * 128 + c] = ab;
            if (c == 0) { float s = 0.f; for (int p = p0; p < p1; p++) s += vso[p]; SvS[q] = s; }
            if (c == 1) { float s = 0.f; for (int p = p0; p < p1; p++) s += bso[p]; SbS[q] = s; }
        }
    }
    __syncthreads();

    // exclusive prefix over buckets -> global
    if (t < 128) {
        float run = 0.f;
        for (int q = 0; q < NB; q++) { g_Cv[b][q * 128 + t] = run; run += Sv[q * 128 + t]; }
        g_Cv[b][NB * 128 + t] = run;
    } else if (t < 256) {
        int c = t - 128;
        float run = 0.f;
        for (int q = 0; q < NB; q++) { g_Cb[b][q * 128 + c] = run; run += Sb[q * 128 + c]; }
        g_Cb[b][NB * 128 + c] = run;
    } else if (t == 256) {
        float run = 0.f;
        for (int q = 0; q < NB; q++) { g_CvS[b][q] = run; run += SvS[q]; }
        g_CvS[b][NB] = run;
    } else if (t == 257) {
        float run = 0.f;
        for (int q = 0; q < NB; q++) { g_CbS[b][q] = run; run += SbS[q]; }
        g_CbS[b][NB] = run;
    }
}

// ============ per-row combine ============
__device__ __forceinline__ float4 combine_row(int b, int i, int lane, const float* __restrict__ H)
{
    float si = g_sic[b * NN + i];
    float uu = __expf(si), aa = __expf(0.2f * si);
    float th = -si;
    int qt = (int)((g_bmax[b] - th) * g_bscale[b]);
    qt = max(0, min(NB - 1, qt));
    int p0 = g_bstart[b][qt], p1 = g_bstart[b][qt + 1];

    float4 pv = *(const float4*)&g_Cv[b][qt * 128 + lane * 4];
    float4 pb = *(const float4*)&g_Cb[b][qt * 128 + lane * 4];
    float pvs = g_CvS[b][qt], pbs = g_CbS[b][qt];

    for (int p = p0; p < p1; p++) {
        float s = g_sjo[b][p];
        if (s >= th) {
            int jj = g_ord[b][p];
            float w = g_vso[b][p], wb = g_bso[b][p];
            float4 hv = *(const float4*)&H[(size_t)jj * FF + lane * 4];
            pv.x = fmaf(w, hv.x, pv.x); pv.y = fmaf(w, hv.y, pv.y);
            pv.z = fmaf(w, hv.z, pv.z); pv.w = fmaf(w, hv.w, pv.w);
            pb.x = fmaf(wb, hv.x, pb.x); pb.y = fmaf(wb, hv.y, pb.y);
            pb.z = fmaf(wb, hv.z, pb.z); pb.w = fmaf(wb, hv.w, pb.w);
            pvs += w; pbs += wb;
        }
    }

    float totbs = g_CbS[b][NB];
    float4 tb = *(const float4*)&g_Cb[b][NB * 128 + lane * 4];
    float inv = 1.f / (uu * pvs + aa * (totbs - pbs));
    float4 o;
    o.x = (uu * pv.x + aa * (tb.x - pb.x)) * inv;
    o.y = (uu * pv.y + aa * (tb.y - pb.y)) * inv;
    o.z = (uu * pv.z + aa * (tb.z - pb.z)) * inv;
    o.w = (uu * pv.w + aa * (tb.w - pb.w)) * inv;
    o.x = (o.x > 0.f) ? o.x : expm1f(o.x);
    o.y = (o.y > 0.f) ? o.y : expm1f(o.y);
    o.z = (o.z > 0.f) ? o.z : expm1f(o.z);
    o.w = (o.w > 0.f) ? o.w : expm1f(o.w);
    return o;
}

// ============ standalone combine: H=hId buffer -> out oId buffer ============
__global__ void attn_combine(int hId, int oId)
{
    int b = blockIdx.y;
    int n = g_n[b];
    int warp = threadIdx.x >> 5, lane = threadIdx.x & 31;
    int i = blockIdx.x * 8 + warp;
    if (i >= n) return;
    const float* H = (hId ? g_xc : g_hc) + (size_t)b * NN * FF;
    float* O = scratchBuf(oId) + (size_t)b * NN * FF;
    float4 o = combine_row(b, i, lane, H);
    *(float4*)&O[(size_t)i * FF + lane * 4] = o;
}

// ============ decoder: single attention row (last node) per sample ============
__global__ void dec_attn_kernel()
{
    int b = blockIdx.x;
    int n = g_n[b];
    const float* H = g_hc + (size_t)b * NN * FF;   // dec h
    const float* sj = g_sjc + b * NN;
    float sLs = g_sL[0];
    int t = threadIdx.x; // 128
    __shared__ float shw[128];
    float acc0 = 0.f, acc1 = 0.f, acc2 = 0.f, acc3 = 0.f, dsum = 0.f;
    for (int j0 = 0; j0 < n; j0 += 128) {
        int j = j0 + t;
        float w = 0.f;
        if (j < n) { float e = sLs + sj[j]; e = (e >= 0.f) ? e : 0.2f * e; w = __expf(e); }
        __syncthreads();
        shw[t] = w; dsum += w;
        __syncthreads();
        int lim = (n - j0 < 128) ? (n - j0) : 128;
        int jj = 0;
        for (; jj + 4 <= lim; jj += 4) {
            acc0 += shw[jj + 0] * H[(size_t)(j0 + jj + 0) * FF + t];
            acc1 += shw[jj + 1] * H[(size_t)(j0 + jj + 1) * FF + t];
            acc2 += shw[jj + 2] * H[(size_t)(j0 + jj + 2) * FF + t];
            acc3 += shw[jj + 3] * H[(size_t)(j0 + jj + 3) * FF + t];
        }
        for (; jj < lim; jj++) acc0 += shw[jj] * H[(size_t)(j0 + jj) * FF + t];
    }
    float acc = acc0 + acc1 + acc2 + acc3;
    __shared__ float shr[128];
    __syncthreads();
    shr[t] = dsum;
    __syncthreads();
    for (int s = 64; s > 0; s >>= 1) { if (t < s) shr[t] += shr[t + s]; __syncthreads(); }
    float eL = sLs + g_sL[1]; eL = (eL >= 0.f) ? eL : 0.2f * eL;
    float wL = __expf(eL);
    float denom = shr[0] + wL;
    acc += wL * g_hlast[t];
    g_feat[b * FF + t] = fmaxf(acc / denom, 0.f);
}

// ============ output MLP + KLD total ============
__global__ void final_kernel(const float* __restrict__ W1, const float* __restrict__ b1,
                             const float* __restrict__ W2, const float* __restrict__ b2,
                             float* __restrict__ out)
{
    int t = threadIdx.x; // 256
    __shared__ float shh[16 * 128];
    for (int u = t; u < 16 * 128; u += 256) {
        int b = u >> 7, c = u & 127;
        const float* f = g_feat + b * FF;
        float acc = b1[c];
        for (int k = 0; k < FF; k++) acc += f[k] * W1[k * FF + c];
        shh[u] = fmaxf(acc, 0.f);
    }
    __shared__ float shr[256];
    float kld = 0.f;
    for (int b = 0; b < BB; b++) {
        int n = g_n[b];
        float p = 0.f;
        for (int r = t; r < n; r += 256) p += g_kldrow1[b * NN + r] + g_kldrow2[b * NN + r];
        shr[t] = p;
        __syncthreads();
        for (int s = 128; s > 0; s >>= 1) { if (t < s) shr[t] += shr[t + s]; __syncthreads(); }
        if (t == 0) kld += 0.5f * shr[0] / fmaxf((float)n, 1.f);
        __syncthreads();
    }
    __syncthreads();
    if (t < 16) {
        float acc = b2[0];
        for (int c = 0; c < FF; c++) acc += shh[t * FF + c] * W2[c];
        out[t] = acc;
    }
    if (t == 0) out[16] = kld;
}

// ============ launch ============
extern "C" void kernel_launch(void* const* d_in, const int* in_sizes, int n_in,
                              void* d_out, int out_size)
{
    (void)in_sizes; (void)n_in; (void)out_size;
    const int*   data  = (const int*)d_in[0];
    const float* embed = (const float*)d_in[1];
    const float* encW  = (const float*)d_in[2];
    const float* eas   = (const float*)d_in[3];
    const float* ead   = (const float*)d_in[4];
    const float* pW    = (const float*)d_in[5];
    const float* pb    = (const float*)d_in[6];
    const float* dW    = (const float*)d_in[7];
    const float* das   = (const float*)d_in[8];
    const float* dad   = (const float*)d_in[9];
    const float* oW1   = (const float*)d_in[10];
    const float* ob1   = (const float*)d_in[11];
    const float* oW2   = (const float*)d_in[12];
    const float* ob2   = (const float*)d_in[13];
    float* out = (float*)d_out;

    const int SMEMB = SQ_TOTF * 4;
    cudaFuncSetAttribute(attn_prep, cudaFuncAttributeMaxDynamicSharedMemorySize, SMEMB);

    // 1) layer-0 h + si0/sj0 (+ hlast/bcomb blk24, Wcomb blks 25-26, compaction blks 27-42)
    gemm2<0><<<dim3(43, 1), 128>>>(embed, encW, FF, nullptr, eas, ead, -1, 0,
                                   dW, das, dad, pW, pb, data);
    // 2) L1 attention prep (gathers compacted h + scores, then buckets over g_hc)
    attn_prep<<<16, 1024, SMEMB>>>(0);
    // 3) L1 combine -> g_mean (x1)
    attn_combine<<<dim3(192, 16), 256>>>(0, 3);
    // 4) L1 linear: x1 @ encW1 -> g_xc + sic/sjc
    gemm2<1><<<dim3(24, 16), 128>>>(nullptr, encW + FF * FF, FF, nullptr,
                                    eas + FF, ead + FF, 3, 2,
                                    nullptr, nullptr, nullptr, nullptr, nullptr, nullptr);
    // 5) L2 attention prep (buckets over g_xc)
    attn_prep<<<16, 1024, SMEMB>>>(1);
    // 6) L2 combine -> g_mean (x2)
    attn_combine<<<dim3(192, 16), 256>>>(1, 3);
    // 7) param head (z=0 mean-KLD, z=1 sigma-KLD) + decoder linear (z=2 via Wcomb) -> g_hc + sic/sjc
    gemm2<2><<<dim3(24, 16, 3), 128>>>(nullptr, pW, 2 * FF, pb, das, dad, 3, 1,
                                       nullptr, nullptr, nullptr, nullptr, nullptr, nullptr);
    // 8) decoder single-row attention
    dec_attn_kernel<<<16, 128>>>();
    // 9) output MLP + KLD
    final_kernel<<<1, 256>>>(oW1, ob1, oW2, ob2, out);
}

// round 11
// speedup vs baseline: 3.8373x; 1.1217x over previous
#include <cuda_runtime.h>
#include <math.h>

#define BB 16
#define NN 1536
#define FF 128
#define NB 128
#define NCHK 48
#define Bb 32   // GEMM row-tile

// ---------------- scratch (device globals; no allocation) ----------------
__device__ __align__(16) float g_h0[NN * FF];
__device__ float g_si0[NN];
__device__ float g_sj0[NN];
__device__ int   g_idx[BB][NN];
__device__ int   g_n[BB];
__device__ __align__(16) float g_hc[(size_t)BB * NN * FF];   // layer-0 h compacted; later dec h
__device__ __align__(16) float g_xc[(size_t)BB * NN * FF];   // layer-1 h
__device__ __align__(16) float g_mean[(size_t)BB * NN * FF]; // combine outputs (x1, then x2)
__device__ float g_sic[BB * NN];
__device__ float g_sjc[BB * NN];
__device__ float g_kldrow1[BB * NN];
__device__ float g_kldrow2[BB * NN];
__device__ __align__(16) float g_hlast[FF];
__device__ float g_sL[2];
__device__ float g_feat[BB * FF];
__device__ __align__(16) float g_Wcomb[FF * FF];
__device__ __align__(16) float g_bcomb[FF];

// bucket-factorized attention scratch
__device__ int   g_ord[BB][NN];
__device__ float g_sjo[BB][NN];
__device__ float g_vso[BB][NN];
__device__ float g_bso[BB][NN];
__device__ int   g_bstart[BB][NB + 4];
__device__ __align__(16) float g_Cv[BB][(NB + 1) * FF];
__device__ __align__(16) float g_Cb[BB][(NB + 1) * FF];
__device__ float g_CvS[BB][NB + 1];
__device__ float g_CbS[BB][NB + 1];
__device__ float g_bmax[BB];
__device__ float g_bscale[BB];

__device__ __forceinline__ float* scratchBuf(int id) {
    switch (id) {
        case 0: return g_h0;
        case 1: return g_hc;
        case 2: return g_xc;
        default: return g_mean;
    }
}

// ============ GEMM: 32x128 tile, 128 threads, 4x8/thread ============
// MODE 0: launch 1. blocks 0-47: embed@encW0 -> g_h0 + si0/sj0; blk 48: hlast+bcomb;
//         blks 49-52: Wcomb = pW_mean @ dec_W; blks 53-68: per-sample compaction.
// MODE 1: batched x@W -> scratch cId + sic/sjc
// MODE 2: z=0 mean-KLD, z=1 sigma-KLD, z=2 dec linear via Wcomb -> g_hc + sic/sjc
template <int MODE>
__global__ void gemm2(const float* __restrict__ Aext,
                      const float* __restrict__ W, int ldW,
                      const float* __restrict__ bias,
                      const float* __restrict__ asrc, const float* __restrict__ adst,
                      int aId, int cId,
                      const float* __restrict__ hW, const float* __restrict__ hs2,
                      const float* __restrict__ hd2,
                      const float* __restrict__ pWm, const float* __restrict__ pbm,
                      const int* __restrict__ dataPtr)
{
    int t = threadIdx.x;  // 128
    if (MODE == 0 && blockIdx.x >= 53) {
        // per-sample compaction
        int b = blockIdx.x - 53;
        if (t < 32) {
            const int* d = dataPtr + b * NN;
            int cnt = 0;
            for (int base = 0; base < NN; base += 32) {
                int v = d[base + t];
                unsigned m = __ballot_sync(0xffffffffu, v != 0);
                if (v != 0) g_idx[b][cnt + __popc(m & ((1u << t) - 1u))] = base + t;
                cnt += __popc(m);
            }
            if (t == 0) g_n[b] = cnt;
        }
        return;
    }
    if (MODE == 0 && blockIdx.x == 48) {
        // hlast = embed[-1] @ dec_W (+ scores), bcomb = pb_mean @ dec_W
        __shared__ float sh[128];
        const float* e = Aext + (size_t)NN * FF;
        float acc = 0.f;
        #pragma unroll 8
        for (int k = 0; k < FF; k++) acc += e[k] * hW[k * FF + t];
        g_hlast[t] = acc;
        sh[t] = acc * hs2[t];
        __syncthreads();
        for (int s = 64; s > 0; s >>= 1) { if (t < s) sh[t] += sh[t + s]; __syncthreads(); }
        if (t == 0) g_sL[0] = sh[0];
        __syncthreads();
        sh[t] = acc * hd2[t];
        __syncthreads();
        for (int s = 64; s > 0; s >>= 1) { if (t < s) sh[t] += sh[t + s]; __syncthreads(); }
        if (t == 0) g_sL[1] = sh[0];
        float bc = 0.f;
        #pragma unroll 8
        for (int m = 0; m < FF; m++) bc += pbm[m] * hW[m * FF + t];
        g_bcomb[t] = bc;
        return;
    }

    bool wcomb = (MODE == 0 && blockIdx.x >= 49);
    int b = (MODE == 0) ? 0 : blockIdx.y;
    int n = wcomb ? FF : ((MODE == 0) ? NN : g_n[b]);
    int i0 = wcomb ? (blockIdx.x - 49) * Bb : blockIdx.x * Bb;
    if (i0 >= n) return;

    const float* A; int lda;
    if (wcomb)          { A = pWm; lda = 2 * FF; }
    else if (MODE == 0) { A = Aext; lda = FF; }
    else                { A = scratchBuf(aId) + (size_t)b * NN * FF; lda = FF; }

    const float* Wp; const float* bp = nullptr; int ldw;
    if (wcomb) { Wp = hW; ldw = FF; }
    else if (MODE == 2) {
        int z = blockIdx.z;
        if (z == 0)      { Wp = W;       bp = bias;      ldw = ldW; }
        else if (z == 1) { Wp = W + FF;  bp = bias + FF; ldw = ldW; }
        else             { Wp = g_Wcomb; bp = g_bcomb;   ldw = FF; }
    } else { Wp = W; ldw = ldW; }

    float* C;
    if (wcomb) C = g_Wcomb;
    else if (MODE == 2 && blockIdx.z == 2) C = g_hc + (size_t)b * NN * FF;
    else C = scratchBuf(cId) + ((MODE == 0) ? 0 : (size_t)b * NN * FF);

    __shared__ float shA[16][36];                 // transposed A tile [k][row]
    __shared__ __align__(16) float shW[16][128];  // W tile [k][col]

    int ty = t >> 4, tx = t & 15;   // ty: 8 row-groups of 4, tx: 16 col-groups of 8
    float acc[4][8] = {};

    for (int k0 = 0; k0 < FF; k0 += 16) {
        __syncthreads();
        {
            int row = t >> 2, c4 = t & 3;   // 32 rows x 4 float4 = 128 threads
            float4 v = make_float4(0.f, 0.f, 0.f, 0.f);
            if (i0 + row < n) v = *(const float4*)&A[(size_t)(i0 + row) * lda + k0 + c4 * 4];
            shA[c4 * 4 + 0][row] = v.x;
            shA[c4 * 4 + 1][row] = v.y;
            shA[c4 * 4 + 2][row] = v.z;
            shA[c4 * 4 + 3][row] = v.w;
        }
        #pragma unroll
        for (int u = t; u < 512; u += 128) {
            int r = u >> 5, c4 = u & 31;
            *(float4*)&shW[r][c4 * 4] = *(const float4*)&Wp[(size_t)(k0 + r) * ldw + c4 * 4];
        }
        __syncthreads();
        #pragma unroll
        for (int k = 0; k < 16; k++) {
            float av[4], bv[8];
            *(float4*)&av[0] = *(float4*)&shA[k][ty * 4];
            *(float4*)&bv[0] = *(float4*)&shW[k][tx * 8];
            *(float4*)&bv[4] = *(float4*)&shW[k][tx * 8 + 4];
            #pragma unroll
            for (int r = 0; r < 4; r++)
                #pragma unroll
                for (int c = 0; c < 8; c++)
                    acc[r][c] = fmaf(av[r], bv[c], acc[r][c]);
        }
    }

    if (wcomb) {
        #pragma unroll
        for (int r = 0; r < 4; r++) {
            int i = i0 + ty * 4 + r;
            *(float4*)&C[(size_t)i * FF + tx * 8]     = make_float4(acc[r][0], acc[r][1], acc[r][2], acc[r][3]);
            *(float4*)&C[(size_t)i * FF + tx * 8 + 4] = make_float4(acc[r][4], acc[r][5], acc[r][6], acc[r][7]);
        }
        return;
    }

    if (MODE == 2 && blockIdx.z <= 1) {
        int z = blockIdx.z;
        float bv8[8];
        #pragma unroll
        for (int c = 0; c < 8; c++) bv8[c] = bp[tx * 8 + c];
        #pragma unroll
        for (int r = 0; r < 4; r++) {
            int i = i0 + ty * 4 + r;
            float kp = 0.f;
            #pragma unroll
            for (int c = 0; c < 8; c++) {
                float v = acc[r][c] + bv8[c];
                kp += (z == 0) ? v * v : (expm1f(v) - v);
            }
            #pragma unroll
            for (int o = 8; o > 0; o >>= 1) kp += __shfl_xor_sync(0xffffffffu, kp, o);
            if (tx == 0 && i < n) {
                if (z == 0) g_kldrow1[b * NN + i] = kp;
                else        g_kldrow2[b * NN + i] = kp;
            }
        }
        return;
    }

    // store + si/sj epilogue (MODE 0 main, MODE 1, MODE 2 z==2)
    float as8[8], ad8[8], bb8[8];
    #pragma unroll
    for (int c = 0; c < 8; c++) {
        as8[c] = asrc[tx * 8 + c];
        ad8[c] = adst[tx * 8 + c];
        bb8[c] = bp ? bp[tx * 8 + c] : 0.f;
    }
    float ss[4], sd[4];
    #pragma unroll
    for (int r = 0; r < 4; r++) {
        int i = i0 + ty * 4 + r;
        float s1 = 0.f, s2 = 0.f;
        float vv[8];
        #pragma unroll
        for (int c = 0; c < 8; c++) {
            float v = acc[r][c] + bb8[c];
            vv[c] = v;
            s1 += v * as8[c]; s2 += v * ad8[c];
        }
        ss[r] = s1; sd[r] = s2;
        if (i < n) {
            *(float4*)&C[(size_t)i * FF + tx * 8]     = make_float4(vv[0], vv[1], vv[2], vv[3]);
            *(float4*)&C[(size_t)i * FF + tx * 8 + 4] = make_float4(vv[4], vv[5], vv[6], vv[7]);
        }
    }
    #pragma unroll
    for (int r = 0; r < 4; r++) {
        #pragma unroll
        for (int o = 8; o > 0; o >>= 1) {
            ss[r] += __shfl_xor_sync(0xffffffffu, ss[r], o);
            sd[r] += __shfl_xor_sync(0xffffffffu, sd[r], o);
        }
    }
    if (tx == 0) {
        #pragma unroll
        for (int r = 0; r < 4; r++) {
            int i = i0 + ty * 4 + r;
            if (i < n) {
                if (MODE == 0) { g_si0[i] = ss[r]; g_sj0[i] = sd[r]; }
                else           { g_sic[b * NN + i] = ss[r]; g_sjc[b * NN + i] = sd[r]; }
            }
        }
    }
}

// ============ attention prep: (optional gather) + bucket structure + prefix sums ============
#define SQ_SJV  0
#define SQ_QV   (SQ_SJV + 1536)
#define SQ_RNK  (SQ_QV + 1536)
#define SQ_ORD  (SQ_RNK + 1536)
#define SQ_CNT  (SQ_ORD + 1536)
#define SQ_TOT  (SQ_CNT + NCHK * NB)
#define SQ_BST  (SQ_TOT + 128)
#define SQ_SJO  (SQ_BST + 132)
#define SQ_VSO  (SQ_SJO + 1536)
#define SQ_BSO  (SQ_VSO + 1536)
#define SQ_SV   (SQ_BSO + 1536)
#define SQ_SB   (SQ_SV + NB * 128)
#define SQ_SVS  (SQ_SB + NB * 128)
#define SQ_SBS  (SQ_SVS + 132)
#define SQ_RED  (SQ_SBS + 132)
#define SQ_TOTF (SQ_RED + 80)

__global__ void attn_prep(int hId)
{
    extern __shared__ float sm[];
    float* sjv = sm + SQ_SJV;
    int*   qv  = (int*)(sm + SQ_QV);
    int*   rnk = (int*)(sm + SQ_RNK);
    int*   ord = (int*)(sm + SQ_ORD);
    int*   cnt = (int*)(sm + SQ_CNT);
    int*   tot = (int*)(sm + SQ_TOT);
    int*   bst = (int*)(sm + SQ_BST);
    float* sjo = sm + SQ_SJO;
    float* vso = sm + SQ_VSO;
    float* bso = sm + SQ_BSO;
    float* Sv  = sm + SQ_SV;
    float* Sb  = sm + SQ_SB;
    float* SvS = sm + SQ_SVS;
    float* SbS = sm + SQ_SBS;
    float* red = sm + SQ_RED;

    int b = blockIdx.x;
    int n = g_n[b];
    int t = threadIdx.x;  // 1024
    int lane = t & 31, warp = t >> 5;
    const float* H = (hId ? g_xc : g_hc) + (size_t)b * NN * FF;

    if (hId == 0) {
        for (int u = t; u < n * 32; u += 1024)
            ((float4*)g_hc)[(size_t)b * NN * 32 + u] =
                ((const float4*)g_h0)[(size_t)g_idx[b][u >> 5] * 32 + (u & 31)];
        for (int jj = t; jj < n; jj += 1024) {
            int src = g_idx[b][jj];
            float sv = g_si0[src], dv = g_sj0[src];
            g_sic[b * NN + jj] = sv;
            g_sjc[b * NN + jj] = dv;
            sjv[jj] = dv;
        }
    } else {
        for (int u = t; u < n; u += 1024) sjv[u] = g_sjc[b * NN + u];
    }
    for (int u = t; u < NCHK * NB; u += 1024) cnt[u] = 0;
    __syncthreads();

    float mn = 1e30f, mx = -1e30f;
    for (int u = t; u < n; u += 1024) {
        float s = sjv[u];
        mn = fminf(mn, s); mx = fmaxf(mx, s);
    }
    #pragma unroll
    for (int o = 16; o > 0; o >>= 1) {
        mn = fminf(mn, __shfl_xor_sync(0xffffffffu, mn, o));
        mx = fmaxf(mx, __shfl_xor_sync(0xffffffffu, mx, o));
    }
    if (lane == 0) { red[warp] = mn; red[32 + warp] = mx; }
    __syncthreads();
    if (t == 0) {
        float a = 1e30f, z = -1e30f;
        for (int w = 0; w < 32; w++) { a = fminf(a, red[w]); z = fmaxf(z, red[32 + w]); }
        float span = z - a;
        float sc = (span > 1e-20f) ? (float)NB / span : 0.f;
        red[64] = z; red[65] = sc;
        g_bmax[b] = z; g_bscale[b] = sc;
    }
    __syncthreads();
    float bmax = red[64], bscale = red[65];

    int nchk = (n + 31) >> 5;
    for (int ch = warp; ch < nchk; ch += 32) {
        int j = ch * 32 + lane;
        int q = -1;
        if (j < n) {
            q = (int)((bmax - sjv[j]) * bscale);
            q = max(0, min(NB - 1, q));
        }
        unsigned mask = __match_any_sync(0xffffffffu, q);
        int rank = __popc(mask & ((1u << lane) - 1u));
        if (j < n) {
            qv[j] = q; rnk[j] = rank;
            if (rank == 0) cnt[ch * NB + q] = __popc(mask);
        }
    }
    __syncthreads();

    if (t < NB) {
        int run = 0;
        for (int ch = 0; ch < nchk; ch++) {
            int c = cnt[ch * NB + t];
            cnt[ch * NB + t] = run;
            run += c;
        }
        tot[t] = run;
    }
    __syncthreads();
    if (t < 32) {
        int base = t * 4;
        int h0 = tot[base], h1 = tot[base + 1], h2 = tot[base + 2], h3 = tot[base + 3];
        int s = h0 + h1 + h2 + h3, inc = s;
        #pragma unroll
        for (int o = 1; o < 32; o <<= 1) {
            int v = __shfl_up_sync(0xffffffffu, inc, o);
            if (lane >= o) inc += v;
        }
        int ex = inc - s;
        bst[base] = ex; bst[base + 1] = ex + h0;
        bst[base + 2] = ex + h0 + h1; bst[base + 3] = ex + h0 + h1 + h2;
        if (t == 31) bst[NB] = inc;
    }
    __syncthreads();
    if (t <= NB) g_bstart[b][t] = bst[t];

    for (int j = t; j < n; j += 1024) {
        int q = qv[j];
        int pos = bst[q] + cnt[(j >> 5) * NB + q] + rnk[j];
        ord[pos] = j;
    }
    __syncthreads();

    for (int pos = t; pos < n; pos += 1024) {
        int j = ord[pos];
        float s = sjv[j];
        float v = __expf(s), w = __expf(0.2f * s);
        sjo[pos] = s; vso[pos] = v; bso[pos] = w;
        g_ord[b][pos] = j; g_sjo[b][pos] = s; g_vso[b][pos] = v; g_bso[b][pos] = w;
    }
    __syncthreads();

    {
        int grp = t >> 7, c = t & 127;
        for (int q = grp; q < NB; q += 8) {
            int p0 = bst[q], p1 = bst[q + 1];
            float av = 0.f, ab = 0.f;
            for (int p = p0; p < p1; p++) {
                int jj = ord[p];
                float hv = H[(size_t)jj * FF + c];
                av = fmaf(vso[p], hv, av);
                ab = fmaf(bso[p], hv, ab);
            }
            Sv[q * 128 + c] = av;
            Sb[q * 128 + c] = ab;
            if (c == 0) { float s = 0.f; for (int p = p0; p < p1; p++) s += vso[p]; SvS[q] = s; }
            if (c == 1) { float s = 0.f; for (int p = p0; p < p1; p++) s += bso[p]; SbS[q] = s; }
        }
    }
    __syncthreads();

    if (t < 128) {
        float run = 0.f;
        for (int q = 0; q < NB; q++) { g_Cv[b][q * 128 + t] = run; run += Sv[q * 128 + t]; }
        g_Cv[b][NB * 128 + t] = run;
    } else if (t < 256) {
        int c = t - 128;
        float run = 0.f;
        for (int q = 0; q < NB; q++) { g_Cb[b][q * 128 + c] = run; run += Sb[q * 128 + c]; }
        g_Cb[b][NB * 128 + c] = run;
    } else if (t == 256) {
        float run = 0.f;
        for (int q = 0; q < NB; q++) { g_CvS[b][q] = run; run += SvS[q]; }
        g_CvS[b][NB] = run;
    } else if (t == 257) {
        float run = 0.f;
        for (int q = 0; q < NB; q++) { g_CbS[b][q] = run; run += SbS[q]; }
        g_CbS[b][NB] = run;
    }
}

// ============ per-row combine ============
__device__ __forceinline__ float4 combine_row(int b, int i, int lane, const float* __restrict__ H)
{
    float si = g_sic[b * NN + i];
    float uu = __expf(si), aa = __expf(0.2f * si);
    float th = -si;
    int qt = (int)((g_bmax[b] - th) * g_bscale[b]);
    qt = max(0, min(NB - 1, qt));
    int p0 = g_bstart[b][qt], p1 = g_bstart[b][qt + 1];

    float4 pv = *(const float4*)&g_Cv[b][qt * 128 + lane * 4];
    float4 pb = *(const float4*)&g_Cb[b][qt * 128 + lane * 4];
    float pvs = g_CvS[b][qt], pbs = g_CbS[b][qt];

    for (int p = p0; p < p1; p++) {
        float s = g_sjo[b][p];
        if (s >= th) {
            int jj = g_ord[b][p];
            float w = g_vso[b][p], wb = g_bso[b][p];
            float4 hv = *(const float4*)&H[(size_t)jj * FF + lane * 4];
            pv.x = fmaf(w, hv.x, pv.x); pv.y = fmaf(w, hv.y, pv.y);
            pv.z = fmaf(w, hv.z, pv.z); pv.w = fmaf(w, hv.w, pv.w);
            pb.x = fmaf(wb, hv.x, pb.x); pb.y = fmaf(wb, hv.y, pb.y);
            pb.z = fmaf(wb, hv.z, pb.z); pb.w = fmaf(wb, hv.w, pb.w);
            pvs += w; pbs += wb;
        }
    }

    float totbs = g_CbS[b][NB];
    float4 tb = *(const float4*)&g_Cb[b][NB * 128 + lane * 4];
    float inv = 1.f / (uu * pvs + aa * (totbs - pbs));
    float4 o;
    o.x = (uu * pv.x + aa * (tb.x - pb.x)) * inv;
    o.y = (uu * pv.y + aa * (tb.y - pb.y)) * inv;
    o.z = (uu * pv.z + aa * (tb.z - pb.z)) * inv;
    o.w = (uu * pv.w + aa * (tb.w - pb.w)) * inv;
    o.x = (o.x > 0.f) ? o.x : expm1f(o.x);
    o.y = (o.y > 0.f) ? o.y : expm1f(o.y);
    o.z = (o.z > 0.f) ? o.z : expm1f(o.z);
    o.w = (o.w > 0.f) ? o.w : expm1f(o.w);
    return o;
}

// ============ standalone combine: H=hId buffer -> out oId buffer ============
__global__ void attn_combine(int hId, int oId)
{
    int b = blockIdx.y;
    int n = g_n[b];
    int warp = threadIdx.x >> 5, lane = threadIdx.x & 31;
    int i = blockIdx.x * 8 + warp;
    if (i >= n) return;
    const float* H = (hId ? g_xc : g_hc) + (size_t)b * NN * FF;
    float* O = scratchBuf(oId) + (size_t)b * NN * FF;
    float4 o = combine_row(b, i, lane, H);
    *(float4*)&O[(size_t)i * FF + lane * 4] = o;
}

// ============ decoder: single attention row per sample (512 threads, 4 row-groups) ============
__global__ void dec_attn_kernel()
{
    int b = blockIdx.x;
    int n = g_n[b];
    const float* H = g_hc + (size_t)b * NN * FF;
    const float* sj = g_sjc + b * NN;
    float sLs = g_sL[0];
    int t = threadIdx.x;          // 512
    int g = t >> 7, c = t & 127;
    __shared__ float shw[512];
    __shared__ float sacc[4][128];
    __shared__ float shr[512];

    float acc = 0.f, dsum = 0.f;
    int T = (n + 127) >> 7;
    int TT = (T + 3) >> 2;
    for (int tt = 0; tt < TT; tt++) {
        int tile = tt * 4 + g;
        int j = tile * 128 + c;
        float w = 0.f;
        if (tile < T && j < n) {
            float e = sLs + sj[j]; e = (e >= 0.f) ? e : 0.2f * e; w = __expf(e);
        }
        __syncthreads();
        shw[t] = w; dsum += w;
        __syncthreads();
        if (tile < T) {
            int base = tile * 128;
            int lim = n - base; if (lim > 128) lim = 128;
            const float* wrow = &shw[g * 128];
            int jj = 0;
            for (; jj + 4 <= lim; jj += 4) {
                acc += wrow[jj + 0] * H[(size_t)(base + jj + 0) * FF + c];
                acc += wrow[jj + 1] * H[(size_t)(base + jj + 1) * FF + c];
                acc += wrow[jj + 2] * H[(size_t)(base + jj + 2) * FF + c];
                acc += wrow[jj + 3] * H[(size_t)(base + jj + 3) * FF + c];
            }
            for (; jj < lim; jj++) acc += wrow[jj] * H[(size_t)(base + jj) * FF + c];
        }
    }
    __syncthreads();
    sacc[g][c] = acc;
    shr[t] = dsum;
    __syncthreads();
    for (int s = 256; s > 0; s >>= 1) { if (t < s) shr[t] += shr[t + s]; __syncthreads(); }
    if (t < 128) {
        float a = sacc[0][t] + sacc[1][t] + sacc[2][t] + sacc[3][t];
        float eL = sLs + g_sL[1]; eL = (eL >= 0.f) ? eL : 0.2f * eL;
        float wL = __expf(eL);
        float denom = shr[0] + wL;
        a += wL * g_hlast[t];
        g_feat[b * FF + t] = fmaxf(a / denom, 0.f);
    }
}

// ============ output MLP + KLD total ============
__global__ void final_kernel(const float* __restrict__ W1, const float* __restrict__ b1,
                             const float* __restrict__ W2, const float* __restrict__ b2,
                             float* __restrict__ out)
{
    int t = threadIdx.x; // 256
    __shared__ float shh[16 * 128];
    for (int u = t; u < 16 * 128; u += 256) {
        int b = u >> 7, c = u & 127;
        const float* f = g_feat + b * FF;
        float acc = b1[c];
        for (int k = 0; k < FF; k++) acc += f[k] * W1[k * FF + c];
        shh[u] = fmaxf(acc, 0.f);
    }
    __shared__ float shr[256];
    float kld = 0.f;
    for (int b = 0; b < BB; b++) {
        int n = g_n[b];
        float p = 0.f;
        for (int r = t; r < n; r += 256) p += g_kldrow1[b * NN + r] + g_kldrow2[b * NN + r];
        shr[t] = p;
        __syncthreads();
        for (int s = 128; s > 0; s >>= 1) { if (t < s) shr[t] += shr[t + s]; __syncthreads(); }
        if (t == 0) kld += 0.5f * shr[0] / fmaxf((float)n, 1.f);
        __syncthreads();
    }
    __syncthreads();
    if (t < 16) {
        float acc = b2[0];
        for (int c = 0; c < FF; c++) acc += shh[t * FF + c] * W2[c];
        out[t] = acc;
    }
    if (t == 0) out[16] = kld;
}

// ============ launch ============
extern "C" void kernel_launch(void* const* d_in, const int* in_sizes, int n_in,
                              void* d_out, int out_size)
{
    (void)in_sizes; (void)n_in; (void)out_size;
    const int*   data  = (const int*)d_in[0];
    const float* embed = (const float*)d_in[1];
    const float* encW  = (const float*)d_in[2];
    const float* eas   = (const float*)d_in[3];
    const float* ead   = (const float*)d_in[4];
    const float* pW    = (const float*)d_in[5];
    const float* pb    = (const float*)d_in[6];
    const float* dW    = (const float*)d_in[7];
    const float* das   = (const float*)d_in[8];
    const float* dad   = (const float*)d_in[9];
    const float* oW1   = (const float*)d_in[10];
    const float* ob1   = (const float*)d_in[11];
    const float* oW2   = (const float*)d_in[12];
    const float* ob2   = (const float*)d_in[13];
    float* out = (float*)d_out;

    const int SMEMB = SQ_TOTF * 4;
    cudaFuncSetAttribute(attn_prep, cudaFuncAttributeMaxDynamicSharedMemorySize, SMEMB);

    // 1) layer-0 h + si0/sj0 (+ hlast/bcomb blk48, Wcomb 49-52, compaction 53-68)
    gemm2<0><<<dim3(69, 1), 128>>>(embed, encW, FF, nullptr, eas, ead, -1, 0,
                                   dW, das, dad, pW, pb, data);
    // 2) L1 attention prep (gathers compacted h + scores, then buckets over g_hc)
    attn_prep<<<16, 1024, SMEMB>>>(0);
    // 3) L1 combine -> g_mean (x1)
    attn_combine<<<dim3(192, 16), 256>>>(0, 3);
    // 4) L1 linear: x1 @ encW1 -> g_xc + sic/sjc
    gemm2<1><<<dim3(48, 16), 128>>>(nullptr, encW + FF * FF, FF, nullptr,
                                    eas + FF, ead + FF, 3, 2,
                                    nullptr, nullptr, nullptr, nullptr, nullptr, nullptr);
    // 5) L2 attention prep (buckets over g_xc)
    attn_prep<<<16, 1024, SMEMB>>>(1);
    // 6) L2 combine -> g_mean (x2)
    attn_combine<<<dim3(192, 16), 256>>>(1, 3);
    // 7) param head (z=0 mean-KLD, z=1 sigma-KLD) + decoder linear (z=2 via Wcomb) -> g_hc + sic/sjc
    gemm2<2><<<dim3(48, 16, 3), 128>>>(nullptr, pW, 2 * FF, pb, das, dad, 3, 1,
                                       nullptr, nullptr, nullptr, nullptr, nullptr, nullptr);
    // 8) decoder single-row attention
    dec_attn_kernel<<<16, 512>>>();
    // 9) output MLP + KLD
    final_kernel<<<1, 256>>>(oW1, ob1, oW2, ob2, out);
}

// round 12
// speedup vs baseline: 4.1385x; 1.0785x over previous
#include <cuda_runtime.h>
#include <math.h>

#define BB 16
#define NN 1536
#define FF 128
#define NB 128
#define NCHK 48
#define Bb 32   // GEMM row-tile

// ---------------- scratch (device globals; no allocation) ----------------
__device__ __align__(16) float g_h0[NN * FF];
__device__ float g_si0[NN];
__device__ float g_sj0[NN];
__device__ int   g_idx[BB][NN];
__device__ int   g_n[BB];
__device__ __align__(16) float g_hc[(size_t)BB * NN * FF];   // layer-0 h compacted; later dec h
__device__ __align__(16) float g_xc[(size_t)BB * NN * FF];   // layer-1 h
__device__ __align__(16) float g_mean[(size_t)BB * NN * FF]; // combine outputs (x1, then x2)
__device__ float g_sic[BB * NN];
__device__ float g_sjc[BB * NN];
__device__ float g_kldrow1[BB * NN];
__device__ float g_kldrow2[BB * NN];
__device__ __align__(16) float g_hlast[FF];
__device__ float g_sL[2];
__device__ float g_feat[BB * FF];
__device__ __align__(16) float g_Wcomb[FF * FF];
__device__ __align__(16) float g_bcomb[FF];

// bucket-factorized attention scratch
__device__ int   g_ord[BB][NN];
__device__ float g_sjo[BB][NN];
__device__ float g_vso[BB][NN];
__device__ float g_bso[BB][NN];
__device__ int   g_bstart[BB][NB + 4];
__device__ __align__(16) float g_Cv[BB][(NB + 1) * FF];
__device__ __align__(16) float g_Cb[BB][(NB + 1) * FF];
__device__ float g_CvS[BB][NB + 1];
__device__ float g_CbS[BB][NB + 1];
__device__ float g_bmax[BB];
__device__ float g_bscale[BB];

__device__ __forceinline__ float* scratchBuf(int id) {
    switch (id) {
        case 0: return g_h0;
        case 1: return g_hc;
        case 2: return g_xc;
        default: return g_mean;
    }
}

// ============ GEMM: 32x128 tile, 128 threads, 4x8/thread, SW-pipelined loads ============
// MODE 0: launch 1. blocks 0-47: embed@encW0 -> g_h0 + si0/sj0; blk 48: hlast+bcomb;
//         blks 49-52: Wcomb = pW_mean @ dec_W; blks 53-68: per-sample compaction.
// MODE 1: batched x@W -> scratch cId + sic/sjc
// MODE 2: z=0 mean-KLD, z=1 sigma-KLD, z=2 dec linear via Wcomb -> g_hc + sic/sjc
template <int MODE>
__global__ void gemm2(const float* __restrict__ Aext,
                      const float* __restrict__ W, int ldW,
                      const float* __restrict__ bias,
                      const float* __restrict__ asrc, const float* __restrict__ adst,
                      int aId, int cId,
                      const float* __restrict__ hW, const float* __restrict__ hs2,
                      const float* __restrict__ hd2,
                      const float* __restrict__ pWm, const float* __restrict__ pbm,
                      const int* __restrict__ dataPtr)
{
    int t = threadIdx.x;  // 128
    if (MODE == 0 && blockIdx.x >= 53) {
        // per-sample compaction
        int b = blockIdx.x - 53;
        if (t < 32) {
            const int* d = dataPtr + b * NN;
            int cnt = 0;
            for (int base = 0; base < NN; base += 32) {
                int v = d[base + t];
                unsigned m = __ballot_sync(0xffffffffu, v != 0);
                if (v != 0) g_idx[b][cnt + __popc(m & ((1u << t) - 1u))] = base + t;
                cnt += __popc(m);
            }
            if (t == 0) g_n[b] = cnt;
        }
        return;
    }
    if (MODE == 0 && blockIdx.x == 48) {
        // hlast = embed[-1] @ dec_W (+ scores), bcomb = pb_mean @ dec_W
        __shared__ float sh[128];
        const float* e = Aext + (size_t)NN * FF;
        float acc = 0.f;
        #pragma unroll 8
        for (int k = 0; k < FF; k++) acc += e[k] * hW[k * FF + t];
        g_hlast[t] = acc;
        sh[t] = acc * hs2[t];
        __syncthreads();
        for (int s = 64; s > 0; s >>= 1) { if (t < s) sh[t] += sh[t + s]; __syncthreads(); }
        if (t == 0) g_sL[0] = sh[0];
        __syncthreads();
        sh[t] = acc * hd2[t];
        __syncthreads();
        for (int s = 64; s > 0; s >>= 1) { if (t < s) sh[t] += sh[t + s]; __syncthreads(); }
        if (t == 0) g_sL[1] = sh[0];
        float bc = 0.f;
        #pragma unroll 8
        for (int m = 0; m < FF; m++) bc += pbm[m] * hW[m * FF + t];
        g_bcomb[t] = bc;
        return;
    }

    bool wcomb = (MODE == 0 && blockIdx.x >= 49);
    int b = (MODE == 0) ? 0 : blockIdx.y;
    int n = wcomb ? FF : ((MODE == 0) ? NN : g_n[b]);
    int i0 = wcomb ? (blockIdx.x - 49) * Bb : blockIdx.x * Bb;
    if (i0 >= n) return;

    const float* A; int lda;
    if (wcomb)          { A = pWm; lda = 2 * FF; }
    else if (MODE == 0) { A = Aext; lda = FF; }
    else                { A = scratchBuf(aId) + (size_t)b * NN * FF; lda = FF; }

    const float* Wp; const float* bp = nullptr; int ldw;
    if (wcomb) { Wp = hW; ldw = FF; }
    else if (MODE == 2) {
        int z = blockIdx.z;
        if (z == 0)      { Wp = W;       bp = bias;      ldw = ldW; }
        else if (z == 1) { Wp = W + FF;  bp = bias + FF; ldw = ldW; }
        else             { Wp = g_Wcomb; bp = g_bcomb;   ldw = FF; }
    } else { Wp = W; ldw = ldW; }

    float* C;
    if (wcomb) C = g_Wcomb;
    else if (MODE == 2 && blockIdx.z == 2) C = g_hc + (size_t)b * NN * FF;
    else C = scratchBuf(cId) + ((MODE == 0) ? 0 : (size_t)b * NN * FF);

    __shared__ float shA[16][36];                 // transposed A tile [k][row]
    __shared__ __align__(16) float shW[16][128];  // W tile [k][col]

    int ty = t >> 4, tx = t & 15;   // ty: 8 row-groups of 4, tx: 16 col-groups of 8
    int rowA = t >> 2, c4A = t & 3; // A staging: 32 rows x 4 float4
    bool rowAok = (i0 + rowA < n);
    const float* Arow = A + (size_t)(i0 + (rowAok ? rowA : 0)) * lda + c4A * 4;
    // W staging: 4 chunks, chunk p covers row (t+128p)>>5, col4 ((t+128p)&31)
    float acc[4][8] = {};
    float4 pA, pW4[4];

    // prefetch k0 = 0
    pA = rowAok ? *(const float4*)(Arow) : make_float4(0.f, 0.f, 0.f, 0.f);
    #pragma unroll
    for (int p = 0; p < 4; p++) {
        int u = t + 128 * p;
        pW4[p] = *(const float4*)&Wp[(size_t)(u >> 5) * ldw + (u & 31) * 4];
    }

    for (int k0 = 0; k0 < FF; k0 += 16) {
        __syncthreads();
        shA[c4A * 4 + 0][rowA] = pA.x;
        shA[c4A * 4 + 1][rowA] = pA.y;
        shA[c4A * 4 + 2][rowA] = pA.z;
        shA[c4A * 4 + 3][rowA] = pA.w;
        #pragma unroll
        for (int p = 0; p < 4; p++) {
            int u = t + 128 * p;
            *(float4*)&shW[u >> 5][(u & 31) * 4] = pW4[p];
        }
        __syncthreads();

        // prefetch next tile (overlaps with compute below)
        if (k0 + 16 < FF) {
            pA = rowAok ? *(const float4*)(Arow + k0 + 16) : make_float4(0.f, 0.f, 0.f, 0.f);
            #pragma unroll
            for (int p = 0; p < 4; p++) {
                int u = t + 128 * p;
                pW4[p] = *(const float4*)&Wp[(size_t)(k0 + 16 + (u >> 5)) * ldw + (u & 31) * 4];
            }
        }

        #pragma unroll
        for (int k = 0; k < 16; k++) {
            float av[4], bv[8];
            *(float4*)&av[0] = *(float4*)&shA[k][ty * 4];
            *(float4*)&bv[0] = *(float4*)&shW[k][tx * 8];
            *(float4*)&bv[4] = *(float4*)&shW[k][tx * 8 + 4];
            #pragma unroll
            for (int r = 0; r < 4; r++)
                #pragma unroll
                for (int c = 0; c < 8; c++)
                    acc[r][c] = fmaf(av[r], bv[c], acc[r][c]);
        }
    }

    if (wcomb) {
        #pragma unroll
        for (int r = 0; r < 4; r++) {
            int i = i0 + ty * 4 + r;
            *(float4*)&C[(size_t)i * FF + tx * 8]     = make_float4(acc[r][0], acc[r][1], acc[r][2], acc[r][3]);
            *(float4*)&C[(size_t)i * FF + tx * 8 + 4] = make_float4(acc[r][4], acc[r][5], acc[r][6], acc[r][7]);
        }
        return;
    }

    if (MODE == 2 && blockIdx.z <= 1) {
        int z = blockIdx.z;
        float bv8[8];
        #pragma unroll
        for (int c = 0; c < 8; c++) bv8[c] = bp[tx * 8 + c];
        #pragma unroll
        for (int r = 0; r < 4; r++) {
            int i = i0 + ty * 4 + r;
            float kp = 0.f;
            #pragma unroll
            for (int c = 0; c < 8; c++) {
                float v = acc[r][c] + bv8[c];
                kp += (z == 0) ? v * v : (expm1f(v) - v);
            }
            #pragma unroll
            for (int o = 8; o > 0; o >>= 1) kp += __shfl_xor_sync(0xffffffffu, kp, o);
            if (tx == 0 && i < n) {
                if (z == 0) g_kldrow1[b * NN + i] = kp;
                else        g_kldrow2[b * NN + i] = kp;
            }
        }
        return;
    }

    // store + si/sj epilogue (MODE 0 main, MODE 1, MODE 2 z==2)
    float as8[8], ad8[8], bb8[8];
    #pragma unroll
    for (int c = 0; c < 8; c++) {
        as8[c] = asrc[tx * 8 + c];
        ad8[c] = adst[tx * 8 + c];
        bb8[c] = bp ? bp[tx * 8 + c] : 0.f;
    }
    float ss[4], sd[4];
    #pragma unroll
    for (int r = 0; r < 4; r++) {
        int i = i0 + ty * 4 + r;
        float s1 = 0.f, s2 = 0.f;
        float vv[8];
        #pragma unroll
        for (int c = 0; c < 8; c++) {
            float v = acc[r][c] + bb8[c];
            vv[c] = v;
            s1 += v * as8[c]; s2 += v * ad8[c];
        }
        ss[r] = s1; sd[r] = s2;
        if (i < n) {
            *(float4*)&C[(size_t)i * FF + tx * 8]     = make_float4(vv[0], vv[1], vv[2], vv[3]);
            *(float4*)&C[(size_t)i * FF + tx * 8 + 4] = make_float4(vv[4], vv[5], vv[6], vv[7]);
        }
    }
    #pragma unroll
    for (int r = 0; r < 4; r++) {
        #pragma unroll
        for (int o = 8; o > 0; o >>= 1) {
            ss[r] += __shfl_xor_sync(0xffffffffu, ss[r], o);
            sd[r] += __shfl_xor_sync(0xffffffffu, sd[r], o);
        }
    }
    if (tx == 0) {
        #pragma unroll
        for (int r = 0; r < 4; r++) {
            int i = i0 + ty * 4 + r;
            if (i < n) {
                if (MODE == 0) { g_si0[i] = ss[r]; g_sj0[i] = sd[r]; }
                else           { g_sic[b * NN + i] = ss[r]; g_sjc[b * NN + i] = sd[r]; }
            }
        }
    }
}

// ============ attention prep: (optional gather) + bucket structure + prefix sums ============
#define SQ_SJV  0
#define SQ_QV   (SQ_SJV + 1536)
#define SQ_RNK  (SQ_QV + 1536)
#define SQ_ORD  (SQ_RNK + 1536)
#define SQ_CNT  (SQ_ORD + 1536)
#define SQ_TOT  (SQ_CNT + NCHK * NB)
#define SQ_BST  (SQ_TOT + 128)
#define SQ_SJO  (SQ_BST + 132)
#define SQ_VSO  (SQ_SJO + 1536)
#define SQ_BSO  (SQ_VSO + 1536)
#define SQ_SV   (SQ_BSO + 1536)
#define SQ_SB   (SQ_SV + NB * 128)
#define SQ_SVS  (SQ_SB + NB * 128)
#define SQ_SBS  (SQ_SVS + 132)
#define SQ_RED  (SQ_SBS + 132)
#define SQ_TOTF (SQ_RED + 80)

__global__ void attn_prep(int hId)
{
    extern __shared__ float sm[];
    float* sjv = sm + SQ_SJV;
    int*   qv  = (int*)(sm + SQ_QV);
    int*   rnk = (int*)(sm + SQ_RNK);
    int*   ord = (int*)(sm + SQ_ORD);
    int*   cnt = (int*)(sm + SQ_CNT);
    int*   tot = (int*)(sm + SQ_TOT);
    int*   bst = (int*)(sm + SQ_BST);
    float* sjo = sm + SQ_SJO;
    float* vso = sm + SQ_VSO;
    float* bso = sm + SQ_BSO;
    float* Sv  = sm + SQ_SV;
    float* Sb  = sm + SQ_SB;
    float* SvS = sm + SQ_SVS;
    float* SbS = sm + SQ_SBS;
    float* red = sm + SQ_RED;

    int b = blockIdx.x;
    int n = g_n[b];
    int t = threadIdx.x;  // 1024
    int lane = t & 31, warp = t >> 5;
    const float* H = (hId ? g_xc : g_hc) + (size_t)b * NN * FF;

    if (hId == 0) {
        for (int u = t; u < n * 32; u += 1024)
            ((float4*)g_hc)[(size_t)b * NN * 32 + u] =
                ((const float4*)g_h0)[(size_t)g_idx[b][u >> 5] * 32 + (u & 31)];
        for (int jj = t; jj < n; jj += 1024) {
            int src = g_idx[b][jj];
            float sv = g_si0[src], dv = g_sj0[src];
            g_sic[b * NN + jj] = sv;
            g_sjc[b * NN + jj] = dv;
            sjv[jj] = dv;
        }
    } else {
        for (int u = t; u < n; u += 1024) sjv[u] = g_sjc[b * NN + u];
    }
    for (int u = t; u < NCHK * NB; u += 1024) cnt[u] = 0;
    __syncthreads();

    float mn = 1e30f, mx = -1e30f;
    for (int u = t; u < n; u += 1024) {
        float s = sjv[u];
        mn = fminf(mn, s); mx = fmaxf(mx, s);
    }
    #pragma unroll
    for (int o = 16; o > 0; o >>= 1) {
        mn = fminf(mn, __shfl_xor_sync(0xffffffffu, mn, o));
        mx = fmaxf(mx, __shfl_xor_sync(0xffffffffu, mx, o));
    }
    if (lane == 0) { red[warp] = mn; red[32 + warp] = mx; }
    __syncthreads();
    if (t == 0) {
        float a = 1e30f, z = -1e30f;
        for (int w = 0; w < 32; w++) { a = fminf(a, red[w]); z = fmaxf(z, red[32 + w]); }
        float span = z - a;
        float sc = (span > 1e-20f) ? (float)NB / span : 0.f;
        red[64] = z; red[65] = sc;
        g_bmax[b] = z; g_bscale[b] = sc;
    }
    __syncthreads();
    float bmax = red[64], bscale = red[65];

    int nchk = (n + 31) >> 5;
    for (int ch = warp; ch < nchk; ch += 32) {
        int j = ch * 32 + lane;
        int q = -1;
        if (j < n) {
            q = (int)((bmax - sjv[j]) * bscale);
            q = max(0, min(NB - 1, q));
        }
        unsigned mask = __match_any_sync(0xffffffffu, q);
        int rank = __popc(mask & ((1u << lane) - 1u));
        if (j < n) {
            qv[j] = q; rnk[j] = rank;
            if (rank == 0) cnt[ch * NB + q] = __popc(mask);
        }
    }
    __syncthreads();

    if (t < NB) {
        int run = 0;
        for (int ch = 0; ch < nchk; ch++) {
            int c = cnt[ch * NB + t];
            cnt[ch * NB + t] = run;
            run += c;
        }
        tot[t] = run;
    }
    __syncthreads();
    if (t < 32) {
        int base = t * 4;
        int h0 = tot[base], h1 = tot[base + 1], h2 = tot[base + 2], h3 = tot[base + 3];
        int s = h0 + h1 + h2 + h3, inc = s;
        #pragma unroll
        for (int o = 1; o < 32; o <<= 1) {
            int v = __shfl_up_sync(0xffffffffu, inc, o);
            if (lane >= o) inc += v;
        }
        int ex = inc - s;
        bst[base] = ex; bst[base + 1] = ex + h0;
        bst[base + 2] = ex + h0 + h1; bst[base + 3] = ex + h0 + h1 + h2;
        if (t == 31) bst[NB] = inc;
    }
    __syncthreads();
    if (t <= NB) g_bstart[b][t] = bst[t];

    for (int j = t; j < n; j += 1024) {
        int q = qv[j];
        int pos = bst[q] + cnt[(j >> 5) * NB + q] + rnk[j];
        ord[pos] = j;
    }
    __syncthreads();

    for (int pos = t; pos < n; pos += 1024) {
        int j = ord[pos];
        float s = sjv[j];
        float v = __expf(s), w = __expf(0.2f * s);
        sjo[pos] = s; vso[pos] = v; bso[pos] = w;
        g_ord[b][pos] = j; g_sjo[b][pos] = s; g_vso[b][pos] = v; g_bso[b][pos] = w;
    }
    __syncthreads();

    {
        int grp = t >> 7, c = t & 127;
        for (int q = grp; q < NB; q += 8) {
            int p0 = bst[q], p1 = bst[q + 1];
            float av = 0.f, ab = 0.f;
            for (int p = p0; p < p1; p++) {
                int jj = ord[p];
                float hv = H[(size_t)jj * FF + c];
                av = fmaf(vso[p], hv, av);
                ab = fmaf(bso[p], hv, ab);
            }
            Sv[q * 128 + c] = av;
            Sb[q * 128 + c] = ab;
            if (c == 0) { float s = 0.f; for (int p = p0; p < p1; p++) s += vso[p]; SvS[q] = s; }
            if (c == 1) { float s = 0.f; for (int p = p0; p < p1; p++) s += bso[p]; SbS[q] = s; }
        }
    }
    __syncthreads();

    if (t < 128) {
        float run = 0.f;
        for (int q = 0; q < NB; q++) { g_Cv[b][q * 128 + t] = run; run += Sv[q * 128 + t]; }
        g_Cv[b][NB * 128 + t] = run;
    } else if (t < 256) {
        int c = t - 128;
        float run = 0.f;
        for (int q = 0; q < NB; q++) { g_Cb[b][q * 128 + c] = run; run += Sb[q * 128 + c]; }
        g_Cb[b][NB * 128 + c] = run;
    } else if (t == 256) {
        float run = 0.f;
        for (int q = 0; q < NB; q++) { g_CvS[b][q] = run; run += SvS[q]; }
        g_CvS[b][NB] = run;
    } else if (t == 257) {
        float run = 0.f;
        for (int q = 0; q < NB; q++) { g_CbS[b][q] = run; run += SbS[q]; }
        g_CbS[b][NB] = run;
    }
}

// ============ per-row combine ============
__device__ __forceinline__ float4 combine_row(int b, int i, int lane, const float* __restrict__ H)
{
    float si = g_sic[b * NN + i];
    float uu = __expf(si), aa = __expf(0.2f * si);
    float th = -si;
    int qt = (int)((g_bmax[b] - th) * g_bscale[b]);
    qt = max(0, min(NB - 1, qt));
    int p0 = g_bstart[b][qt], p1 = g_bstart[b][qt + 1];

    float4 pv = *(const float4*)&g_Cv[b][qt * 128 + lane * 4];
    float4 pb = *(const float4*)&g_Cb[b][qt * 128 + lane * 4];
    float pvs = g_CvS[b][qt], pbs = g_CbS[b][qt];

    for (int p = p0; p < p1; p++) {
        float s = g_sjo[b][p];
        if (s >= th) {
            int jj = g_ord[b][p];
            float w = g_vso[b][p], wb = g_bso[b][p];
            float4 hv = *(const float4*)&H[(size_t)jj * FF + lane * 4];
            pv.x = fmaf(w, hv.x, pv.x); pv.y = fmaf(w, hv.y, pv.y);
            pv.z = fmaf(w, hv.z, pv.z); pv.w = fmaf(w, hv.w, pv.w);
            pb.x = fmaf(wb, hv.x, pb.x); pb.y = fmaf(wb, hv.y, pb.y);
            pb.z = fmaf(wb, hv.z, pb.z); pb.w = fmaf(wb, hv.w, pb.w);
            pvs += w; pbs += wb;
        }
    }

    float totbs = g_CbS[b][NB];
    float4 tb = *(const float4*)&g_Cb[b][NB * 128 + lane * 4];
    float inv = 1.f / (uu * pvs + aa * (totbs - pbs));
    float4 o;
    o.x = (uu * pv.x + aa * (tb.x - pb.x)) * inv;
    o.y = (uu * pv.y + aa * (tb.y - pb.y)) * inv;
    o.z = (uu * pv.z + aa * (tb.z - pb.z)) * inv;
    o.w = (uu * pv.w + aa * (tb.w - pb.w)) * inv;
    o.x = (o.x > 0.f) ? o.x : expm1f(o.x);
    o.y = (o.y > 0.f) ? o.y : expm1f(o.y);
    o.z = (o.z > 0.f) ? o.z : expm1f(o.z);
    o.w = (o.w > 0.f) ? o.w : expm1f(o.w);
    return o;
}

// ============ standalone combine: H=hId buffer -> out oId buffer ============
__global__ void attn_combine(int hId, int oId)
{
    int b = blockIdx.y;
    int n = g_n[b];
    int warp = threadIdx.x >> 5, lane = threadIdx.x & 31;
    int i = blockIdx.x * 8 + warp;
    if (i >= n) return;
    const float* H = (hId ? g_xc : g_hc) + (size_t)b * NN * FF;
    float* O = scratchBuf(oId) + (size_t)b * NN * FF;
    float4 o = combine_row(b, i, lane, H);
    *(float4*)&O[(size_t)i * FF + lane * 4] = o;
}

// ============ decoder: single attention row per sample (512 threads, 4 row-groups) ============
__global__ void dec_attn_kernel()
{
    int b = blockIdx.x;
    int n = g_n[b];
    const float* H = g_hc + (size_t)b * NN * FF;
    const float* sj = g_sjc + b * NN;
    float sLs = g_sL[0];
    int t = threadIdx.x;          // 512
    int g = t >> 7, c = t & 127;
    __shared__ float shw[512];
    __shared__ float sacc[4][128];
    __shared__ float shr[512];

    float acc = 0.f, dsum = 0.f;
    int T = (n + 127) >> 7;
    int TT = (T + 3) >> 2;
    for (int tt = 0; tt < TT; tt++) {
        int tile = tt * 4 + g;
        int j = tile * 128 + c;
        float w = 0.f;
        if (tile < T && j < n) {
            float e = sLs + sj[j]; e = (e >= 0.f) ? e : 0.2f * e; w = __expf(e);
        }
        __syncthreads();
        shw[t] = w; dsum += w;
        __syncthreads();
        if (tile < T) {
            int base = tile * 128;
            int lim = n - base; if (lim > 128) lim = 128;
            const float* wrow = &shw[g * 128];
            int jj = 0;
            for (; jj + 4 <= lim; jj += 4) {
                acc += wrow[jj + 0] * H[(size_t)(base + jj + 0) * FF + c];
                acc += wrow[jj + 1] * H[(size_t)(base + jj + 1) * FF + c];
                acc += wrow[jj + 2] * H[(size_t)(base + jj + 2) * FF + c];
                acc += wrow[jj + 3] * H[(size_t)(base + jj + 3) * FF + c];
            }
            for (; jj < lim; jj++) acc += wrow[jj] * H[(size_t)(base + jj) * FF + c];
        }
    }
    __syncthreads();
    sacc[g][c] = acc;
    shr[t] = dsum;
    __syncthreads();
    for (int s = 256; s > 0; s >>= 1) { if (t < s) shr[t] += shr[t + s]; __syncthreads(); }
    if (t < 128) {
        float a = sacc[0][t] + sacc[1][t] + sacc[2][t] + sacc[3][t];
        float eL = sLs + g_sL[1]; eL = (eL >= 0.f) ? eL : 0.2f * eL;
        float wL = __expf(eL);
        float denom = shr[0] + wL;
        a += wL * g_hlast[t];
        g_feat[b * FF + t] = fmaxf(a / denom, 0.f);
    }
}

// ============ output MLP + KLD total ============
__global__ void final_kernel(const float* __restrict__ W1, const float* __restrict__ b1,
                             const float* __restrict__ W2, const float* __restrict__ b2,
                             float* __restrict__ out)
{
    int t = threadIdx.x; // 256
    __shared__ float shh[16 * 128];
    for (int u = t; u < 16 * 128; u += 256) {
        int b = u >> 7, c = u & 127;
        const float* f = g_feat + b * FF;
        float acc = b1[c];
        for (int k = 0; k < FF; k++) acc += f[k] * W1[k * FF + c];
        shh[u] = fmaxf(acc, 0.f);
    }
    __shared__ float shr[256];
    float kld = 0.f;
    for (int b = 0; b < BB; b++) {
        int n = g_n[b];
        float p = 0.f;
        for (int r = t; r < n; r += 256) p += g_kldrow1[b * NN + r] + g_kldrow2[b * NN + r];
        shr[t] = p;
        __syncthreads();
        for (int s = 128; s > 0; s >>= 1) { if (t < s) shr[t] += shr[t + s]; __syncthreads(); }
        if (t == 0) kld += 0.5f * shr[0] / fmaxf((float)n, 1.f);
        __syncthreads();
    }
    __syncthreads();
    if (t < 16) {
        float acc = b2[0];
        for (int c = 0; c < FF; c++) acc += shh[t * FF + c] * W2[c];
        out[t] = acc;
    }
    if (t == 0) out[16] = kld;
}

// ============ launch ============
extern "C" void kernel_launch(void* const* d_in, const int* in_sizes, int n_in,
                              void* d_out, int out_size)
{
    (void)in_sizes; (void)n_in; (void)out_size;
    const int*   data  = (const int*)d_in[0];
    const float* embed = (const float*)d_in[1];
    const float* encW  = (const float*)d_in[2];
    const float* eas   = (const float*)d_in[3];
    const float* ead   = (const float*)d_in[4];
    const float* pW    = (const float*)d_in[5];
    const float* pb    = (const float*)d_in[6];
    const float* dW    = (const float*)d_in[7];
    const float* das   = (const float*)d_in[8];
    const float* dad   = (const float*)d_in[9];
    const float* oW1   = (const float*)d_in[10];
    const float* ob1   = (const float*)d_in[11];
    const float* oW2   = (const float*)d_in[12];
    const float* ob2   = (const float*)d_in[13];
    float* out = (float*)d_out;

    const int SMEMB = SQ_TOTF * 4;
    cudaFuncSetAttribute(attn_prep, cudaFuncAttributeMaxDynamicSharedMemorySize, SMEMB);

    // 1) layer-0 h + si0/sj0 (+ hlast/bcomb blk48, Wcomb 49-52, compaction 53-68)
    gemm2<0><<<dim3(69, 1), 128>>>(embed, encW, FF, nullptr, eas, ead, -1, 0,
                                   dW, das, dad, pW, pb, data);
    // 2) L1 attention prep (gathers compacted h + scores, then buckets over g_hc)
    attn_prep<<<16, 1024, SMEMB>>>(0);
    // 3) L1 combine -> g_mean (x1)
    attn_combine<<<dim3(192, 16), 256>>>(0, 3);
    // 4) L1 linear: x1 @ encW1 -> g_xc + sic/sjc
    gemm2<1><<<dim3(48, 16), 128>>>(nullptr, encW + FF * FF, FF, nullptr,
                                    eas + FF, ead + FF, 3, 2,
                                    nullptr, nullptr, nullptr, nullptr, nullptr, nullptr);
    // 5) L2 attention prep (buckets over g_xc)
    attn_prep<<<16, 1024, SMEMB>>>(1);
    // 6) L2 combine -> g_mean (x2)
    attn_combine<<<dim3(192, 16), 256>>>(1, 3);
    // 7) param head (z=0 mean-KLD, z=1 sigma-KLD) + decoder linear (z=2 via Wcomb) -> g_hc + sic/sjc
    gemm2<2><<<dim3(48, 16, 3), 128>>>(nullptr, pW, 2 * FF, pb, das, dad, 3, 1,
                                       nullptr, nullptr, nullptr, nullptr, nullptr, nullptr);
    // 8) decoder single-row attention
    dec_attn_kernel<<<16, 512>>>();
    // 9) output MLP + KLD
    final_kernel<<<1, 256>>>(oW1, ob1, oW2, ob2, out);
}